// round 6
// baseline (speedup 1.0000x reference)
#include <cuda_runtime.h>
#include <cstdint>

#define C_CH 32
#define DIM  128
#define NK   27
#define VOL_ELEMS (C_CH * DIM * DIM * DIM)
#define NCELL 4096            // 16x16x16 cells of 8^3 voxels
#define PERM_MAX (1 << 18)
#define TPW 16                // vertices per warp

// feat layout: row c at offset 20*c + 4*(c>>3)  (16B-aligned rows, bank-clean STS)
#define BUFW 656              // words per single feat buffer (>= off(31)+16 = 648)
#define WREG (2 * BUFW)       // double-buffered region per warp

// Scratch (device globals: allocation-free per harness rules)
__device__ float g_vol[VOL_ELEMS];                    // channel-last [z][y][x][c]
__device__ float g_G[NK * C_CH * C_CH];               // [k][j][o] folded weights
__device__ unsigned long long g_G2[NK * C_CH * C_CH]; // duplicated {g,g} pairs
__device__ float g_bias[C_CH];
__device__ int   g_hist[NCELL];
__device__ int   g_base[NCELL];
__device__ int   g_perm[PERM_MAX];

// neighbour shifts (x = k/9-1, y = (k/3)%3-1, z = k%3-1) * 0.0625
#define M1 -0.0625f
#define P1  0.0625f
#define Z0  0.0f
__constant__ float c_shx[NK] = {M1,M1,M1,M1,M1,M1,M1,M1,M1,
                                Z0,Z0,Z0,Z0,Z0,Z0,Z0,Z0,Z0,
                                P1,P1,P1,P1,P1,P1,P1,P1,P1};
__constant__ float c_shy[NK] = {M1,M1,M1,Z0,Z0,Z0,P1,P1,P1,
                                M1,M1,M1,Z0,Z0,Z0,P1,P1,P1,
                                M1,M1,M1,Z0,Z0,Z0,P1,P1,P1};
__constant__ float c_shz[NK] = {M1,Z0,P1,M1,Z0,P1,M1,Z0,P1,
                                M1,Z0,P1,M1,Z0,P1,M1,Z0,P1,
                                M1,Z0,P1,M1,Z0,P1,M1,Z0,P1};

// ---------------------------------------------------------------------------
// Prep 1 (27 blocks): M[k][j][o] = sum_c conv_w[o,c,k]*Wd[c,j]
// ---------------------------------------------------------------------------
__global__ __launch_bounds__(1024) void prep1_kernel(
    const float* __restrict__ w_d1, const float* __restrict__ w_d2,
    const float* __restrict__ conv_w)
{
    __shared__ float Wds[1024];    // Wd[c][j]
    __shared__ float convs[1024];  // conv[c][o] for this k
    const int tid = threadIdx.x, k = blockIdx.x;
    const int o = tid & 31, j = tid >> 5;

    {   // Wd = w_d2 @ w_d1
        float s = 0.f;
        #pragma unroll
        for (int m = 0; m < 32; m++)
            s += w_d2[(tid >> 5) * 32 + m] * w_d1[m * 32 + (tid & 31)];
        Wds[tid] = s;
    }
    convs[tid] = conv_w[(o * 32 + (tid >> 5)) * 27 + k];
    __syncthreads();

    float acc = 0.f;
    #pragma unroll
    for (int c = 0; c < 32; c++)
        acc += convs[c * 32 + o] * Wds[c * 32 + j];
    g_G[k * 1024 + j * 32 + o] = acc;
}

// ---------------------------------------------------------------------------
// Prep 2 (1 block): center-tap correction + fused bias + zero histograms
// + build duplicated-pair table g_G2.
// ---------------------------------------------------------------------------
__global__ __launch_bounds__(1024) void prep2_kernel(
    const float* __restrict__ w_d2, const float* __restrict__ b_d1,
    const float* __restrict__ b_d2,
    const float* __restrict__ w_c1, const float* __restrict__ b_c1,
    const float* __restrict__ w_c2, const float* __restrict__ b_c2,
    const float* __restrict__ conv_w, const float* __restrict__ conv_b)
{
    __shared__ float Wcs[1024], part[1024], bds[32], bcs[32];
    const int tid = threadIdx.x;
    const int o = tid & 31, j = tid >> 5;

    #pragma unroll
    for (int i = 0; i < NCELL / 1024; i++) {
        g_hist[tid + 1024 * i] = 0;
        g_base[tid + 1024 * i] = 0;
    }

    {   // Wc = w_c2 @ w_c1
        float s = 0.f;
        #pragma unroll
        for (int m = 0; m < 32; m++)
            s += w_c2[(tid >> 5) * 32 + m] * w_c1[m * 32 + (tid & 31)];
        Wcs[tid] = s;
    }
    if (tid < 32) {
        float sd = 0.f, sc = 0.f;
        #pragma unroll
        for (int m = 0; m < 32; m++) {
            sd += w_d2[tid * 32 + m] * b_d1[m];
            sc += w_c2[tid * 32 + m] * b_c1[m];
        }
        bds[tid] = sd + b_d2[tid];
        bcs[tid] = sc + b_c2[tid];
    }
    float rs = 0.f;
    #pragma unroll
    for (int k = 0; k < NK; k++)
        rs += conv_w[(o * 32 + j) * 27 + k];
    __syncthreads();

    part[j * 32 + o] = bds[j] * rs;

    float S = 0.f;
    #pragma unroll
    for (int k = 0; k < NK; k++) S += g_G[k * 1024 + tid];
    g_G[13 * 1024 + tid] += Wcs[o * 32 + j] - S;

    for (int k = 0; k < NK; k++) {
        const unsigned u = __float_as_uint(g_G[k * 1024 + tid]);
        g_G2[k * 1024 + tid] = (unsigned long long)u |
                               ((unsigned long long)u << 32);
    }
    __syncthreads();

    if (tid < 32) {
        float a = 0.f;
        #pragma unroll
        for (int c = 0; c < 32; c++) a += part[c * 32 + tid];
        g_bias[tid] = a + conv_b[tid] + bcs[tid];
    }
}

// ---------------------------------------------------------------------------
// Transpose [C][D][H][W] -> channel-last [D][H][W][C], STG.128 stores.
// ---------------------------------------------------------------------------
__global__ __launch_bounds__(256) void transpose_kernel(const float* __restrict__ vin)
{
    __shared__ float tile[32][33];
    const int x0 = blockIdx.x * 32;
    const int y = blockIdx.y, z = blockIdx.z;
    const int tid = threadIdx.x;
    const int tx = tid & 31, ty = tid >> 5;

    #pragma unroll
    for (int i = 0; i < 4; i++) {
        const int c = ty + 8 * i;
        tile[c][tx] = vin[(((size_t)c * DIM + z) * DIM + y) * DIM + x0 + tx];
    }
    __syncthreads();

    const int q  = tid & 7;
    const int xl = (tid >> 3) & 3;
    const int xg = tid >> 5;
    const size_t obase = ((size_t)z * DIM + y) * DIM + x0;
    const int xx = xg * 4 + xl;
    float4 v;
    v.x = tile[4 * q + 0][xx];
    v.y = tile[4 * q + 1][xx];
    v.z = tile[4 * q + 2][xx];
    v.w = tile[4 * q + 3][xx];
    reinterpret_cast<float4*>(g_vol + (obase + xx) * C_CH)[q] = v;
}

// ---------------------------------------------------------------------------
// Vertex binning: histogram -> scan -> scatter (cells of 8^3 voxels).
// ---------------------------------------------------------------------------
__device__ __forceinline__ int cell_of(float x, float y, float z)
{
    float px = fminf(fmaxf((x + 1.f) * 63.5f, 0.f), 127.f);
    float py = fminf(fmaxf((y + 1.f) * 63.5f, 0.f), 127.f);
    float pz = fminf(fmaxf((z + 1.f) * 63.5f, 0.f), 127.f);
    const int cx = ((int)px) >> 3, cy = ((int)py) >> 3, cz = ((int)pz) >> 3;
    return (cz << 8) | (cy << 4) | cx;
}

__global__ void count_kernel(const float* __restrict__ verts, int Ntot)
{
    const int n = blockIdx.x * blockDim.x + threadIdx.x;
    if (n >= Ntot) return;
    atomicAdd(&g_hist[cell_of(verts[3 * n], verts[3 * n + 1], verts[3 * n + 2])], 1);
}

__global__ __launch_bounds__(1024) void scan_kernel()
{
    __shared__ int sh[1024];
    const int t = threadIdx.x;
    int h0 = g_hist[4 * t], h1 = g_hist[4 * t + 1],
        h2 = g_hist[4 * t + 2], h3 = g_hist[4 * t + 3];
    const int mysum = h0 + h1 + h2 + h3;
    sh[t] = mysum;
    __syncthreads();
    for (int off = 1; off < 1024; off <<= 1) {
        int v = (t >= off) ? sh[t - off] : 0;
        __syncthreads();
        sh[t] += v;
        __syncthreads();
    }
    int e = sh[t] - mysum;
    g_base[4 * t]     = e;
    g_base[4 * t + 1] = e + h0;
    g_base[4 * t + 2] = e + h0 + h1;
    g_base[4 * t + 3] = e + h0 + h1 + h2;
}

__global__ void scatter_kernel(const float* __restrict__ verts, int Ntot)
{
    const int n = blockIdx.x * blockDim.x + threadIdx.x;
    if (n >= Ntot) return;
    const int c = cell_of(verts[3 * n], verts[3 * n + 1], verts[3 * n + 2]);
    const int pos = atomicAdd(&g_base[c], 1);
    g_perm[pos] = n;
}

// ---------------------------------------------------------------------------
// Sample neighbour k for this warp's 16 vertices into buf (feat[c][v]).
// lane = (vertex-quad v4, channel-quad c4); float4 corner loads.
// ---------------------------------------------------------------------------
__device__ __forceinline__ void sample_k(
    int k, float gxv, float gyv, float gzv,
    int c4, int v4, int rowbase, float* buf)
{
    const float gx = gxv + c_shx[k];
    const float gy = gyv + c_shy[k];
    const float gz = gzv + c_shz[k];
    float px = fminf(fmaxf((gx + 1.f) * 63.5f, 0.f), 127.f);
    float py = fminf(fmaxf((gy + 1.f) * 63.5f, 0.f), 127.f);
    float pz = fminf(fmaxf((gz + 1.f) * 63.5f, 0.f), 127.f);
    const float fx = floorf(px), fy = floorf(py), fz = floorf(pz);
    const int ix = (int)fx, iy = (int)fy, iz = (int)fz;
    const float wx = px - fx, wy = py - fy, wz = pz - fz;
    const int base = iz * (DIM * DIM * C_CH) + iy * (DIM * C_CH) + ix * C_CH;
    const int sx = (ix < DIM - 1) ? C_CH : 0;
    const int sy = (iy < DIM - 1) ? DIM * C_CH : 0;
    const int sz = (iz < DIM - 1) ? DIM * DIM * C_CH : 0;

    #pragma unroll
    for (int g4 = 0; g4 < 4; g4++) {
        const int src = g4 * 4 + v4;
        const int b   = __shfl_sync(0xffffffffu, base, src);
        const int sx4 = __shfl_sync(0xffffffffu, sx, src) >> 2;
        const int sy4 = __shfl_sync(0xffffffffu, sy, src) >> 2;
        const int sz4 = __shfl_sync(0xffffffffu, sz, src) >> 2;
        const float wxv = __shfl_sync(0xffffffffu, wx, src);
        const float wyv = __shfl_sync(0xffffffffu, wy, src);
        const float wzv = __shfl_sync(0xffffffffu, wz, src);

        const float4* p = reinterpret_cast<const float4*>(g_vol + b) + c4;
        const float4 f000 = __ldg(p);
        const float4 f001 = __ldg(p + sx4);
        const float4 f010 = __ldg(p + sy4);
        const float4 f011 = __ldg(p + sy4 + sx4);
        const float4 f100 = __ldg(p + sz4);
        const float4 f101 = __ldg(p + sz4 + sx4);
        const float4 f110 = __ldg(p + sz4 + sy4);
        const float4 f111 = __ldg(p + sz4 + sy4 + sx4);

        const float ax0 = 1.f - wxv, ay0 = 1.f - wyv, az0 = 1.f - wzv;
        const float c00 = az0 * ay0, c01 = az0 * wyv;
        const float c10 = wzv * ay0, c11 = wzv * wyv;
        const float w000 = c00 * ax0, w001 = c00 * wxv;
        const float w010 = c01 * ax0, w011 = c01 * wxv;
        const float w100 = c10 * ax0, w101 = c10 * wxv;
        const float w110 = c11 * ax0, w111 = c11 * wxv;

        float rx = f000.x * w000, ry = f000.y * w000,
              rz = f000.z * w000, rw = f000.w * w000;
        rx = fmaf(f001.x, w001, rx); ry = fmaf(f001.y, w001, ry);
        rz = fmaf(f001.z, w001, rz); rw = fmaf(f001.w, w001, rw);
        rx = fmaf(f010.x, w010, rx); ry = fmaf(f010.y, w010, ry);
        rz = fmaf(f010.z, w010, rz); rw = fmaf(f010.w, w010, rw);
        rx = fmaf(f011.x, w011, rx); ry = fmaf(f011.y, w011, ry);
        rz = fmaf(f011.z, w011, rz); rw = fmaf(f011.w, w011, rw);
        rx = fmaf(f100.x, w100, rx); ry = fmaf(f100.y, w100, ry);
        rz = fmaf(f100.z, w100, rz); rw = fmaf(f100.w, w100, rw);
        rx = fmaf(f101.x, w101, rx); ry = fmaf(f101.y, w101, ry);
        rz = fmaf(f101.z, w101, rz); rw = fmaf(f101.w, w101, rw);
        rx = fmaf(f110.x, w110, rx); ry = fmaf(f110.y, w110, ry);
        rz = fmaf(f110.z, w110, rz); rw = fmaf(f110.w, w110, rw);
        rx = fmaf(f111.x, w111, rx); ry = fmaf(f111.y, w111, ry);
        rz = fmaf(f111.z, w111, rz); rw = fmaf(f111.w, w111, rw);

        const int col = g4 * 4 + v4;
        buf[rowbase +  0 + col] = rx;
        buf[rowbase + 20 + col] = ry;
        buf[rowbase + 40 + col] = rz;
        buf[rowbase + 60 + col] = rw;
    }
}

// ---------------------------------------------------------------------------
// Fused sample + GEMM, software-pipelined: sample(k+1) -> buffer B overlaps
// reduce(k) <- buffer A (independent streams, single syncwarp per iter).
// ---------------------------------------------------------------------------
__global__ __launch_bounds__(256, 3) void main_kernel(
    const float* __restrict__ verts, float* __restrict__ out, int Ntot)
{
    __shared__ __align__(16) float fs[8 * WREG];
    const int warp = threadIdx.x >> 5, lane = threadIdx.x & 31;
    const int nTiles = (Ntot + TPW - 1) / TPW;
    const int tile = blockIdx.x * 8 + warp;
    if (tile >= nTiles) return;

    const int n0 = tile * TPW;
    const int v = lane & 15;
    const int idx = n0 + v;
    const bool valid = (idx < Ntot);
    const int n = valid ? g_perm[idx] : 0;

    float gxv = 0.f, gyv = 0.f, gzv = 0.f;
    if (valid) {
        gxv = verts[3 * n + 0];
        gyv = verts[3 * n + 1];
        gzv = verts[3 * n + 2];
    }

    const int c4 = lane & 7;              // channel quad
    const int v4 = lane >> 3;             // vertex within group of 4
    // STS row base: off(4*c4) = 80*c4 + 4*(c4>>1) -> banks {0,16,4,20,...}+v4
    const int rowbase = 80 * c4 + ((c4 >> 1) << 2);

    float* fw = fs + warp * WREG;
    unsigned long long acc2[8];
    #pragma unroll
    for (int i = 0; i < 8; i++) acc2[i] = 0ull;

    // prologue: fill buffer 0 with k=0 feats
    sample_k(0, gxv, gyv, gzv, c4, v4, rowbase, fw);
    __syncwarp();

    #pragma unroll 1
    for (int k = 0; k < NK; k++) {
        float* bufA = fw + (k & 1) * BUFW;
        float* bufB = fw + ((k + 1) & 1) * BUFW;

        // sample next neighbour (memory stream) — interleaves with reduce
        if (k + 1 < NK)
            sample_k(k + 1, gxv, gyv, gzv, c4, v4, rowbase, bufB);

        // reduce current neighbour (FMA stream)
        const unsigned long long* gk = g_G2 + k * 1024 + lane;
        #pragma unroll
        for (int c = 0; c < 32; c++) {
            const unsigned long long g2 = __ldg(gk + c * 32);
            const ulonglong2* fq = reinterpret_cast<const ulonglong2*>(
                bufA + (c * 20 + ((c >> 3) << 2)));
            const ulonglong2 q0 = fq[0];
            const ulonglong2 q1 = fq[1];
            const ulonglong2 q2 = fq[2];
            const ulonglong2 q3 = fq[3];
            asm("fma.rn.f32x2 %0, %1, %2, %0;" : "+l"(acc2[0]) : "l"(q0.x), "l"(g2));
            asm("fma.rn.f32x2 %0, %1, %2, %0;" : "+l"(acc2[1]) : "l"(q0.y), "l"(g2));
            asm("fma.rn.f32x2 %0, %1, %2, %0;" : "+l"(acc2[2]) : "l"(q1.x), "l"(g2));
            asm("fma.rn.f32x2 %0, %1, %2, %0;" : "+l"(acc2[3]) : "l"(q1.y), "l"(g2));
            asm("fma.rn.f32x2 %0, %1, %2, %0;" : "+l"(acc2[4]) : "l"(q2.x), "l"(g2));
            asm("fma.rn.f32x2 %0, %1, %2, %0;" : "+l"(acc2[5]) : "l"(q2.y), "l"(g2));
            asm("fma.rn.f32x2 %0, %1, %2, %0;" : "+l"(acc2[6]) : "l"(q3.x), "l"(g2));
            asm("fma.rn.f32x2 %0, %1, %2, %0;" : "+l"(acc2[7]) : "l"(q3.y), "l"(g2));
        }
        __syncwarp();
    }

    const float bias = __ldg(&g_bias[lane]);
    #pragma unroll
    for (int v2 = 0; v2 < 8; v2++) {
        const float lo = __uint_as_float((unsigned)(acc2[v2] & 0xffffffffull));
        const float hi = __uint_as_float((unsigned)(acc2[v2] >> 32));
        const int ia = n0 + 2 * v2, ib = ia + 1;
        if (ia < Ntot) out[g_perm[ia] * C_CH + lane] = lo + bias;
        if (ib < Ntot) out[g_perm[ib] * C_CH + lane] = hi + bias;
    }
}

// ---------------------------------------------------------------------------
extern "C" void kernel_launch(void* const* d_in, const int* in_sizes, int n_in,
                              void* d_out, int out_size)
{
    const float* voxel = (const float*)d_in[0];
    const float* verts = (const float*)d_in[1];
    const int Ntot = in_sizes[1] / 3;

    prep1_kernel<<<27, 1024>>>(
        (const float*)d_in[2], (const float*)d_in[4], (const float*)d_in[10]);

    prep2_kernel<<<1, 1024>>>(
        (const float*)d_in[4], (const float*)d_in[3], (const float*)d_in[5],
        (const float*)d_in[6], (const float*)d_in[7], (const float*)d_in[8],
        (const float*)d_in[9], (const float*)d_in[10], (const float*)d_in[11]);

    count_kernel<<<(Ntot + 255) / 256, 256>>>(verts, Ntot);
    scan_kernel<<<1, 1024>>>();
    scatter_kernel<<<(Ntot + 255) / 256, 256>>>(verts, Ntot);

    dim3 tb(256);
    dim3 tg(DIM / 32, DIM, DIM);
    transpose_kernel<<<tg, tb>>>(voxel);

    const int nTiles = (Ntot + TPW - 1) / TPW;
    const int blocks = (nTiles + 7) / 8;
    main_kernel<<<blocks, 256>>>(verts, (float*)d_out, Ntot);
}

// round 8
// speedup vs baseline: 1.1759x; 1.1759x over previous
#include <cuda_runtime.h>
#include <cuda_fp16.h>
#include <cstdint>

#define C_CH 32
#define DIM  128
#define NK   27
#define VOL_ELEMS (C_CH * DIM * DIM * DIM)
#define NCELL 4096            // 16x16x16 cells of 8^3 voxels
#define PERM_MAX (1 << 18)
#define TPW 16                // vertices per warp

// feat smem layout: row c at offset 36*c + 4*(c>>3) (16B-aligned, bank-clean STS)
#define WREG 1168             // words per warp region (32*36+16)

// Scratch (device globals: allocation-free per harness rules)
__device__ __half g_volh[VOL_ELEMS];                  // channel-last fp16 volume
__device__ float g_G[NK * C_CH * C_CH];               // [k][j][o] folded weights
__device__ unsigned long long g_G2[NK * C_CH * C_CH]; // duplicated {g,g} pairs
__device__ float g_bias[C_CH];
__device__ int   g_hist[NCELL];
__device__ int   g_base[NCELL];
__device__ int   g_perm[PERM_MAX];

// neighbour shifts (x = k/9-1, y = (k/3)%3-1, z = k%3-1) * 0.0625
#define M1 -0.0625f
#define P1  0.0625f
#define Z0  0.0f
__constant__ float c_shx[NK] = {M1,M1,M1,M1,M1,M1,M1,M1,M1,
                                Z0,Z0,Z0,Z0,Z0,Z0,Z0,Z0,Z0,
                                P1,P1,P1,P1,P1,P1,P1,P1,P1};
__constant__ float c_shy[NK] = {M1,M1,M1,Z0,Z0,Z0,P1,P1,P1,
                                M1,M1,M1,Z0,Z0,Z0,P1,P1,P1,
                                M1,M1,M1,Z0,Z0,Z0,P1,P1,P1};
__constant__ float c_shz[NK] = {M1,Z0,P1,M1,Z0,P1,M1,Z0,P1,
                                M1,Z0,P1,M1,Z0,P1,M1,Z0,P1,
                                M1,Z0,P1,M1,Z0,P1,M1,Z0,P1};

// ---------------------------------------------------------------------------
// Prep 1 (27 blocks): M[k][j][o] = sum_c conv_w[o,c,k]*Wd[c,j]
// ---------------------------------------------------------------------------
__global__ __launch_bounds__(1024) void prep1_kernel(
    const float* __restrict__ w_d1, const float* __restrict__ w_d2,
    const float* __restrict__ conv_w)
{
    __shared__ float Wds[1024];    // Wd[c][j]
    __shared__ float convs[1024];  // conv[c][o] for this k
    const int tid = threadIdx.x, k = blockIdx.x;
    const int o = tid & 31, j = tid >> 5;

    {   // Wd = w_d2 @ w_d1
        float s = 0.f;
        #pragma unroll
        for (int m = 0; m < 32; m++)
            s += w_d2[(tid >> 5) * 32 + m] * w_d1[m * 32 + (tid & 31)];
        Wds[tid] = s;
    }
    convs[tid] = conv_w[(o * 32 + (tid >> 5)) * 27 + k];
    __syncthreads();

    float acc = 0.f;
    #pragma unroll
    for (int c = 0; c < 32; c++)
        acc += convs[c * 32 + o] * Wds[c * 32 + j];
    g_G[k * 1024 + j * 32 + o] = acc;
}

// ---------------------------------------------------------------------------
// Prep 2 (1 block): center-tap correction + fused bias + zero histograms
// + build duplicated-pair table g_G2.
// ---------------------------------------------------------------------------
__global__ __launch_bounds__(1024) void prep2_kernel(
    const float* __restrict__ w_d2, const float* __restrict__ b_d1,
    const float* __restrict__ b_d2,
    const float* __restrict__ w_c1, const float* __restrict__ b_c1,
    const float* __restrict__ w_c2, const float* __restrict__ b_c2,
    const float* __restrict__ conv_w, const float* __restrict__ conv_b)
{
    __shared__ float Wcs[1024], part[1024], bds[32], bcs[32];
    const int tid = threadIdx.x;
    const int o = tid & 31, j = tid >> 5;

    #pragma unroll
    for (int i = 0; i < NCELL / 1024; i++) {
        g_hist[tid + 1024 * i] = 0;
        g_base[tid + 1024 * i] = 0;
    }

    {   // Wc = w_c2 @ w_c1
        float s = 0.f;
        #pragma unroll
        for (int m = 0; m < 32; m++)
            s += w_c2[(tid >> 5) * 32 + m] * w_c1[m * 32 + (tid & 31)];
        Wcs[tid] = s;
    }
    if (tid < 32) {
        float sd = 0.f, sc = 0.f;
        #pragma unroll
        for (int m = 0; m < 32; m++) {
            sd += w_d2[tid * 32 + m] * b_d1[m];
            sc += w_c2[tid * 32 + m] * b_c1[m];
        }
        bds[tid] = sd + b_d2[tid];
        bcs[tid] = sc + b_c2[tid];
    }
    float rs = 0.f;
    #pragma unroll
    for (int k = 0; k < NK; k++)
        rs += conv_w[(o * 32 + j) * 27 + k];
    __syncthreads();

    part[j * 32 + o] = bds[j] * rs;

    float S = 0.f;
    #pragma unroll
    for (int k = 0; k < NK; k++) S += g_G[k * 1024 + tid];
    g_G[13 * 1024 + tid] += Wcs[o * 32 + j] - S;

    for (int k = 0; k < NK; k++) {
        const unsigned u = __float_as_uint(g_G[k * 1024 + tid]);
        g_G2[k * 1024 + tid] = (unsigned long long)u |
                               ((unsigned long long)u << 32);
    }
    __syncthreads();

    if (tid < 32) {
        float a = 0.f;
        #pragma unroll
        for (int c = 0; c < 32; c++) a += part[c * 32 + tid];
        g_bias[tid] = a + conv_b[tid] + bcs[tid];
    }
}

// ---------------------------------------------------------------------------
// Transpose + convert: [C][D][H][W] fp32 -> channel-last fp16 [D][H][W][C].
// Store phase: lane = (x, channel-quad) so a warp writes 256B contiguous.
// ---------------------------------------------------------------------------
__global__ __launch_bounds__(256) void transpose_kernel(const float* __restrict__ vin)
{
    __shared__ float tile[32][33];
    const int x0 = blockIdx.x * 32;
    const int y = blockIdx.y, z = blockIdx.z;
    const int tid = threadIdx.x;
    const int tx = tid & 31, ty = tid >> 5;

    #pragma unroll
    for (int i = 0; i < 4; i++) {
        const int c = ty + 8 * i;
        tile[c][tx] = vin[(((size_t)c * DIM + z) * DIM + y) * DIM + x0 + tx];
    }
    __syncthreads();

    const int g  = tid & 7;          // channel quad (4 halves = 8B)
    const int xx = tid >> 3;         // x within tile (0..31)
    const size_t obase = ((size_t)z * DIM + y) * DIM + x0;

    __half2 h01 = __floats2half2_rn(tile[4 * g + 0][xx], tile[4 * g + 1][xx]);
    __half2 h23 = __floats2half2_rn(tile[4 * g + 2][xx], tile[4 * g + 3][xx]);
    uint2 u;
    u.x = *reinterpret_cast<unsigned*>(&h01);
    u.y = *reinterpret_cast<unsigned*>(&h23);
    reinterpret_cast<uint2*>(g_volh + (obase + xx) * C_CH)[g] = u;
}

// ---------------------------------------------------------------------------
// Vertex binning: histogram -> scan -> scatter (cells of 8^3 voxels).
// ---------------------------------------------------------------------------
__device__ __forceinline__ int cell_of(float x, float y, float z)
{
    float px = fminf(fmaxf((x + 1.f) * 63.5f, 0.f), 127.f);
    float py = fminf(fmaxf((y + 1.f) * 63.5f, 0.f), 127.f);
    float pz = fminf(fmaxf((z + 1.f) * 63.5f, 0.f), 127.f);
    const int cx = ((int)px) >> 3, cy = ((int)py) >> 3, cz = ((int)pz) >> 3;
    return (cz << 8) | (cy << 4) | cx;
}

__global__ void count_kernel(const float* __restrict__ verts, int Ntot)
{
    const int n = blockIdx.x * blockDim.x + threadIdx.x;
    if (n >= Ntot) return;
    atomicAdd(&g_hist[cell_of(verts[3 * n], verts[3 * n + 1], verts[3 * n + 2])], 1);
}

__global__ __launch_bounds__(1024) void scan_kernel()
{
    __shared__ int sh[1024];
    const int t = threadIdx.x;
    int h0 = g_hist[4 * t], h1 = g_hist[4 * t + 1],
        h2 = g_hist[4 * t + 2], h3 = g_hist[4 * t + 3];
    const int mysum = h0 + h1 + h2 + h3;
    sh[t] = mysum;
    __syncthreads();
    for (int off = 1; off < 1024; off <<= 1) {
        int v = (t >= off) ? sh[t - off] : 0;
        __syncthreads();
        sh[t] += v;
        __syncthreads();
    }
    int e = sh[t] - mysum;
    g_base[4 * t]     = e;
    g_base[4 * t + 1] = e + h0;
    g_base[4 * t + 2] = e + h0 + h1;
    g_base[4 * t + 3] = e + h0 + h1 + h2;
}

__global__ void scatter_kernel(const float* __restrict__ verts, int Ntot)
{
    const int n = blockIdx.x * blockDim.x + threadIdx.x;
    if (n >= Ntot) return;
    const int c = cell_of(verts[3 * n], verts[3 * n + 1], verts[3 * n + 2]);
    const int pos = atomicAdd(&g_base[c], 1);
    g_perm[pos] = n;
}

// ---------------------------------------------------------------------------
// uint2 (4 halves) -> float4
// ---------------------------------------------------------------------------
__device__ __forceinline__ float4 h4_to_f4(uint2 u)
{
    const __half2 a = *reinterpret_cast<const __half2*>(&u.x);
    const __half2 b = *reinterpret_cast<const __half2*>(&u.y);
    const float2 lo = __half22float2(a);
    const float2 hi = __half22float2(b);
    return make_float4(lo.x, lo.y, hi.x, hi.y);
}

// ---------------------------------------------------------------------------
// Fused sample + GEMM over permuted vertices. One warp = 16 vertices.
// Sampling lane = (vertex-quad v4, channel-quad c4); LDG.64 fp16 corner loads
// (64B line per corner), trilinear in fp32. Reduction lane = output channel:
// LDG.64 pre-duplicated G + LDS.128 feats + packed fma.rn.f32x2.
// ---------------------------------------------------------------------------
__global__ __launch_bounds__(256, 3) void main_kernel(
    const float* __restrict__ verts, float* __restrict__ out, int Ntot)
{
    __shared__ __align__(16) float fs[8 * WREG];
    const int warp = threadIdx.x >> 5, lane = threadIdx.x & 31;
    const int nTiles = (Ntot + TPW - 1) / TPW;
    const int tile = blockIdx.x * 8 + warp;
    if (tile >= nTiles) return;

    const int n0 = tile * TPW;
    const int v = lane & 15;
    const int idx = n0 + v;
    const bool valid = (idx < Ntot);
    const int n = valid ? g_perm[idx] : 0;

    float gxv = 0.f, gyv = 0.f, gzv = 0.f;
    if (valid) {
        gxv = verts[3 * n + 0];
        gyv = verts[3 * n + 1];
        gzv = verts[3 * n + 2];
    }

    const int c4 = lane & 7;              // channel quad
    const int v4 = lane >> 3;             // vertex within group of 4
    const int rowbase = 144 * c4 + ((c4 >> 1) << 2);

    float* fw = fs + warp * WREG;
    unsigned long long acc2[8];
    #pragma unroll
    for (int i = 0; i < 8; i++) acc2[i] = 0ull;

    #pragma unroll 1
    for (int k = 0; k < NK; k++) {
        const float gx = gxv + c_shx[k];
        const float gy = gyv + c_shy[k];
        const float gz = gzv + c_shz[k];
        float px = fminf(fmaxf((gx + 1.f) * 63.5f, 0.f), 127.f);
        float py = fminf(fmaxf((gy + 1.f) * 63.5f, 0.f), 127.f);
        float pz = fminf(fmaxf((gz + 1.f) * 63.5f, 0.f), 127.f);
        const float fx = floorf(px), fy = floorf(py), fz = floorf(pz);
        const int ix = (int)fx, iy = (int)fy, iz = (int)fz;
        const float wx = px - fx, wy = py - fy, wz = pz - fz;
        const int base = iz * (DIM * DIM * C_CH) + iy * (DIM * C_CH) + ix * C_CH;
        const int sx = (ix < DIM - 1) ? (C_CH >> 2) : 0;             // uint2 units
        const int sy = (iy < DIM - 1) ? (DIM * C_CH >> 2) : 0;
        const int sz = (iz < DIM - 1) ? (DIM * DIM * C_CH >> 2) : 0;

        #pragma unroll
        for (int g4 = 0; g4 < 4; g4++) {
            const int src = g4 * 4 + v4;
            const int b   = __shfl_sync(0xffffffffu, base, src);
            const int sx4 = __shfl_sync(0xffffffffu, sx, src);
            const int sy4 = __shfl_sync(0xffffffffu, sy, src);
            const int sz4 = __shfl_sync(0xffffffffu, sz, src);
            const float wxv = __shfl_sync(0xffffffffu, wx, src);
            const float wyv = __shfl_sync(0xffffffffu, wy, src);
            const float wzv = __shfl_sync(0xffffffffu, wz, src);

            const uint2* p = reinterpret_cast<const uint2*>(g_volh + b) + c4;
            const float4 f000 = h4_to_f4(__ldg(p));
            const float4 f001 = h4_to_f4(__ldg(p + sx4));
            const float4 f010 = h4_to_f4(__ldg(p + sy4));
            const float4 f011 = h4_to_f4(__ldg(p + sy4 + sx4));
            const float4 f100 = h4_to_f4(__ldg(p + sz4));
            const float4 f101 = h4_to_f4(__ldg(p + sz4 + sx4));
            const float4 f110 = h4_to_f4(__ldg(p + sz4 + sy4));
            const float4 f111 = h4_to_f4(__ldg(p + sz4 + sy4 + sx4));

            const float ax0 = 1.f - wxv, ay0 = 1.f - wyv, az0 = 1.f - wzv;
            const float c00 = az0 * ay0, c01 = az0 * wyv;
            const float c10 = wzv * ay0, c11 = wzv * wyv;
            const float w000 = c00 * ax0, w001 = c00 * wxv;
            const float w010 = c01 * ax0, w011 = c01 * wxv;
            const float w100 = c10 * ax0, w101 = c10 * wxv;
            const float w110 = c11 * ax0, w111 = c11 * wxv;

            float rx = f000.x * w000, ry = f000.y * w000,
                  rz = f000.z * w000, rw = f000.w * w000;
            rx = fmaf(f001.x, w001, rx); ry = fmaf(f001.y, w001, ry);
            rz = fmaf(f001.z, w001, rz); rw = fmaf(f001.w, w001, rw);
            rx = fmaf(f010.x, w010, rx); ry = fmaf(f010.y, w010, ry);
            rz = fmaf(f010.z, w010, rz); rw = fmaf(f010.w, w010, rw);
            rx = fmaf(f011.x, w011, rx); ry = fmaf(f011.y, w011, ry);
            rz = fmaf(f011.z, w011, rz); rw = fmaf(f011.w, w011, rw);
            rx = fmaf(f100.x, w100, rx); ry = fmaf(f100.y, w100, ry);
            rz = fmaf(f100.z, w100, rz); rw = fmaf(f100.w, w100, rw);
            rx = fmaf(f101.x, w101, rx); ry = fmaf(f101.y, w101, ry);
            rz = fmaf(f101.z, w101, rz); rw = fmaf(f101.w, w101, rw);
            rx = fmaf(f110.x, w110, rx); ry = fmaf(f110.y, w110, ry);
            rz = fmaf(f110.z, w110, rz); rw = fmaf(f110.w, w110, rw);
            rx = fmaf(f111.x, w111, rx); ry = fmaf(f111.y, w111, ry);
            rz = fmaf(f111.z, w111, rz); rw = fmaf(f111.w, w111, rw);

            const int col = g4 * 4 + v4;
            fw[rowbase +   0 + col] = rx;
            fw[rowbase +  36 + col] = ry;
            fw[rowbase +  72 + col] = rz;
            fw[rowbase + 108 + col] = rw;
        }
        __syncwarp();

        // reduction: acc[v][lane] += f[v][c] * G[k][c][lane]
        const unsigned long long* gk = g_G2 + k * 1024 + lane;
        #pragma unroll
        for (int c = 0; c < 32; c++) {
            const unsigned long long g2 = __ldg(gk + c * 32);
            const ulonglong2* fq = reinterpret_cast<const ulonglong2*>(
                fw + (c * 36 + ((c >> 3) << 2)));
            const ulonglong2 q0 = fq[0];
            const ulonglong2 q1 = fq[1];
            const ulonglong2 q2 = fq[2];
            const ulonglong2 q3 = fq[3];
            asm("fma.rn.f32x2 %0, %1, %2, %0;" : "+l"(acc2[0]) : "l"(q0.x), "l"(g2));
            asm("fma.rn.f32x2 %0, %1, %2, %0;" : "+l"(acc2[1]) : "l"(q0.y), "l"(g2));
            asm("fma.rn.f32x2 %0, %1, %2, %0;" : "+l"(acc2[2]) : "l"(q1.x), "l"(g2));
            asm("fma.rn.f32x2 %0, %1, %2, %0;" : "+l"(acc2[3]) : "l"(q1.y), "l"(g2));
            asm("fma.rn.f32x2 %0, %1, %2, %0;" : "+l"(acc2[4]) : "l"(q2.x), "l"(g2));
            asm("fma.rn.f32x2 %0, %1, %2, %0;" : "+l"(acc2[5]) : "l"(q2.y), "l"(g2));
            asm("fma.rn.f32x2 %0, %1, %2, %0;" : "+l"(acc2[6]) : "l"(q3.x), "l"(g2));
            asm("fma.rn.f32x2 %0, %1, %2, %0;" : "+l"(acc2[7]) : "l"(q3.y), "l"(g2));
        }
        __syncwarp();
    }

    const float bias = __ldg(&g_bias[lane]);
    #pragma unroll
    for (int v2 = 0; v2 < 8; v2++) {
        const float lo = __uint_as_float((unsigned)(acc2[v2] & 0xffffffffull));
        const float hi = __uint_as_float((unsigned)(acc2[v2] >> 32));
        const int ia = n0 + 2 * v2, ib = ia + 1;
        if (ia < Ntot) out[g_perm[ia] * C_CH + lane] = lo + bias;
        if (ib < Ntot) out[g_perm[ib] * C_CH + lane] = hi + bias;
    }
}

// ---------------------------------------------------------------------------
extern "C" void kernel_launch(void* const* d_in, const int* in_sizes, int n_in,
                              void* d_out, int out_size)
{
    const float* voxel = (const float*)d_in[0];
    const float* verts = (const float*)d_in[1];
    const int Ntot = in_sizes[1] / 3;

    prep1_kernel<<<27, 1024>>>(
        (const float*)d_in[2], (const float*)d_in[4], (const float*)d_in[10]);

    prep2_kernel<<<1, 1024>>>(
        (const float*)d_in[4], (const float*)d_in[3], (const float*)d_in[5],
        (const float*)d_in[6], (const float*)d_in[7], (const float*)d_in[8],
        (const float*)d_in[9], (const float*)d_in[10], (const float*)d_in[11]);

    count_kernel<<<(Ntot + 255) / 256, 256>>>(verts, Ntot);
    scan_kernel<<<1, 1024>>>();
    scatter_kernel<<<(Ntot + 255) / 256, 256>>>(verts, Ntot);

    dim3 tb(256);
    dim3 tg(DIM / 32, DIM, DIM);
    transpose_kernel<<<tg, tb>>>(voxel);

    const int nTiles = (Ntot + TPW - 1) / TPW;
    const int blocks = (nTiles + 7) / 8;
    main_kernel<<<blocks, 256>>>(verts, (float*)d_out, Ntot);
}

// round 9
// speedup vs baseline: 1.6334x; 1.3890x over previous
#include <cuda_runtime.h>
#include <cuda_fp16.h>
#include <cstdint>

#define C_CH 32
#define DIM  128
#define NK   27
#define VOL_ELEMS (C_CH * DIM * DIM * DIM)
#define NCELL 4096            // 16x16x16 cells of 8^3 voxels
#define PERM_MAX (1 << 18)
#define TPW 16                // vertices per warp

#define ROWB 80               // bytes per feat row (16 fp16 padded to 80B: bank-clean)
#define WFEAT (16 * ROWB)     // 1280B per warp feat tile
#define GB_WORDS (NK * 512)   // pre-packed B-fragment words (13824)

// Scratch (device globals: allocation-free per harness rules)
__device__ __half g_volh[VOL_ELEMS];          // channel-last fp16 volume
__device__ float g_G[NK * C_CH * C_CH];       // [k][c][o] folded weights (fp32)
__device__ unsigned g_Gb[GB_WORDS];           // fp16 B-fragments, mma lane layout
__device__ float g_bias[C_CH];
__device__ int   g_hist[NCELL];
__device__ int   g_base[NCELL];
__device__ int   g_perm[PERM_MAX];

// neighbour shifts (x = k/9-1, y = (k/3)%3-1, z = k%3-1) * 0.0625
#define M1 -0.0625f
#define P1  0.0625f
#define Z0  0.0f
__constant__ float c_shx[NK] = {M1,M1,M1,M1,M1,M1,M1,M1,M1,
                                Z0,Z0,Z0,Z0,Z0,Z0,Z0,Z0,Z0,
                                P1,P1,P1,P1,P1,P1,P1,P1,P1};
__constant__ float c_shy[NK] = {M1,M1,M1,Z0,Z0,Z0,P1,P1,P1,
                                M1,M1,M1,Z0,Z0,Z0,P1,P1,P1,
                                M1,M1,M1,Z0,Z0,Z0,P1,P1,P1};
__constant__ float c_shz[NK] = {M1,Z0,P1,M1,Z0,P1,M1,Z0,P1,
                                M1,Z0,P1,M1,Z0,P1,M1,Z0,P1,
                                M1,Z0,P1,M1,Z0,P1,M1,Z0,P1};

// ---------------------------------------------------------------------------
// Prep 1 (27 blocks): M[k][j][o] = sum_c conv_w[o,c,k]*Wd[c,j]
// ---------------------------------------------------------------------------
__global__ __launch_bounds__(1024) void prep1_kernel(
    const float* __restrict__ w_d1, const float* __restrict__ w_d2,
    const float* __restrict__ conv_w)
{
    __shared__ float Wds[1024];    // Wd[c][j]
    __shared__ float convs[1024];  // conv[c][o] for this k
    const int tid = threadIdx.x, k = blockIdx.x;
    const int o = tid & 31, j = tid >> 5;

    {   // Wd = w_d2 @ w_d1
        float s = 0.f;
        #pragma unroll
        for (int m = 0; m < 32; m++)
            s += w_d2[(tid >> 5) * 32 + m] * w_d1[m * 32 + (tid & 31)];
        Wds[tid] = s;
    }
    convs[tid] = conv_w[(o * 32 + (tid >> 5)) * 27 + k];
    __syncthreads();

    float acc = 0.f;
    #pragma unroll
    for (int c = 0; c < 32; c++)
        acc += convs[c * 32 + o] * Wds[c * 32 + j];
    g_G[k * 1024 + j * 32 + o] = acc;
}

// ---------------------------------------------------------------------------
// Prep 2 (1 block): center-tap correction + fused bias + zero histograms
// + pack fp16 B-fragments (mma m16n8k16 lane layout) into g_Gb.
// ---------------------------------------------------------------------------
__global__ __launch_bounds__(1024) void prep2_kernel(
    const float* __restrict__ w_d2, const float* __restrict__ b_d1,
    const float* __restrict__ b_d2,
    const float* __restrict__ w_c1, const float* __restrict__ b_c1,
    const float* __restrict__ w_c2, const float* __restrict__ b_c2,
    const float* __restrict__ conv_w, const float* __restrict__ conv_b)
{
    __shared__ float Wcs[1024], part[1024], bds[32], bcs[32];
    const int tid = threadIdx.x;
    const int o = tid & 31, j = tid >> 5;

    #pragma unroll
    for (int i = 0; i < NCELL / 1024; i++) {
        g_hist[tid + 1024 * i] = 0;
        g_base[tid + 1024 * i] = 0;
    }

    {   // Wc = w_c2 @ w_c1
        float s = 0.f;
        #pragma unroll
        for (int m = 0; m < 32; m++)
            s += w_c2[(tid >> 5) * 32 + m] * w_c1[m * 32 + (tid & 31)];
        Wcs[tid] = s;
    }
    if (tid < 32) {
        float sd = 0.f, sc = 0.f;
        #pragma unroll
        for (int m = 0; m < 32; m++) {
            sd += w_d2[tid * 32 + m] * b_d1[m];
            sc += w_c2[tid * 32 + m] * b_c1[m];
        }
        bds[tid] = sd + b_d2[tid];
        bcs[tid] = sc + b_c2[tid];
    }
    float rs = 0.f;
    #pragma unroll
    for (int k = 0; k < NK; k++)
        rs += conv_w[(o * 32 + j) * 27 + k];
    __syncthreads();

    part[j * 32 + o] = bds[j] * rs;

    float S = 0.f;
    #pragma unroll
    for (int k = 0; k < NK; k++) S += g_G[k * 1024 + tid];
    g_G[13 * 1024 + tid] += Wcs[o * 32 + j] - S;
    __syncthreads();   // correction visible to all threads before packing

    // pack B-fragments: word i = k*512 + ks*256 + (nt*2+r)*32 + l
    // half2{ G[k][c][o], G[k][c+1][o] }, c = 16ks+8r+2(l&3), o = 8nt+(l>>2)
    for (int i = tid; i < GB_WORDS; i += 1024) {
        const int k = i >> 9;
        const int e = i & 511;
        const int ks = e >> 8;
        const int nt = (e >> 6) & 3;
        const int r  = (e >> 5) & 1;
        const int l  = e & 31;
        const int c  = 16 * ks + 8 * r + 2 * (l & 3);
        const int oo = 8 * nt + (l >> 2);
        __half2 h = __floats2half2_rn(g_G[k * 1024 + c * 32 + oo],
                                      g_G[k * 1024 + (c + 1) * 32 + oo]);
        g_Gb[i] = *reinterpret_cast<unsigned*>(&h);
    }

    if (tid < 32) {
        float a = 0.f;
        #pragma unroll
        for (int c = 0; c < 32; c++) a += part[c * 32 + tid];
        g_bias[tid] = a + conv_b[tid] + bcs[tid];
    }
}

// ---------------------------------------------------------------------------
// Transpose + convert: [C][D][H][W] fp32 -> channel-last fp16 [D][H][W][C].
// ---------------------------------------------------------------------------
__global__ __launch_bounds__(256) void transpose_kernel(const float* __restrict__ vin)
{
    __shared__ float tile[32][33];
    const int x0 = blockIdx.x * 32;
    const int y = blockIdx.y, z = blockIdx.z;
    const int tid = threadIdx.x;
    const int tx = tid & 31, ty = tid >> 5;

    #pragma unroll
    for (int i = 0; i < 4; i++) {
        const int c = ty + 8 * i;
        tile[c][tx] = vin[(((size_t)c * DIM + z) * DIM + y) * DIM + x0 + tx];
    }
    __syncthreads();

    const int g  = tid & 7;          // channel quad (4 halves = 8B)
    const int xx = tid >> 3;         // x within tile (0..31)
    const size_t obase = ((size_t)z * DIM + y) * DIM + x0;

    __half2 h01 = __floats2half2_rn(tile[4 * g + 0][xx], tile[4 * g + 1][xx]);
    __half2 h23 = __floats2half2_rn(tile[4 * g + 2][xx], tile[4 * g + 3][xx]);
    uint2 u;
    u.x = *reinterpret_cast<unsigned*>(&h01);
    u.y = *reinterpret_cast<unsigned*>(&h23);
    reinterpret_cast<uint2*>(g_volh + (obase + xx) * C_CH)[g] = u;
}

// ---------------------------------------------------------------------------
// Vertex binning: histogram -> scan -> scatter (cells of 8^3 voxels).
// ---------------------------------------------------------------------------
__device__ __forceinline__ int cell_of(float x, float y, float z)
{
    float px = fminf(fmaxf((x + 1.f) * 63.5f, 0.f), 127.f);
    float py = fminf(fmaxf((y + 1.f) * 63.5f, 0.f), 127.f);
    float pz = fminf(fmaxf((z + 1.f) * 63.5f, 0.f), 127.f);
    const int cx = ((int)px) >> 3, cy = ((int)py) >> 3, cz = ((int)pz) >> 3;
    return (cz << 8) | (cy << 4) | cx;
}

__global__ void count_kernel(const float* __restrict__ verts, int Ntot)
{
    const int n = blockIdx.x * blockDim.x + threadIdx.x;
    if (n >= Ntot) return;
    atomicAdd(&g_hist[cell_of(verts[3 * n], verts[3 * n + 1], verts[3 * n + 2])], 1);
}

__global__ __launch_bounds__(1024) void scan_kernel()
{
    __shared__ int sh[1024];
    const int t = threadIdx.x;
    int h0 = g_hist[4 * t], h1 = g_hist[4 * t + 1],
        h2 = g_hist[4 * t + 2], h3 = g_hist[4 * t + 3];
    const int mysum = h0 + h1 + h2 + h3;
    sh[t] = mysum;
    __syncthreads();
    for (int off = 1; off < 1024; off <<= 1) {
        int v = (t >= off) ? sh[t - off] : 0;
        __syncthreads();
        sh[t] += v;
        __syncthreads();
    }
    int e = sh[t] - mysum;
    g_base[4 * t]     = e;
    g_base[4 * t + 1] = e + h0;
    g_base[4 * t + 2] = e + h0 + h1;
    g_base[4 * t + 3] = e + h0 + h1 + h2;
}

__global__ void scatter_kernel(const float* __restrict__ verts, int Ntot)
{
    const int n = blockIdx.x * blockDim.x + threadIdx.x;
    if (n >= Ntot) return;
    const int c = cell_of(verts[3 * n], verts[3 * n + 1], verts[3 * n + 2]);
    const int pos = atomicAdd(&g_base[c], 1);
    g_perm[pos] = n;
}

// ---------------------------------------------------------------------------
// uint2 (4 halves) -> float4
// ---------------------------------------------------------------------------
__device__ __forceinline__ float4 h4_to_f4(uint2 u)
{
    const __half2 a = *reinterpret_cast<const __half2*>(&u.x);
    const __half2 b = *reinterpret_cast<const __half2*>(&u.y);
    const float2 lo = __half22float2(a);
    const float2 hi = __half22float2(b);
    return make_float4(lo.x, lo.y, hi.x, hi.y);
}

__device__ __forceinline__ void mma_16816(
    float* d, unsigned a0, unsigned a1, unsigned a2, unsigned a3,
    unsigned b0, unsigned b1)
{
    asm volatile(
        "mma.sync.aligned.m16n8k16.row.col.f32.f16.f16.f32 "
        "{%0,%1,%2,%3}, {%4,%5,%6,%7}, {%8,%9}, {%0,%1,%2,%3};"
        : "+f"(d[0]), "+f"(d[1]), "+f"(d[2]), "+f"(d[3])
        : "r"(a0), "r"(a1), "r"(a2), "r"(a3), "r"(b0), "r"(b1));
}

// ---------------------------------------------------------------------------
// Fused sample + tensor-core GEMM. One warp = 16 vertices.
// Sampling: lane = (vertex-quad, channel-quad), fp16 corner LDG.64, fp32
// trilinear, fp16 feats -> smem tile [16v][32c] (80B rows). Reduction:
// ldmatrix A-frags + pre-packed B-frags from global + HMMA fp32 accum.
// ---------------------------------------------------------------------------
__global__ __launch_bounds__(256, 3) void main_kernel(
    const float* __restrict__ verts, float* __restrict__ out, int Ntot)
{
    __shared__ __align__(16) unsigned char feats[8 * WFEAT];
    const int warp = threadIdx.x >> 5, lane = threadIdx.x & 31;
    const int nTiles = (Ntot + TPW - 1) / TPW;
    const int tile = blockIdx.x * 8 + warp;
    if (tile >= nTiles) return;

    const int n0 = tile * TPW;
    const int v = lane & 15;
    const int idx = n0 + v;
    const bool valid = (idx < Ntot);
    const int n = valid ? g_perm[idx] : 0;

    float gxv = 0.f, gyv = 0.f, gzv = 0.f;
    if (valid) {
        gxv = verts[3 * n + 0];
        gyv = verts[3 * n + 1];
        gzv = verts[3 * n + 2];
    }

    const int c4 = lane & 7;              // channel quad
    const int v4 = lane >> 3;             // vertex within group of 4

    unsigned char* fb = feats + warp * WFEAT;
    const unsigned fb_s = (unsigned)__cvta_generic_to_shared(fb);

    // ldmatrix.x4 addresses: group g = lane>>3:
    //   g0: rows 0-7 colB 0 | g1: rows 8-15 colB 0 | g2: rows 0-7 colB 16B | g3: rows 8-15 colB 16B
    const int lg = lane >> 3;
    const unsigned arow = (lane & 7) + ((lg & 1) << 3);
    const unsigned lm0 = fb_s + arow * ROWB + ((lg >> 1) << 4);  // ks=0 (c 0-15)
    const unsigned lm1 = lm0 + 32;                                // ks=1 (c 16-31)

    float d[4][4];
    #pragma unroll
    for (int i = 0; i < 4; i++)
        #pragma unroll
        for (int q = 0; q < 4; q++) d[i][q] = 0.f;

    #pragma unroll 1
    for (int k = 0; k < NK; k++) {
        const float gx = gxv + c_shx[k];
        const float gy = gyv + c_shy[k];
        const float gz = gzv + c_shz[k];
        float px = fminf(fmaxf((gx + 1.f) * 63.5f, 0.f), 127.f);
        float py = fminf(fmaxf((gy + 1.f) * 63.5f, 0.f), 127.f);
        float pz = fminf(fmaxf((gz + 1.f) * 63.5f, 0.f), 127.f);
        const float fx = floorf(px), fy = floorf(py), fz = floorf(pz);
        const int ix = (int)fx, iy = (int)fy, iz = (int)fz;
        const float wx = px - fx, wy = py - fy, wz = pz - fz;
        const int base = iz * (DIM * DIM * C_CH) + iy * (DIM * C_CH) + ix * C_CH;
        const int sx = (ix < DIM - 1) ? (C_CH >> 2) : 0;             // uint2 units
        const int sy = (iy < DIM - 1) ? (DIM * C_CH >> 2) : 0;
        const int sz = (iz < DIM - 1) ? (DIM * DIM * C_CH >> 2) : 0;

        #pragma unroll
        for (int g4 = 0; g4 < 4; g4++) {
            const int src = g4 * 4 + v4;
            const int b   = __shfl_sync(0xffffffffu, base, src);
            const int sx4 = __shfl_sync(0xffffffffu, sx, src);
            const int sy4 = __shfl_sync(0xffffffffu, sy, src);
            const int sz4 = __shfl_sync(0xffffffffu, sz, src);
            const float wxv = __shfl_sync(0xffffffffu, wx, src);
            const float wyv = __shfl_sync(0xffffffffu, wy, src);
            const float wzv = __shfl_sync(0xffffffffu, wz, src);

            const uint2* p = reinterpret_cast<const uint2*>(g_volh + b) + c4;
            const float4 f000 = h4_to_f4(__ldg(p));
            const float4 f001 = h4_to_f4(__ldg(p + sx4));
            const float4 f010 = h4_to_f4(__ldg(p + sy4));
            const float4 f011 = h4_to_f4(__ldg(p + sy4 + sx4));
            const float4 f100 = h4_to_f4(__ldg(p + sz4));
            const float4 f101 = h4_to_f4(__ldg(p + sz4 + sx4));
            const float4 f110 = h4_to_f4(__ldg(p + sz4 + sy4));
            const float4 f111 = h4_to_f4(__ldg(p + sz4 + sy4 + sx4));

            const float ax0 = 1.f - wxv, ay0 = 1.f - wyv, az0 = 1.f - wzv;
            const float c00 = az0 * ay0, c01 = az0 * wyv;
            const float c10 = wzv * ay0, c11 = wzv * wyv;
            const float w000 = c00 * ax0, w001 = c00 * wxv;
            const float w010 = c01 * ax0, w011 = c01 * wxv;
            const float w100 = c10 * ax0, w101 = c10 * wxv;
            const float w110 = c11 * ax0, w111 = c11 * wxv;

            float rx = f000.x * w000, ry = f000.y * w000,
                  rz = f000.z * w000, rw = f000.w * w000;
            rx = fmaf(f001.x, w001, rx); ry = fmaf(f001.y, w001, ry);
            rz = fmaf(f001.z, w001, rz); rw = fmaf(f001.w, w001, rw);
            rx = fmaf(f010.x, w010, rx); ry = fmaf(f010.y, w010, ry);
            rz = fmaf(f010.z, w010, rz); rw = fmaf(f010.w, w010, rw);
            rx = fmaf(f011.x, w011, rx); ry = fmaf(f011.y, w011, ry);
            rz = fmaf(f011.z, w011, rz); rw = fmaf(f011.w, w011, rw);
            rx = fmaf(f100.x, w100, rx); ry = fmaf(f100.y, w100, ry);
            rz = fmaf(f100.z, w100, rz); rw = fmaf(f100.w, w100, rw);
            rx = fmaf(f101.x, w101, rx); ry = fmaf(f101.y, w101, ry);
            rz = fmaf(f101.z, w101, rz); rw = fmaf(f101.w, w101, rw);
            rx = fmaf(f110.x, w110, rx); ry = fmaf(f110.y, w110, ry);
            rz = fmaf(f110.z, w110, rz); rw = fmaf(f110.w, w110, rw);
            rx = fmaf(f111.x, w111, rx); ry = fmaf(f111.y, w111, ry);
            rz = fmaf(f111.z, w111, rz); rw = fmaf(f111.w, w111, rw);

            __half2 h0 = __floats2half2_rn(rx, ry);
            __half2 h1 = __floats2half2_rn(rz, rw);
            uint2 u;
            u.x = *reinterpret_cast<unsigned*>(&h0);
            u.y = *reinterpret_cast<unsigned*>(&h1);
            *reinterpret_cast<uint2*>(fb + src * ROWB + c4 * 8) = u;
        }
        __syncwarp();

        // A fragments via ldmatrix (row-major feats [16][32] fp16)
        unsigned a0, a1, a2, a3, a4, a5, a6, a7;
        asm volatile("ldmatrix.sync.aligned.m8n8.x4.shared.b16 {%0,%1,%2,%3}, [%4];"
                     : "=r"(a0), "=r"(a1), "=r"(a2), "=r"(a3) : "r"(lm0) : "memory");
        asm volatile("ldmatrix.sync.aligned.m8n8.x4.shared.b16 {%0,%1,%2,%3}, [%4];"
                     : "=r"(a4), "=r"(a5), "=r"(a6), "=r"(a7) : "r"(lm1) : "memory");

        // B fragments: pre-packed, coalesced LDG.32 (L1-resident 55KB table)
        const unsigned* gb = g_Gb + k * 512 + lane;
        #pragma unroll
        for (int nt = 0; nt < 4; nt++) {
            const unsigned b0 = __ldg(gb + (nt * 2 + 0) * 32);
            const unsigned b1 = __ldg(gb + (nt * 2 + 1) * 32);
            mma_16816(d[nt], a0, a1, a2, a3, b0, b1);
        }
        #pragma unroll
        for (int nt = 0; nt < 4; nt++) {
            const unsigned b0 = __ldg(gb + 256 + (nt * 2 + 0) * 32);
            const unsigned b1 = __ldg(gb + 256 + (nt * 2 + 1) * 32);
            mma_16816(d[nt], a4, a5, a6, a7, b0, b1);
        }
        __syncwarp();
    }

    // epilogue: D fragment rows {lane>>2, +8}, cols 2*(lane&3)+{0,1} per n-tile
    const int r0 = lane >> 2, r1 = r0 + 8;
    const int cb = 2 * (lane & 3);
    const int i0 = n0 + r0, i1 = n0 + r1;
    const int p0 = (i0 < Ntot) ? g_perm[i0] : -1;
    const int p1 = (i1 < Ntot) ? g_perm[i1] : -1;

    #pragma unroll
    for (int nt = 0; nt < 4; nt++) {
        const int col = 8 * nt + cb;
        const float blo = __ldg(&g_bias[col]);
        const float bhi = __ldg(&g_bias[col + 1]);
        if (p0 >= 0) {
            float2 w0 = make_float2(d[nt][0] + blo, d[nt][1] + bhi);
            *reinterpret_cast<float2*>(out + p0 * C_CH + col) = w0;
        }
        if (p1 >= 0) {
            float2 w1 = make_float2(d[nt][2] + blo, d[nt][3] + bhi);
            *reinterpret_cast<float2*>(out + p1 * C_CH + col) = w1;
        }
    }
}

// ---------------------------------------------------------------------------
extern "C" void kernel_launch(void* const* d_in, const int* in_sizes, int n_in,
                              void* d_out, int out_size)
{
    const float* voxel = (const float*)d_in[0];
    const float* verts = (const float*)d_in[1];
    const int Ntot = in_sizes[1] / 3;

    prep1_kernel<<<27, 1024>>>(
        (const float*)d_in[2], (const float*)d_in[4], (const float*)d_in[10]);

    prep2_kernel<<<1, 1024>>>(
        (const float*)d_in[4], (const float*)d_in[3], (const float*)d_in[5],
        (const float*)d_in[6], (const float*)d_in[7], (const float*)d_in[8],
        (const float*)d_in[9], (const float*)d_in[10], (const float*)d_in[11]);

    count_kernel<<<(Ntot + 255) / 256, 256>>>(verts, Ntot);
    scan_kernel<<<1, 1024>>>();
    scatter_kernel<<<(Ntot + 255) / 256, 256>>>(verts, Ntot);

    dim3 tb(256);
    dim3 tg(DIM / 32, DIM, DIM);
    transpose_kernel<<<tg, tb>>>(voxel);

    const int nTiles = (Ntot + TPW - 1) / TPW;
    const int blocks = (nTiles + 7) / 8;
    main_kernel<<<blocks, 256>>>(verts, (float*)d_out, Ntot);
}

// round 10
// speedup vs baseline: 1.6382x; 1.0029x over previous
#include <cuda_runtime.h>
#include <cuda_fp16.h>
#include <cstdint>

#define C_CH 32
#define DIM  128
#define NK   27
#define VOL_ELEMS (C_CH * DIM * DIM * DIM)
#define NCELL 4096            // 16x16x16 cells of 8^3 voxels
#define PERM_MAX (1 << 18)
#define TPW 16                // vertices per tile

#define ROWB 80               // bytes per feat row (16 fp16 padded to 80B)
#define WFEAT (16 * ROWB)     // 1280B per warp feat tile
#define GB_WORDS (NK * 512)   // pre-packed B-fragment words (13824)

// Scratch (device globals: allocation-free per harness rules)
__device__ __half g_volh[VOL_ELEMS];          // channel-last fp16 volume
__device__ float g_G[NK * C_CH * C_CH];       // [k][c][o] folded weights (fp32)
__device__ unsigned g_Gb[GB_WORDS];           // fp16 B-frags, paired lane layout
__device__ float g_bias[C_CH];
__device__ int   g_hist[NCELL];
__device__ int   g_base[NCELL];
__device__ int   g_perm[PERM_MAX];

// neighbour shifts (x = k/9-1, y = (k/3)%3-1, z = k%3-1) * 0.0625
#define M1 -0.0625f
#define P1  0.0625f
#define Z0  0.0f
__constant__ float c_shx[NK] = {M1,M1,M1,M1,M1,M1,M1,M1,M1,
                                Z0,Z0,Z0,Z0,Z0,Z0,Z0,Z0,Z0,
                                P1,P1,P1,P1,P1,P1,P1,P1,P1};
__constant__ float c_shy[NK] = {M1,M1,M1,Z0,Z0,Z0,P1,P1,P1,
                                M1,M1,M1,Z0,Z0,Z0,P1,P1,P1,
                                M1,M1,M1,Z0,Z0,Z0,P1,P1,P1};
__constant__ float c_shz[NK] = {M1,Z0,P1,M1,Z0,P1,M1,Z0,P1,
                                M1,Z0,P1,M1,Z0,P1,M1,Z0,P1,
                                M1,Z0,P1,M1,Z0,P1,M1,Z0,P1};

// ---------------------------------------------------------------------------
// Prep 1 (27 blocks): M[k][j][o] = sum_c conv_w[o,c,k]*Wd[c,j]
// ---------------------------------------------------------------------------
__global__ __launch_bounds__(1024) void prep1_kernel(
    const float* __restrict__ w_d1, const float* __restrict__ w_d2,
    const float* __restrict__ conv_w)
{
    __shared__ float Wds[1024];    // Wd[c][j]
    __shared__ float convs[1024];  // conv[c][o] for this k
    const int tid = threadIdx.x, k = blockIdx.x;
    const int o = tid & 31, j = tid >> 5;

    {   // Wd = w_d2 @ w_d1
        float s = 0.f;
        #pragma unroll
        for (int m = 0; m < 32; m++)
            s += w_d2[(tid >> 5) * 32 + m] * w_d1[m * 32 + (tid & 31)];
        Wds[tid] = s;
    }
    convs[tid] = conv_w[(o * 32 + (tid >> 5)) * 27 + k];
    __syncthreads();

    float acc = 0.f;
    #pragma unroll
    for (int c = 0; c < 32; c++)
        acc += convs[c * 32 + o] * Wds[c * 32 + j];
    g_G[k * 1024 + j * 32 + o] = acc;
}

// ---------------------------------------------------------------------------
// Prep 2 (1 block): center-tap correction + fused bias + zero histograms
// + pack fp16 B-fragments (paired b0/b1 per lane) into g_Gb.
// ---------------------------------------------------------------------------
__global__ __launch_bounds__(1024) void prep2_kernel(
    const float* __restrict__ w_d2, const float* __restrict__ b_d1,
    const float* __restrict__ b_d2,
    const float* __restrict__ w_c1, const float* __restrict__ b_c1,
    const float* __restrict__ w_c2, const float* __restrict__ b_c2,
    const float* __restrict__ conv_w, const float* __restrict__ conv_b)
{
    __shared__ float Wcs[1024], part[1024], bds[32], bcs[32];
    const int tid = threadIdx.x;
    const int o = tid & 31, j = tid >> 5;

    #pragma unroll
    for (int i = 0; i < NCELL / 1024; i++) {
        g_hist[tid + 1024 * i] = 0;
        g_base[tid + 1024 * i] = 0;
    }

    {   // Wc = w_c2 @ w_c1
        float s = 0.f;
        #pragma unroll
        for (int m = 0; m < 32; m++)
            s += w_c2[(tid >> 5) * 32 + m] * w_c1[m * 32 + (tid & 31)];
        Wcs[tid] = s;
    }
    if (tid < 32) {
        float sd = 0.f, sc = 0.f;
        #pragma unroll
        for (int m = 0; m < 32; m++) {
            sd += w_d2[tid * 32 + m] * b_d1[m];
            sc += w_c2[tid * 32 + m] * b_c1[m];
        }
        bds[tid] = sd + b_d2[tid];
        bcs[tid] = sc + b_c2[tid];
    }
    float rs = 0.f;
    #pragma unroll
    for (int k = 0; k < NK; k++)
        rs += conv_w[(o * 32 + j) * 27 + k];
    __syncthreads();

    part[j * 32 + o] = bds[j] * rs;

    float S = 0.f;
    #pragma unroll
    for (int k = 0; k < NK; k++) S += g_G[k * 1024 + tid];
    g_G[13 * 1024 + tid] += Wcs[o * 32 + j] - S;
    __syncthreads();   // correction visible before packing

    // pack B-fragments, paired: word i = k*512 + ks*256 + nt*64 + 2l + r
    // half2{ G[k][c][o], G[k][c+1][o] }, c = 16ks+8r+2(l&3), o = 8nt+(l>>2)
    for (int i = tid; i < GB_WORDS; i += 1024) {
        const int k = i >> 9;
        const int e = i & 511;
        const int ks = e >> 8;
        const int nt = (e >> 6) & 3;
        const int l  = (e >> 1) & 31;
        const int r  = e & 1;
        const int c  = 16 * ks + 8 * r + 2 * (l & 3);
        const int oo = 8 * nt + (l >> 2);
        __half2 h = __floats2half2_rn(g_G[k * 1024 + c * 32 + oo],
                                      g_G[k * 1024 + (c + 1) * 32 + oo]);
        g_Gb[i] = *reinterpret_cast<unsigned*>(&h);
    }

    if (tid < 32) {
        float a = 0.f;
        #pragma unroll
        for (int c = 0; c < 32; c++) a += part[c * 32 + tid];
        g_bias[tid] = a + conv_b[tid] + bcs[tid];
    }
}

// ---------------------------------------------------------------------------
// Transpose + convert: [C][D][H][W] fp32 -> channel-last fp16 [D][H][W][C].
// ---------------------------------------------------------------------------
__global__ __launch_bounds__(256) void transpose_kernel(const float* __restrict__ vin)
{
    __shared__ float tile[32][33];
    const int x0 = blockIdx.x * 32;
    const int y = blockIdx.y, z = blockIdx.z;
    const int tid = threadIdx.x;
    const int tx = tid & 31, ty = tid >> 5;

    #pragma unroll
    for (int i = 0; i < 4; i++) {
        const int c = ty + 8 * i;
        tile[c][tx] = vin[(((size_t)c * DIM + z) * DIM + y) * DIM + x0 + tx];
    }
    __syncthreads();

    const int g  = tid & 7;          // channel quad (4 halves = 8B)
    const int xx = tid >> 3;         // x within tile (0..31)
    const size_t obase = ((size_t)z * DIM + y) * DIM + x0;

    __half2 h01 = __floats2half2_rn(tile[4 * g + 0][xx], tile[4 * g + 1][xx]);
    __half2 h23 = __floats2half2_rn(tile[4 * g + 2][xx], tile[4 * g + 3][xx]);
    uint2 u;
    u.x = *reinterpret_cast<unsigned*>(&h01);
    u.y = *reinterpret_cast<unsigned*>(&h23);
    reinterpret_cast<uint2*>(g_volh + (obase + xx) * C_CH)[g] = u;
}

// ---------------------------------------------------------------------------
// Vertex binning: histogram -> scan -> scatter (cells of 8^3 voxels).
// ---------------------------------------------------------------------------
__device__ __forceinline__ int cell_of(float x, float y, float z)
{
    float px = fminf(fmaxf((x + 1.f) * 63.5f, 0.f), 127.f);
    float py = fminf(fmaxf((y + 1.f) * 63.5f, 0.f), 127.f);
    float pz = fminf(fmaxf((z + 1.f) * 63.5f, 0.f), 127.f);
    const int cx = ((int)px) >> 3, cy = ((int)py) >> 3, cz = ((int)pz) >> 3;
    return (cz << 8) | (cy << 4) | cx;
}

__global__ void count_kernel(const float* __restrict__ verts, int Ntot)
{
    const int n = blockIdx.x * blockDim.x + threadIdx.x;
    if (n >= Ntot) return;
    atomicAdd(&g_hist[cell_of(verts[3 * n], verts[3 * n + 1], verts[3 * n + 2])], 1);
}

__global__ __launch_bounds__(1024) void scan_kernel()
{
    __shared__ int sh[1024];
    const int t = threadIdx.x;
    int h0 = g_hist[4 * t], h1 = g_hist[4 * t + 1],
        h2 = g_hist[4 * t + 2], h3 = g_hist[4 * t + 3];
    const int mysum = h0 + h1 + h2 + h3;
    sh[t] = mysum;
    __syncthreads();
    for (int off = 1; off < 1024; off <<= 1) {
        int v = (t >= off) ? sh[t - off] : 0;
        __syncthreads();
        sh[t] += v;
        __syncthreads();
    }
    int e = sh[t] - mysum;
    g_base[4 * t]     = e;
    g_base[4 * t + 1] = e + h0;
    g_base[4 * t + 2] = e + h0 + h1;
    g_base[4 * t + 3] = e + h0 + h1 + h2;
}

__global__ void scatter_kernel(const float* __restrict__ verts, int Ntot)
{
    const int n = blockIdx.x * blockDim.x + threadIdx.x;
    if (n >= Ntot) return;
    const int c = cell_of(verts[3 * n], verts[3 * n + 1], verts[3 * n + 2]);
    const int pos = atomicAdd(&g_base[c], 1);
    g_perm[pos] = n;
}

// ---------------------------------------------------------------------------
__device__ __forceinline__ float4 h4_to_f4(uint2 u)
{
    const __half2 a = *reinterpret_cast<const __half2*>(&u.x);
    const __half2 b = *reinterpret_cast<const __half2*>(&u.y);
    const float2 lo = __half22float2(a);
    const float2 hi = __half22float2(b);
    return make_float4(lo.x, lo.y, hi.x, hi.y);
}

__device__ __forceinline__ void mma_16816(
    float* d, unsigned a0, unsigned a1, unsigned a2, unsigned a3,
    unsigned b0, unsigned b1)
{
    asm volatile(
        "mma.sync.aligned.m16n8k16.row.col.f32.f16.f16.f32 "
        "{%0,%1,%2,%3}, {%4,%5,%6,%7}, {%8,%9}, {%0,%1,%2,%3};"
        : "+f"(d[0]), "+f"(d[1]), "+f"(d[2]), "+f"(d[3])
        : "r"(a0), "r"(a1), "r"(a2), "r"(a3), "r"(b0), "r"(b1));
}

// ---------------------------------------------------------------------------
// Fused sample + tensor-core GEMM with 2-way SPLIT-K over neighbours.
// Block = 8 warps = 4 tiles x 2 k-halves. Each warp samples+mma's its half
// of k for its 16-vertex tile; khalf=1 dumps D-fragments to smem; khalf=0
// adds and writes the output. Doubles resident warps at zero per-vertex cost.
// ---------------------------------------------------------------------------
__global__ __launch_bounds__(256, 3) void main_kernel(
    const float* __restrict__ verts, float* __restrict__ out, int Ntot)
{
    __shared__ __align__(16) unsigned char feats[8 * WFEAT];
    __shared__ float partial[4 * 16 * 32];      // [tib][q][lane]
    const int warp = threadIdx.x >> 5, lane = threadIdx.x & 31;
    const int tib = warp >> 1, khalf = warp & 1;
    const int nTiles = (Ntot + TPW - 1) / TPW;
    const int tile = blockIdx.x * 4 + tib;
    const bool live = (tile < nTiles);

    const int n0 = tile * TPW;
    const int v = lane & 15;
    const int idx = n0 + v;
    const bool valid = live && (idx < Ntot);
    const int n = valid ? g_perm[idx] : 0;

    float gxv = 0.f, gyv = 0.f, gzv = 0.f;
    if (valid) {
        gxv = verts[3 * n + 0];
        gyv = verts[3 * n + 1];
        gzv = verts[3 * n + 2];
    }

    const int c4 = lane & 7;              // channel quad
    const int v4 = lane >> 3;             // vertex within group of 4

    unsigned char* fb = feats + warp * WFEAT;
    const unsigned fb_s = (unsigned)__cvta_generic_to_shared(fb);

    const int lg = lane >> 3;
    const unsigned arow = (lane & 7) + ((lg & 1) << 3);
    const unsigned lm0 = fb_s + arow * ROWB + ((lg >> 1) << 4);  // ks=0
    const unsigned lm1 = lm0 + 32;                                // ks=1

    float d[4][4];
    #pragma unroll
    for (int i = 0; i < 4; i++)
        #pragma unroll
        for (int q = 0; q < 4; q++) d[i][q] = 0.f;

    const int k0 = khalf ? 14 : 0;
    const int k1 = khalf ? NK : 14;

    if (live) {
        #pragma unroll 1
        for (int k = k0; k < k1; k++) {
            const float gx = gxv + c_shx[k];
            const float gy = gyv + c_shy[k];
            const float gz = gzv + c_shz[k];
            float px = fminf(fmaxf((gx + 1.f) * 63.5f, 0.f), 127.f);
            float py = fminf(fmaxf((gy + 1.f) * 63.5f, 0.f), 127.f);
            float pz = fminf(fmaxf((gz + 1.f) * 63.5f, 0.f), 127.f);
            const float fx = floorf(px), fy = floorf(py), fz = floorf(pz);
            const int ix = (int)fx, iy = (int)fy, iz = (int)fz;
            const float wx = px - fx, wy = py - fy, wz = pz - fz;
            const int base = iz * (DIM * DIM * C_CH) + iy * (DIM * C_CH) + ix * C_CH;
            const int sx = (ix < DIM - 1) ? (C_CH >> 2) : 0;         // uint2 units
            const int sy = (iy < DIM - 1) ? (DIM * C_CH >> 2) : 0;
            const int sz = (iz < DIM - 1) ? (DIM * DIM * C_CH >> 2) : 0;

            #pragma unroll
            for (int g4 = 0; g4 < 4; g4++) {
                const int src = g4 * 4 + v4;
                const int b   = __shfl_sync(0xffffffffu, base, src);
                const int sx4 = __shfl_sync(0xffffffffu, sx, src);
                const int sy4 = __shfl_sync(0xffffffffu, sy, src);
                const int sz4 = __shfl_sync(0xffffffffu, sz, src);
                const float wxv = __shfl_sync(0xffffffffu, wx, src);
                const float wyv = __shfl_sync(0xffffffffu, wy, src);
                const float wzv = __shfl_sync(0xffffffffu, wz, src);

                const uint2* p = reinterpret_cast<const uint2*>(g_volh + b) + c4;
                const float4 f000 = h4_to_f4(__ldg(p));
                const float4 f001 = h4_to_f4(__ldg(p + sx4));
                const float4 f010 = h4_to_f4(__ldg(p + sy4));
                const float4 f011 = h4_to_f4(__ldg(p + sy4 + sx4));
                const float4 f100 = h4_to_f4(__ldg(p + sz4));
                const float4 f101 = h4_to_f4(__ldg(p + sz4 + sx4));
                const float4 f110 = h4_to_f4(__ldg(p + sz4 + sy4));
                const float4 f111 = h4_to_f4(__ldg(p + sz4 + sy4 + sx4));

                const float ax0 = 1.f - wxv, ay0 = 1.f - wyv, az0 = 1.f - wzv;
                const float c00 = az0 * ay0, c01 = az0 * wyv;
                const float c10 = wzv * ay0, c11 = wzv * wyv;
                const float w000 = c00 * ax0, w001 = c00 * wxv;
                const float w010 = c01 * ax0, w011 = c01 * wxv;
                const float w100 = c10 * ax0, w101 = c10 * wxv;
                const float w110 = c11 * ax0, w111 = c11 * wxv;

                float rx = f000.x * w000, ry = f000.y * w000,
                      rz = f000.z * w000, rw = f000.w * w000;
                rx = fmaf(f001.x, w001, rx); ry = fmaf(f001.y, w001, ry);
                rz = fmaf(f001.z, w001, rz); rw = fmaf(f001.w, w001, rw);
                rx = fmaf(f010.x, w010, rx); ry = fmaf(f010.y, w010, ry);
                rz = fmaf(f010.z, w010, rz); rw = fmaf(f010.w, w010, rw);
                rx = fmaf(f011.x, w011, rx); ry = fmaf(f011.y, w011, ry);
                rz = fmaf(f011.z, w011, rz); rw = fmaf(f011.w, w011, rw);
                rx = fmaf(f100.x, w100, rx); ry = fmaf(f100.y, w100, ry);
                rz = fmaf(f100.z, w100, rz); rw = fmaf(f100.w, w100, rw);
                rx = fmaf(f101.x, w101, rx); ry = fmaf(f101.y, w101, ry);
                rz = fmaf(f101.z, w101, rz); rw = fmaf(f101.w, w101, rw);
                rx = fmaf(f110.x, w110, rx); ry = fmaf(f110.y, w110, ry);
                rz = fmaf(f110.z, w110, rz); rw = fmaf(f110.w, w110, rw);
                rx = fmaf(f111.x, w111, rx); ry = fmaf(f111.y, w111, ry);
                rz = fmaf(f111.z, w111, rz); rw = fmaf(f111.w, w111, rw);

                __half2 h0 = __floats2half2_rn(rx, ry);
                __half2 h1 = __floats2half2_rn(rz, rw);
                uint2 u;
                u.x = *reinterpret_cast<unsigned*>(&h0);
                u.y = *reinterpret_cast<unsigned*>(&h1);
                *reinterpret_cast<uint2*>(fb + src * ROWB + c4 * 8) = u;
            }
            __syncwarp();

            unsigned a0, a1, a2, a3, a4, a5, a6, a7;
            asm volatile("ldmatrix.sync.aligned.m8n8.x4.shared.b16 {%0,%1,%2,%3}, [%4];"
                         : "=r"(a0), "=r"(a1), "=r"(a2), "=r"(a3) : "r"(lm0) : "memory");
            asm volatile("ldmatrix.sync.aligned.m8n8.x4.shared.b16 {%0,%1,%2,%3}, [%4];"
                         : "=r"(a4), "=r"(a5), "=r"(a6), "=r"(a7) : "r"(lm1) : "memory");

            // paired B fragments: LDG.64, coalesced
            const uint2* gb2 = reinterpret_cast<const uint2*>(g_Gb) +
                               k * 256 + lane;
            #pragma unroll
            for (int nt = 0; nt < 4; nt++) {
                const uint2 b01 = __ldg(gb2 + nt * 32);
                mma_16816(d[nt], a0, a1, a2, a3, b01.x, b01.y);
            }
            #pragma unroll
            for (int nt = 0; nt < 4; nt++) {
                const uint2 b01 = __ldg(gb2 + 128 + nt * 32);
                mma_16816(d[nt], a4, a5, a6, a7, b01.x, b01.y);
            }
            __syncwarp();
        }
    }

    // split-K combine: khalf=1 publishes, khalf=0 reduces + stores
    if (live && khalf) {
        #pragma unroll
        for (int nt = 0; nt < 4; nt++)
            #pragma unroll
            for (int q = 0; q < 4; q++)
                partial[tib * 512 + (nt * 4 + q) * 32 + lane] = d[nt][q];
    }
    __syncthreads();
    if (live && !khalf) {
        #pragma unroll
        for (int nt = 0; nt < 4; nt++)
            #pragma unroll
            for (int q = 0; q < 4; q++)
                d[nt][q] += partial[tib * 512 + (nt * 4 + q) * 32 + lane];

        const int r0 = lane >> 2;
        const int cb = 2 * (lane & 3);
        const int i0 = n0 + r0, i1 = i0 + 8;
        const int p0 = (i0 < Ntot) ? g_perm[i0] : -1;
        const int p1 = (i1 < Ntot) ? g_perm[i1] : -1;

        #pragma unroll
        for (int nt = 0; nt < 4; nt++) {
            const int col = 8 * nt + cb;
            const float blo = __ldg(&g_bias[col]);
            const float bhi = __ldg(&g_bias[col + 1]);
            if (p0 >= 0) {
                float2 w0 = make_float2(d[nt][0] + blo, d[nt][1] + bhi);
                *reinterpret_cast<float2*>(out + p0 * C_CH + col) = w0;
            }
            if (p1 >= 0) {
                float2 w1 = make_float2(d[nt][2] + blo, d[nt][3] + bhi);
                *reinterpret_cast<float2*>(out + p1 * C_CH + col) = w1;
            }
        }
    }
}

// ---------------------------------------------------------------------------
extern "C" void kernel_launch(void* const* d_in, const int* in_sizes, int n_in,
                              void* d_out, int out_size)
{
    const float* voxel = (const float*)d_in[0];
    const float* verts = (const float*)d_in[1];
    const int Ntot = in_sizes[1] / 3;

    prep1_kernel<<<27, 1024>>>(
        (const float*)d_in[2], (const float*)d_in[4], (const float*)d_in[10]);

    prep2_kernel<<<1, 1024>>>(
        (const float*)d_in[4], (const float*)d_in[3], (const float*)d_in[5],
        (const float*)d_in[6], (const float*)d_in[7], (const float*)d_in[8],
        (const float*)d_in[9], (const float*)d_in[10], (const float*)d_in[11]);

    count_kernel<<<(Ntot + 255) / 256, 256>>>(verts, Ntot);
    scan_kernel<<<1, 1024>>>();
    scatter_kernel<<<(Ntot + 255) / 256, 256>>>(verts, Ntot);

    dim3 tb(256);
    dim3 tg(DIM / 32, DIM, DIM);
    transpose_kernel<<<tg, tb>>>(voxel);

    const int nTiles = (Ntot + TPW - 1) / TPW;
    const int blocks = (nTiles + 3) / 4;
    main_kernel<<<blocks, 256>>>(verts, (float*)d_out, Ntot);
}

// round 11
// speedup vs baseline: 1.6834x; 1.0276x over previous
#include <cuda_runtime.h>
#include <cuda_fp16.h>
#include <cstdint>

#define C_CH 32
#define DIM  128
#define NK   27
#define VOL_ELEMS (C_CH * DIM * DIM * DIM)
#define NCELL 4096            // 16x16x16 cells of 8^3 voxels
#define PERM_MAX (1 << 18)
#define TPW 16                // vertices per tile

#define ROWB 80               // bytes per feat row (16 fp16 padded to 80B)
#define WFEAT (16 * ROWB)     // 1280B per warp feat tile
#define GB_WORDS (NK * 512)   // pre-packed B-fragment words (13824)

// Scratch (device globals: allocation-free per harness rules)
__device__ __half g_volh[VOL_ELEMS];          // channel-last fp16 volume
__device__ float g_G[NK * C_CH * C_CH];       // [k][c][o] folded weights (fp32)
__device__ unsigned g_Gb[GB_WORDS];           // fp16 B-frags, paired lane layout
__device__ float g_bias[C_CH];
__device__ int   g_hist[NCELL];
__device__ int   g_base[NCELL];
__device__ int   g_perm[PERM_MAX];

// neighbour shifts pre-scaled to pixel space: {-1,0,1} * 0.0625 * 63.5
#define M1 -3.96875f
#define P1  3.96875f
#define Z0  0.0f
__constant__ float c_shx[NK] = {M1,M1,M1,M1,M1,M1,M1,M1,M1,
                                Z0,Z0,Z0,Z0,Z0,Z0,Z0,Z0,Z0,
                                P1,P1,P1,P1,P1,P1,P1,P1,P1};
__constant__ float c_shy[NK] = {M1,M1,M1,Z0,Z0,Z0,P1,P1,P1,
                                M1,M1,M1,Z0,Z0,Z0,P1,P1,P1,
                                M1,M1,M1,Z0,Z0,Z0,P1,P1,P1};
__constant__ float c_shz[NK] = {M1,Z0,P1,M1,Z0,P1,M1,Z0,P1,
                                M1,Z0,P1,M1,Z0,P1,M1,Z0,P1,
                                M1,Z0,P1,M1,Z0,P1,M1,Z0,P1};

// ---------------------------------------------------------------------------
// Prep 1 (27 blocks): M[k][j][o] = sum_c conv_w[o,c,k]*Wd[c,j]
// ---------------------------------------------------------------------------
__global__ __launch_bounds__(1024) void prep1_kernel(
    const float* __restrict__ w_d1, const float* __restrict__ w_d2,
    const float* __restrict__ conv_w)
{
    __shared__ float Wds[1024];    // Wd[c][j]
    __shared__ float convs[1024];  // conv[c][o] for this k
    const int tid = threadIdx.x, k = blockIdx.x;
    const int o = tid & 31, j = tid >> 5;

    {   // Wd = w_d2 @ w_d1
        float s = 0.f;
        #pragma unroll
        for (int m = 0; m < 32; m++)
            s += w_d2[(tid >> 5) * 32 + m] * w_d1[m * 32 + (tid & 31)];
        Wds[tid] = s;
    }
    convs[tid] = conv_w[(o * 32 + (tid >> 5)) * 27 + k];
    __syncthreads();

    float acc = 0.f;
    #pragma unroll
    for (int c = 0; c < 32; c++)
        acc += convs[c * 32 + o] * Wds[c * 32 + j];
    g_G[k * 1024 + j * 32 + o] = acc;
}

// ---------------------------------------------------------------------------
// Prep 2 (1 block): center-tap correction + fused bias + zero histograms
// + pack fp16 B-fragments (paired b0/b1 per lane) into g_Gb.
// ---------------------------------------------------------------------------
__global__ __launch_bounds__(1024) void prep2_kernel(
    const float* __restrict__ w_d2, const float* __restrict__ b_d1,
    const float* __restrict__ b_d2,
    const float* __restrict__ w_c1, const float* __restrict__ b_c1,
    const float* __restrict__ w_c2, const float* __restrict__ b_c2,
    const float* __restrict__ conv_w, const float* __restrict__ conv_b)
{
    __shared__ float Wcs[1024], part[1024], bds[32], bcs[32];
    const int tid = threadIdx.x;
    const int o = tid & 31, j = tid >> 5;

    #pragma unroll
    for (int i = 0; i < NCELL / 1024; i++) {
        g_hist[tid + 1024 * i] = 0;
        g_base[tid + 1024 * i] = 0;
    }

    {   // Wc = w_c2 @ w_c1
        float s = 0.f;
        #pragma unroll
        for (int m = 0; m < 32; m++)
            s += w_c2[(tid >> 5) * 32 + m] * w_c1[m * 32 + (tid & 31)];
        Wcs[tid] = s;
    }
    if (tid < 32) {
        float sd = 0.f, sc = 0.f;
        #pragma unroll
        for (int m = 0; m < 32; m++) {
            sd += w_d2[tid * 32 + m] * b_d1[m];
            sc += w_c2[tid * 32 + m] * b_c1[m];
        }
        bds[tid] = sd + b_d2[tid];
        bcs[tid] = sc + b_c2[tid];
    }
    float rs = 0.f;
    #pragma unroll
    for (int k = 0; k < NK; k++)
        rs += conv_w[(o * 32 + j) * 27 + k];
    __syncthreads();

    part[j * 32 + o] = bds[j] * rs;

    float S = 0.f;
    #pragma unroll
    for (int k = 0; k < NK; k++) S += g_G[k * 1024 + tid];
    g_G[13 * 1024 + tid] += Wcs[o * 32 + j] - S;
    __syncthreads();   // correction visible before packing

    // pack B-fragments, paired: word i = k*512 + ks*256 + nt*64 + 2l + r
    // half2{ G[k][c][o], G[k][c+1][o] }, c = 16ks+8r+2(l&3), o = 8nt+(l>>2)
    for (int i = tid; i < GB_WORDS; i += 1024) {
        const int k = i >> 9;
        const int e = i & 511;
        const int ks = e >> 8;
        const int nt = (e >> 6) & 3;
        const int l  = (e >> 1) & 31;
        const int r  = e & 1;
        const int c  = 16 * ks + 8 * r + 2 * (l & 3);
        const int oo = 8 * nt + (l >> 2);
        __half2 h = __floats2half2_rn(g_G[k * 1024 + c * 32 + oo],
                                      g_G[k * 1024 + (c + 1) * 32 + oo]);
        g_Gb[i] = *reinterpret_cast<unsigned*>(&h);
    }

    if (tid < 32) {
        float a = 0.f;
        #pragma unroll
        for (int c = 0; c < 32; c++) a += part[c * 32 + tid];
        g_bias[tid] = a + conv_b[tid] + bcs[tid];
    }
}

// ---------------------------------------------------------------------------
// Transpose + convert: [C][D][H][W] fp32 -> channel-last fp16 [D][H][W][C].
// ---------------------------------------------------------------------------
__global__ __launch_bounds__(256) void transpose_kernel(const float* __restrict__ vin)
{
    __shared__ float tile[32][33];
    const int x0 = blockIdx.x * 32;
    const int y = blockIdx.y, z = blockIdx.z;
    const int tid = threadIdx.x;
    const int tx = tid & 31, ty = tid >> 5;

    #pragma unroll
    for (int i = 0; i < 4; i++) {
        const int c = ty + 8 * i;
        tile[c][tx] = vin[(((size_t)c * DIM + z) * DIM + y) * DIM + x0 + tx];
    }
    __syncthreads();

    const int g  = tid & 7;          // channel quad (4 halves = 8B)
    const int xx = tid >> 3;         // x within tile (0..31)
    const size_t obase = ((size_t)z * DIM + y) * DIM + x0;

    __half2 h01 = __floats2half2_rn(tile[4 * g + 0][xx], tile[4 * g + 1][xx]);
    __half2 h23 = __floats2half2_rn(tile[4 * g + 2][xx], tile[4 * g + 3][xx]);
    uint2 u;
    u.x = *reinterpret_cast<unsigned*>(&h01);
    u.y = *reinterpret_cast<unsigned*>(&h23);
    reinterpret_cast<uint2*>(g_volh + (obase + xx) * C_CH)[g] = u;
}

// ---------------------------------------------------------------------------
// Vertex binning: histogram -> scan -> scatter (cells of 8^3 voxels).
// ---------------------------------------------------------------------------
__device__ __forceinline__ int cell_of(float x, float y, float z)
{
    float px = fminf(fmaxf((x + 1.f) * 63.5f, 0.f), 127.f);
    float py = fminf(fmaxf((y + 1.f) * 63.5f, 0.f), 127.f);
    float pz = fminf(fmaxf((z + 1.f) * 63.5f, 0.f), 127.f);
    const int cx = ((int)px) >> 3, cy = ((int)py) >> 3, cz = ((int)pz) >> 3;
    return (cz << 8) | (cy << 4) | cx;
}

__global__ void count_kernel(const float* __restrict__ verts, int Ntot)
{
    const int n = blockIdx.x * blockDim.x + threadIdx.x;
    if (n >= Ntot) return;
    atomicAdd(&g_hist[cell_of(verts[3 * n], verts[3 * n + 1], verts[3 * n + 2])], 1);
}

__global__ __launch_bounds__(1024) void scan_kernel()
{
    __shared__ int sh[1024];
    const int t = threadIdx.x;
    int h0 = g_hist[4 * t], h1 = g_hist[4 * t + 1],
        h2 = g_hist[4 * t + 2], h3 = g_hist[4 * t + 3];
    const int mysum = h0 + h1 + h2 + h3;
    sh[t] = mysum;
    __syncthreads();
    for (int off = 1; off < 1024; off <<= 1) {
        int v = (t >= off) ? sh[t - off] : 0;
        __syncthreads();
        sh[t] += v;
        __syncthreads();
    }
    int e = sh[t] - mysum;
    g_base[4 * t]     = e;
    g_base[4 * t + 1] = e + h0;
    g_base[4 * t + 2] = e + h0 + h1;
    g_base[4 * t + 3] = e + h0 + h1 + h2;
}

__global__ void scatter_kernel(const float* __restrict__ verts, int Ntot)
{
    const int n = blockIdx.x * blockDim.x + threadIdx.x;
    if (n >= Ntot) return;
    const int c = cell_of(verts[3 * n], verts[3 * n + 1], verts[3 * n + 2]);
    const int pos = atomicAdd(&g_base[c], 1);
    g_perm[pos] = n;
}

// ---------------------------------------------------------------------------
__device__ __forceinline__ __half2 u2h(unsigned u)
{
    return *reinterpret_cast<__half2*>(&u);
}

__device__ __forceinline__ void mma_16816(
    float* d, unsigned a0, unsigned a1, unsigned a2, unsigned a3,
    unsigned b0, unsigned b1)
{
    asm volatile(
        "mma.sync.aligned.m16n8k16.row.col.f32.f16.f16.f32 "
        "{%0,%1,%2,%3}, {%4,%5,%6,%7}, {%8,%9}, {%0,%1,%2,%3};"
        : "+f"(d[0]), "+f"(d[1]), "+f"(d[2]), "+f"(d[3])
        : "r"(a0), "r"(a1), "r"(a2), "r"(a3), "r"(b0), "r"(b1));
}

// ---------------------------------------------------------------------------
// Fused sample + tensor-core GEMM, 2-way split-K over neighbours.
// Sampling trilinear is done ENTIRELY in fp16 (HFMA2, zero F2F converts):
// weights computed fp32, splat-packed once (cvt.rn.f16x2), 8-corner weighted
// sum as two z-partials + HADD2, stored directly as half2.
// ---------------------------------------------------------------------------
__global__ __launch_bounds__(256, 3) void main_kernel(
    const float* __restrict__ verts, float* __restrict__ out, int Ntot)
{
    __shared__ __align__(16) unsigned char feats[8 * WFEAT];
    __shared__ float partial[4 * 16 * 32];      // [tib][q][lane]
    const int warp = threadIdx.x >> 5, lane = threadIdx.x & 31;
    const int tib = warp >> 1, khalf = warp & 1;
    const int nTiles = (Ntot + TPW - 1) / TPW;
    const int tile = blockIdx.x * 4 + tib;
    const bool live = (tile < nTiles);

    const int n0 = tile * TPW;
    const int v = lane & 15;
    const int idx = n0 + v;
    const bool valid = live && (idx < Ntot);
    const int n = valid ? g_perm[idx] : 0;

    float px0 = 0.f, py0 = 0.f, pz0 = 0.f;   // hoisted pixel-space coords
    if (valid) {
        px0 = fmaf(verts[3 * n + 0], 63.5f, 63.5f);
        py0 = fmaf(verts[3 * n + 1], 63.5f, 63.5f);
        pz0 = fmaf(verts[3 * n + 2], 63.5f, 63.5f);
    }

    const int c4 = lane & 7;              // channel quad
    const int v4 = lane >> 3;             // vertex within group of 4

    unsigned char* fb = feats + warp * WFEAT;
    const unsigned fb_s = (unsigned)__cvta_generic_to_shared(fb);

    const int lg = lane >> 3;
    const unsigned arow = (lane & 7) + ((lg & 1) << 3);
    const unsigned lm0 = fb_s + arow * ROWB + ((lg >> 1) << 4);  // ks=0
    const unsigned lm1 = lm0 + 32;                                // ks=1

    float d[4][4];
    #pragma unroll
    for (int i = 0; i < 4; i++)
        #pragma unroll
        for (int q = 0; q < 4; q++) d[i][q] = 0.f;

    const int k0 = khalf ? 14 : 0;
    const int k1 = khalf ? NK : 14;

    if (live) {
        #pragma unroll 1
        for (int k = k0; k < k1; k++) {
            float px = fminf(fmaxf(px0 + c_shx[k], 0.f), 127.f);
            float py = fminf(fmaxf(py0 + c_shy[k], 0.f), 127.f);
            float pz = fminf(fmaxf(pz0 + c_shz[k], 0.f), 127.f);
            const float fx = floorf(px), fy = floorf(py), fz = floorf(pz);
            const int ix = (int)fx, iy = (int)fy, iz = (int)fz;
            const float wx = px - fx, wy = py - fy, wz = pz - fz;
            const int base = iz * (DIM * DIM * C_CH) + iy * (DIM * C_CH) + ix * C_CH;
            const int sx = (ix < DIM - 1) ? (C_CH >> 2) : 0;         // uint2 units
            const int sy = (iy < DIM - 1) ? (DIM * C_CH >> 2) : 0;
            const int sz = (iz < DIM - 1) ? (DIM * DIM * C_CH >> 2) : 0;

            #pragma unroll
            for (int g4 = 0; g4 < 4; g4++) {
                const int src = g4 * 4 + v4;
                const int b   = __shfl_sync(0xffffffffu, base, src);
                const int sx4 = __shfl_sync(0xffffffffu, sx, src);
                const int sy4 = __shfl_sync(0xffffffffu, sy, src);
                const int sz4 = __shfl_sync(0xffffffffu, sz, src);
                const float wxv = __shfl_sync(0xffffffffu, wx, src);
                const float wyv = __shfl_sync(0xffffffffu, wy, src);
                const float wzv = __shfl_sync(0xffffffffu, wz, src);

                const uint2* p = reinterpret_cast<const uint2*>(g_volh + b) + c4;
                const uint2 u000 = __ldg(p);
                const uint2 u001 = __ldg(p + sx4);
                const uint2 u010 = __ldg(p + sy4);
                const uint2 u011 = __ldg(p + sy4 + sx4);
                const uint2 u100 = __ldg(p + sz4);
                const uint2 u101 = __ldg(p + sz4 + sx4);
                const uint2 u110 = __ldg(p + sz4 + sy4);
                const uint2 u111 = __ldg(p + sz4 + sy4 + sx4);

                // corner weights in fp32, splat-packed to half2 (1 cvt each)
                const float ax0 = 1.f - wxv, ay0 = 1.f - wyv, az0 = 1.f - wzv;
                const float c00 = az0 * ay0, c01 = az0 * wyv;
                const float c10 = wzv * ay0, c11 = wzv * wyv;
                const __half2 h000 = __floats2half2_rn(c00 * ax0, c00 * ax0);
                const __half2 h001 = __floats2half2_rn(c00 * wxv, c00 * wxv);
                const __half2 h010 = __floats2half2_rn(c01 * ax0, c01 * ax0);
                const __half2 h011 = __floats2half2_rn(c01 * wxv, c01 * wxv);
                const __half2 h100 = __floats2half2_rn(c10 * ax0, c10 * ax0);
                const __half2 h101 = __floats2half2_rn(c10 * wxv, c10 * wxv);
                const __half2 h110 = __floats2half2_rn(c11 * ax0, c11 * ax0);
                const __half2 h111 = __floats2half2_rn(c11 * wxv, c11 * wxv);

                // trilinear entirely in fp16: two z-partials + final add
                __half2 paX = __hmul2(h000, u2h(u000.x));
                paX = __hfma2(h001, u2h(u001.x), paX);
                paX = __hfma2(h010, u2h(u010.x), paX);
                paX = __hfma2(h011, u2h(u011.x), paX);
                __half2 pbX = __hmul2(h100, u2h(u100.x));
                pbX = __hfma2(h101, u2h(u101.x), pbX);
                pbX = __hfma2(h110, u2h(u110.x), pbX);
                pbX = __hfma2(h111, u2h(u111.x), pbX);
                __half2 rX = __hadd2(paX, pbX);

                __half2 paY = __hmul2(h000, u2h(u000.y));
                paY = __hfma2(h001, u2h(u001.y), paY);
                paY = __hfma2(h010, u2h(u010.y), paY);
                paY = __hfma2(h011, u2h(u011.y), paY);
                __half2 pbY = __hmul2(h100, u2h(u100.y));
                pbY = __hfma2(h101, u2h(u101.y), pbY);
                pbY = __hfma2(h110, u2h(u110.y), pbY);
                pbY = __hfma2(h111, u2h(u111.y), pbY);
                __half2 rY = __hadd2(paY, pbY);

                uint2 u;
                u.x = *reinterpret_cast<unsigned*>(&rX);
                u.y = *reinterpret_cast<unsigned*>(&rY);
                *reinterpret_cast<uint2*>(fb + src * ROWB + c4 * 8) = u;
            }
            __syncwarp();

            unsigned a0, a1, a2, a3, a4, a5, a6, a7;
            asm volatile("ldmatrix.sync.aligned.m8n8.x4.shared.b16 {%0,%1,%2,%3}, [%4];"
                         : "=r"(a0), "=r"(a1), "=r"(a2), "=r"(a3) : "r"(lm0) : "memory");
            asm volatile("ldmatrix.sync.aligned.m8n8.x4.shared.b16 {%0,%1,%2,%3}, [%4];"
                         : "=r"(a4), "=r"(a5), "=r"(a6), "=r"(a7) : "r"(lm1) : "memory");

            // paired B fragments: LDG.64, coalesced
            const uint2* gb2 = reinterpret_cast<const uint2*>(g_Gb) +
                               k * 256 + lane;
            #pragma unroll
            for (int nt = 0; nt < 4; nt++) {
                const uint2 b01 = __ldg(gb2 + nt * 32);
                mma_16816(d[nt], a0, a1, a2, a3, b01.x, b01.y);
            }
            #pragma unroll
            for (int nt = 0; nt < 4; nt++) {
                const uint2 b01 = __ldg(gb2 + 128 + nt * 32);
                mma_16816(d[nt], a4, a5, a6, a7, b01.x, b01.y);
            }
            __syncwarp();
        }
    }

    // split-K combine: khalf=1 publishes, khalf=0 reduces + stores
    if (live && khalf) {
        #pragma unroll
        for (int nt = 0; nt < 4; nt++)
            #pragma unroll
            for (int q = 0; q < 4; q++)
                partial[tib * 512 + (nt * 4 + q) * 32 + lane] = d[nt][q];
    }
    __syncthreads();
    if (live && !khalf) {
        #pragma unroll
        for (int nt = 0; nt < 4; nt++)
            #pragma unroll
            for (int q = 0; q < 4; q++)
                d[nt][q] += partial[tib * 512 + (nt * 4 + q) * 32 + lane];

        const int r0 = lane >> 2;
        const int cb = 2 * (lane & 3);
        const int i0 = n0 + r0, i1 = i0 + 8;
        const int p0 = (i0 < Ntot) ? g_perm[i0] : -1;
        const int p1 = (i1 < Ntot) ? g_perm[i1] : -1;

        #pragma unroll
        for (int nt = 0; nt < 4; nt++) {
            const int col = 8 * nt + cb;
            const float blo = __ldg(&g_bias[col]);
            const float bhi = __ldg(&g_bias[col + 1]);
            if (p0 >= 0) {
                float2 w0 = make_float2(d[nt][0] + blo, d[nt][1] + bhi);
                *reinterpret_cast<float2*>(out + p0 * C_CH + col) = w0;
            }
            if (p1 >= 0) {
                float2 w1 = make_float2(d[nt][2] + blo, d[nt][3] + bhi);
                *reinterpret_cast<float2*>(out + p1 * C_CH + col) = w1;
            }
        }
    }
}

// ---------------------------------------------------------------------------
extern "C" void kernel_launch(void* const* d_in, const int* in_sizes, int n_in,
                              void* d_out, int out_size)
{
    const float* voxel = (const float*)d_in[0];
    const float* verts = (const float*)d_in[1];
    const int Ntot = in_sizes[1] / 3;

    prep1_kernel<<<27, 1024>>>(
        (const float*)d_in[2], (const float*)d_in[4], (const float*)d_in[10]);

    prep2_kernel<<<1, 1024>>>(
        (const float*)d_in[4], (const float*)d_in[3], (const float*)d_in[5],
        (const float*)d_in[6], (const float*)d_in[7], (const float*)d_in[8],
        (const float*)d_in[9], (const float*)d_in[10], (const float*)d_in[11]);

    count_kernel<<<(Ntot + 255) / 256, 256>>>(verts, Ntot);
    scan_kernel<<<1, 1024>>>();
    scatter_kernel<<<(Ntot + 255) / 256, 256>>>(verts, Ntot);

    dim3 tb(256);
    dim3 tg(DIM / 32, DIM, DIM);
    transpose_kernel<<<tg, tb>>>(voxel);

    const int nTiles = (Ntot + TPW - 1) / TPW;
    const int blocks = (nTiles + 3) / 4;
    main_kernel<<<blocks, 256>>>(verts, (float*)d_out, Ntot);
}

// round 12
// speedup vs baseline: 1.7602x; 1.0456x over previous
#include <cuda_runtime.h>
#include <cuda_fp16.h>
#include <cstdint>

#define C_CH 32
#define DIM  128
#define NK   27
#define VOL_ELEMS (C_CH * DIM * DIM * DIM)
#define NCELL 4096            // 16x16x16 cells of 8^3 voxels
#define PERM_MAX (1 << 18)
#define TPW 16                // vertices per tile

#define ROWB 80               // bytes per feat row (16 fp16 padded to 80B)
#define WFEAT (16 * ROWB)     // 1280B per warp feat tile
#define GB_WORDS (NK * 512)   // pre-packed B-fragment words (13824)

// Scratch (device globals: allocation-free per harness rules)
__device__ __half g_volh[VOL_ELEMS];          // channel-last fp16 volume
__device__ float g_G[NK * C_CH * C_CH];       // [k][c][o] folded weights (fp32)
__device__ unsigned g_Gb[GB_WORDS];           // fp16 B-frags, paired lane layout
__device__ float g_bias[C_CH];
__device__ int   g_hist[NCELL];
__device__ int   g_base[NCELL];
__device__ int   g_perm[PERM_MAX];

// neighbour shifts pre-scaled to pixel space: {-1,0,1} * 0.0625 * 63.5
#define M1 -3.96875f
#define P1  3.96875f
#define Z0  0.0f
__constant__ float c_shx[NK] = {M1,M1,M1,M1,M1,M1,M1,M1,M1,
                                Z0,Z0,Z0,Z0,Z0,Z0,Z0,Z0,Z0,
                                P1,P1,P1,P1,P1,P1,P1,P1,P1};
__constant__ float c_shy[NK] = {M1,M1,M1,Z0,Z0,Z0,P1,P1,P1,
                                M1,M1,M1,Z0,Z0,Z0,P1,P1,P1,
                                M1,M1,M1,Z0,Z0,Z0,P1,P1,P1};
__constant__ float c_shz[NK] = {M1,Z0,P1,M1,Z0,P1,M1,Z0,P1,
                                M1,Z0,P1,M1,Z0,P1,M1,Z0,P1,
                                M1,Z0,P1,M1,Z0,P1,M1,Z0,P1};

// ---------------------------------------------------------------------------
// Prep 1 (27 blocks): M[k][j][o] = sum_c conv_w[o,c,k]*Wd[c,j]
// ---------------------------------------------------------------------------
__global__ __launch_bounds__(1024) void prep1_kernel(
    const float* __restrict__ w_d1, const float* __restrict__ w_d2,
    const float* __restrict__ conv_w)
{
    __shared__ float Wds[1024];    // Wd[c][j]
    __shared__ float convs[1024];  // conv[c][o] for this k
    const int tid = threadIdx.x, k = blockIdx.x;
    const int o = tid & 31, j = tid >> 5;

    {   // Wd = w_d2 @ w_d1
        float s = 0.f;
        #pragma unroll
        for (int m = 0; m < 32; m++)
            s += w_d2[(tid >> 5) * 32 + m] * w_d1[m * 32 + (tid & 31)];
        Wds[tid] = s;
    }
    convs[tid] = conv_w[(o * 32 + (tid >> 5)) * 27 + k];
    __syncthreads();

    float acc = 0.f;
    #pragma unroll
    for (int c = 0; c < 32; c++)
        acc += convs[c * 32 + o] * Wds[c * 32 + j];
    g_G[k * 1024 + j * 32 + o] = acc;
}

// ---------------------------------------------------------------------------
// Prep 2 (1 block): center-tap correction + fused bias
// + pack fp16 B-fragments (paired b0/b1 per lane) into g_Gb.
// ---------------------------------------------------------------------------
__global__ __launch_bounds__(1024) void prep2_kernel(
    const float* __restrict__ w_d2, const float* __restrict__ b_d1,
    const float* __restrict__ b_d2,
    const float* __restrict__ w_c1, const float* __restrict__ b_c1,
    const float* __restrict__ w_c2, const float* __restrict__ b_c2,
    const float* __restrict__ conv_w, const float* __restrict__ conv_b)
{
    __shared__ float Wcs[1024], part[1024], bds[32], bcs[32];
    const int tid = threadIdx.x;
    const int o = tid & 31, j = tid >> 5;

    {   // Wc = w_c2 @ w_c1
        float s = 0.f;
        #pragma unroll
        for (int m = 0; m < 32; m++)
            s += w_c2[(tid >> 5) * 32 + m] * w_c1[m * 32 + (tid & 31)];
        Wcs[tid] = s;
    }
    if (tid < 32) {
        float sd = 0.f, sc = 0.f;
        #pragma unroll
        for (int m = 0; m < 32; m++) {
            sd += w_d2[tid * 32 + m] * b_d1[m];
            sc += w_c2[tid * 32 + m] * b_c1[m];
        }
        bds[tid] = sd + b_d2[tid];
        bcs[tid] = sc + b_c2[tid];
    }
    float rs = 0.f;
    #pragma unroll
    for (int k = 0; k < NK; k++)
        rs += conv_w[(o * 32 + j) * 27 + k];
    __syncthreads();

    part[j * 32 + o] = bds[j] * rs;

    float S = 0.f;
    #pragma unroll
    for (int k = 0; k < NK; k++) S += g_G[k * 1024 + tid];
    g_G[13 * 1024 + tid] += Wcs[o * 32 + j] - S;
    __syncthreads();   // correction visible before packing

    // pack B-fragments, paired: word i = k*512 + ks*256 + nt*64 + 2l + r
    // half2{ G[k][c][o], G[k][c+1][o] }, c = 16ks+8r+2(l&3), o = 8nt+(l>>2)
    for (int i = tid; i < GB_WORDS; i += 1024) {
        const int k = i >> 9;
        const int e = i & 511;
        const int ks = e >> 8;
        const int nt = (e >> 6) & 3;
        const int l  = (e >> 1) & 31;
        const int r  = e & 1;
        const int c  = 16 * ks + 8 * r + 2 * (l & 3);
        const int oo = 8 * nt + (l >> 2);
        __half2 h = __floats2half2_rn(g_G[k * 1024 + c * 32 + oo],
                                      g_G[k * 1024 + (c + 1) * 32 + oo]);
        g_Gb[i] = *reinterpret_cast<unsigned*>(&h);
    }

    if (tid < 32) {
        float a = 0.f;
        #pragma unroll
        for (int c = 0; c < 32; c++) a += part[c * 32 + tid];
        g_bias[tid] = a + conv_b[tid] + bcs[tid];
    }
}

// ---------------------------------------------------------------------------
// Transpose + convert: [C][D][H][W] fp32 -> channel-last fp16 [D][H][W][C].
// ---------------------------------------------------------------------------
__global__ __launch_bounds__(256) void transpose_kernel(const float* __restrict__ vin)
{
    __shared__ float tile[32][33];
    const int x0 = blockIdx.x * 32;
    const int y = blockIdx.y, z = blockIdx.z;
    const int tid = threadIdx.x;
    const int tx = tid & 31, ty = tid >> 5;

    #pragma unroll
    for (int i = 0; i < 4; i++) {
        const int c = ty + 8 * i;
        tile[c][tx] = vin[(((size_t)c * DIM + z) * DIM + y) * DIM + x0 + tx];
    }
    __syncthreads();

    const int g  = tid & 7;          // channel quad (4 halves = 8B)
    const int xx = tid >> 3;         // x within tile (0..31)
    const size_t obase = ((size_t)z * DIM + y) * DIM + x0;

    __half2 h01 = __floats2half2_rn(tile[4 * g + 0][xx], tile[4 * g + 1][xx]);
    __half2 h23 = __floats2half2_rn(tile[4 * g + 2][xx], tile[4 * g + 3][xx]);
    uint2 u;
    u.x = *reinterpret_cast<unsigned*>(&h01);
    u.y = *reinterpret_cast<unsigned*>(&h23);
    reinterpret_cast<uint2*>(g_volh + (obase + xx) * C_CH)[g] = u;
}

// ---------------------------------------------------------------------------
// Vertex binning: zero+count -> scan -> scatter (cells of 8^3 voxels).
// ---------------------------------------------------------------------------
__device__ __forceinline__ int cell_of(float x, float y, float z)
{
    float px = fminf(fmaxf((x + 1.f) * 63.5f, 0.f), 127.f);
    float py = fminf(fmaxf((y + 1.f) * 63.5f, 0.f), 127.f);
    float pz = fminf(fmaxf((z + 1.f) * 63.5f, 0.f), 127.f);
    const int cx = ((int)px) >> 3, cy = ((int)py) >> 3, cz = ((int)pz) >> 3;
    return (cz << 8) | (cy << 4) | cx;
}

__global__ void zero_kernel()
{
    const int t = blockIdx.x * blockDim.x + threadIdx.x;
    if (t < NCELL) { g_hist[t] = 0; g_base[t] = 0; }
}

__global__ void count_kernel(const float* __restrict__ verts, int Ntot)
{
    const int n = blockIdx.x * blockDim.x + threadIdx.x;
    if (n >= Ntot) return;
    atomicAdd(&g_hist[cell_of(verts[3 * n], verts[3 * n + 1], verts[3 * n + 2])], 1);
}

__global__ __launch_bounds__(1024) void scan_kernel()
{
    __shared__ int sh[1024];
    const int t = threadIdx.x;
    int h0 = g_hist[4 * t], h1 = g_hist[4 * t + 1],
        h2 = g_hist[4 * t + 2], h3 = g_hist[4 * t + 3];
    const int mysum = h0 + h1 + h2 + h3;
    sh[t] = mysum;
    __syncthreads();
    for (int off = 1; off < 1024; off <<= 1) {
        int v = (t >= off) ? sh[t - off] : 0;
        __syncthreads();
        sh[t] += v;
        __syncthreads();
    }
    int e = sh[t] - mysum;
    g_base[4 * t]     = e;
    g_base[4 * t + 1] = e + h0;
    g_base[4 * t + 2] = e + h0 + h1;
    g_base[4 * t + 3] = e + h0 + h1 + h2;
}

__global__ void scatter_kernel(const float* __restrict__ verts, int Ntot)
{
    const int n = blockIdx.x * blockDim.x + threadIdx.x;
    if (n >= Ntot) return;
    const int c = cell_of(verts[3 * n], verts[3 * n + 1], verts[3 * n + 2]);
    const int pos = atomicAdd(&g_base[c], 1);
    g_perm[pos] = n;
}

// ---------------------------------------------------------------------------
__device__ __forceinline__ __half2 u2h(unsigned u)
{
    return *reinterpret_cast<__half2*>(&u);
}

__device__ __forceinline__ void mma_16816(
    float* d, unsigned a0, unsigned a1, unsigned a2, unsigned a3,
    unsigned b0, unsigned b1)
{
    asm volatile(
        "mma.sync.aligned.m16n8k16.row.col.f32.f16.f16.f32 "
        "{%0,%1,%2,%3}, {%4,%5,%6,%7}, {%8,%9}, {%0,%1,%2,%3};"
        : "+f"(d[0]), "+f"(d[1]), "+f"(d[2]), "+f"(d[3])
        : "r"(a0), "r"(a1), "r"(a2), "r"(a3), "r"(b0), "r"(b1));
}

// ---------------------------------------------------------------------------
// Fused sample + tensor-core GEMM, 2-way split-K over neighbours.
// fp16 trilinear (HFMA2), ldmatrix A-frags, pre-packed B-frags, HMMA fp32.
// ---------------------------------------------------------------------------
__global__ __launch_bounds__(256, 3) void main_kernel(
    const float* __restrict__ verts, float* __restrict__ out, int Ntot)
{
    __shared__ __align__(16) unsigned char feats[8 * WFEAT];
    __shared__ float partial[4 * 16 * 32];      // [tib][q][lane]
    const int warp = threadIdx.x >> 5, lane = threadIdx.x & 31;
    const int tib = warp >> 1, khalf = warp & 1;
    const int nTiles = (Ntot + TPW - 1) / TPW;
    const int tile = blockIdx.x * 4 + tib;
    const bool live = (tile < nTiles);

    const int n0 = tile * TPW;
    const int v = lane & 15;
    const int idx = n0 + v;
    const bool valid = live && (idx < Ntot);
    const int n = valid ? g_perm[idx] : 0;

    float px0 = 0.f, py0 = 0.f, pz0 = 0.f;   // hoisted pixel-space coords
    if (valid) {
        px0 = fmaf(verts[3 * n + 0], 63.5f, 63.5f);
        py0 = fmaf(verts[3 * n + 1], 63.5f, 63.5f);
        pz0 = fmaf(verts[3 * n + 2], 63.5f, 63.5f);
    }

    const int c4 = lane & 7;              // channel quad
    const int v4 = lane >> 3;             // vertex within group of 4

    unsigned char* fb = feats + warp * WFEAT;
    const unsigned fb_s = (unsigned)__cvta_generic_to_shared(fb);

    const int lg = lane >> 3;
    const unsigned arow = (lane & 7) + ((lg & 1) << 3);
    const unsigned lm0 = fb_s + arow * ROWB + ((lg >> 1) << 4);  // ks=0
    const unsigned lm1 = lm0 + 32;                                // ks=1

    float d[4][4];
    #pragma unroll
    for (int i = 0; i < 4; i++)
        #pragma unroll
        for (int q = 0; q < 4; q++) d[i][q] = 0.f;

    const int k0 = khalf ? 14 : 0;
    const int k1 = khalf ? NK : 14;

    if (live) {
        #pragma unroll 1
        for (int k = k0; k < k1; k++) {
            float px = fminf(fmaxf(px0 + c_shx[k], 0.f), 127.f);
            float py = fminf(fmaxf(py0 + c_shy[k], 0.f), 127.f);
            float pz = fminf(fmaxf(pz0 + c_shz[k], 0.f), 127.f);
            const float fx = floorf(px), fy = floorf(py), fz = floorf(pz);
            const int ix = (int)fx, iy = (int)fy, iz = (int)fz;
            const float wx = px - fx, wy = py - fy, wz = pz - fz;
            const int base = iz * (DIM * DIM * C_CH) + iy * (DIM * C_CH) + ix * C_CH;
            const int sx = (ix < DIM - 1) ? (C_CH >> 2) : 0;         // uint2 units
            const int sy = (iy < DIM - 1) ? (DIM * C_CH >> 2) : 0;
            const int sz = (iz < DIM - 1) ? (DIM * DIM * C_CH >> 2) : 0;

            #pragma unroll
            for (int g4 = 0; g4 < 4; g4++) {
                const int src = g4 * 4 + v4;
                const int b   = __shfl_sync(0xffffffffu, base, src);
                const int sx4 = __shfl_sync(0xffffffffu, sx, src);
                const int sy4 = __shfl_sync(0xffffffffu, sy, src);
                const int sz4 = __shfl_sync(0xffffffffu, sz, src);
                const float wxv = __shfl_sync(0xffffffffu, wx, src);
                const float wyv = __shfl_sync(0xffffffffu, wy, src);
                const float wzv = __shfl_sync(0xffffffffu, wz, src);

                const uint2* p = reinterpret_cast<const uint2*>(g_volh + b) + c4;
                const uint2 u000 = __ldg(p);
                const uint2 u001 = __ldg(p + sx4);
                const uint2 u010 = __ldg(p + sy4);
                const uint2 u011 = __ldg(p + sy4 + sx4);
                const uint2 u100 = __ldg(p + sz4);
                const uint2 u101 = __ldg(p + sz4 + sx4);
                const uint2 u110 = __ldg(p + sz4 + sy4);
                const uint2 u111 = __ldg(p + sz4 + sy4 + sx4);

                // corner weights in fp32, splat-packed to half2 (1 cvt each)
                const float ax0 = 1.f - wxv, ay0 = 1.f - wyv, az0 = 1.f - wzv;
                const float c00 = az0 * ay0, c01 = az0 * wyv;
                const float c10 = wzv * ay0, c11 = wzv * wyv;
                const __half2 h000 = __floats2half2_rn(c00 * ax0, c00 * ax0);
                const __half2 h001 = __floats2half2_rn(c00 * wxv, c00 * wxv);
                const __half2 h010 = __floats2half2_rn(c01 * ax0, c01 * ax0);
                const __half2 h011 = __floats2half2_rn(c01 * wxv, c01 * wxv);
                const __half2 h100 = __floats2half2_rn(c10 * ax0, c10 * ax0);
                const __half2 h101 = __floats2half2_rn(c10 * wxv, c10 * wxv);
                const __half2 h110 = __floats2half2_rn(c11 * ax0, c11 * ax0);
                const __half2 h111 = __floats2half2_rn(c11 * wxv, c11 * wxv);

                // trilinear entirely in fp16: two z-partials + final add
                __half2 paX = __hmul2(h000, u2h(u000.x));
                paX = __hfma2(h001, u2h(u001.x), paX);
                paX = __hfma2(h010, u2h(u010.x), paX);
                paX = __hfma2(h011, u2h(u011.x), paX);
                __half2 pbX = __hmul2(h100, u2h(u100.x));
                pbX = __hfma2(h101, u2h(u101.x), pbX);
                pbX = __hfma2(h110, u2h(u110.x), pbX);
                pbX = __hfma2(h111, u2h(u111.x), pbX);
                __half2 rX = __hadd2(paX, pbX);

                __half2 paY = __hmul2(h000, u2h(u000.y));
                paY = __hfma2(h001, u2h(u001.y), paY);
                paY = __hfma2(h010, u2h(u010.y), paY);
                paY = __hfma2(h011, u2h(u011.y), paY);
                __half2 pbY = __hmul2(h100, u2h(u100.y));
                pbY = __hfma2(h101, u2h(u101.y), pbY);
                pbY = __hfma2(h110, u2h(u110.y), pbY);
                pbY = __hfma2(h111, u2h(u111.y), pbY);
                __half2 rY = __hadd2(paY, pbY);

                uint2 u;
                u.x = *reinterpret_cast<unsigned*>(&rX);
                u.y = *reinterpret_cast<unsigned*>(&rY);
                *reinterpret_cast<uint2*>(fb + src * ROWB + c4 * 8) = u;
            }
            __syncwarp();

            unsigned a0, a1, a2, a3, a4, a5, a6, a7;
            asm volatile("ldmatrix.sync.aligned.m8n8.x4.shared.b16 {%0,%1,%2,%3}, [%4];"
                         : "=r"(a0), "=r"(a1), "=r"(a2), "=r"(a3) : "r"(lm0) : "memory");
            asm volatile("ldmatrix.sync.aligned.m8n8.x4.shared.b16 {%0,%1,%2,%3}, [%4];"
                         : "=r"(a4), "=r"(a5), "=r"(a6), "=r"(a7) : "r"(lm1) : "memory");

            // paired B fragments: LDG.64, coalesced
            const uint2* gb2 = reinterpret_cast<const uint2*>(g_Gb) +
                               k * 256 + lane;
            #pragma unroll
            for (int nt = 0; nt < 4; nt++) {
                const uint2 b01 = __ldg(gb2 + nt * 32);
                mma_16816(d[nt], a0, a1, a2, a3, b01.x, b01.y);
            }
            #pragma unroll
            for (int nt = 0; nt < 4; nt++) {
                const uint2 b01 = __ldg(gb2 + 128 + nt * 32);
                mma_16816(d[nt], a4, a5, a6, a7, b01.x, b01.y);
            }
            __syncwarp();
        }
    }

    // split-K combine: khalf=1 publishes, khalf=0 reduces + stores
    if (live && khalf) {
        #pragma unroll
        for (int nt = 0; nt < 4; nt++)
            #pragma unroll
            for (int q = 0; q < 4; q++)
                partial[tib * 512 + (nt * 4 + q) * 32 + lane] = d[nt][q];
    }
    __syncthreads();
    if (live && !khalf) {
        #pragma unroll
        for (int nt = 0; nt < 4; nt++)
            #pragma unroll
            for (int q = 0; q < 4; q++)
                d[nt][q] += partial[tib * 512 + (nt * 4 + q) * 32 + lane];

        const int r0 = lane >> 2;
        const int cb = 2 * (lane & 3);
        const int i0 = n0 + r0, i1 = i0 + 8;
        const int p0 = (i0 < Ntot) ? g_perm[i0] : -1;
        const int p1 = (i1 < Ntot) ? g_perm[i1] : -1;

        #pragma unroll
        for (int nt = 0; nt < 4; nt++) {
            const int col = 8 * nt + cb;
            const float blo = __ldg(&g_bias[col]);
            const float bhi = __ldg(&g_bias[col + 1]);
            if (p0 >= 0) {
                float2 w0 = make_float2(d[nt][0] + blo, d[nt][1] + bhi);
                *reinterpret_cast<float2*>(out + p0 * C_CH + col) = w0;
            }
            if (p1 >= 0) {
                float2 w1 = make_float2(d[nt][2] + blo, d[nt][3] + bhi);
                *reinterpret_cast<float2*>(out + p1 * C_CH + col) = w1;
            }
        }
    }
}

// ---------------------------------------------------------------------------
// Launch with fork-join stream topology inside graph capture:
//   main stream : transpose (DRAM-bound long pole)
//   s_prep      : prep1 -> prep2
//   s_bin       : zero -> count -> scan -> scatter
// All join before main_kernel. Hides ~24us of small-kernel work under the
// transpose. Streams/events are lazily-created host objects (no device alloc).
// ---------------------------------------------------------------------------
extern "C" void kernel_launch(void* const* d_in, const int* in_sizes, int n_in,
                              void* d_out, int out_size)
{
    const float* voxel = (const float*)d_in[0];
    const float* verts = (const float*)d_in[1];
    const int Ntot = in_sizes[1] / 3;

    static cudaStream_t s_prep = nullptr, s_bin = nullptr;
    static cudaEvent_t e_fork, e_prep, e_bin;
    if (!s_prep) {
        cudaStreamCreateWithFlags(&s_prep, cudaStreamNonBlocking);
        cudaStreamCreateWithFlags(&s_bin, cudaStreamNonBlocking);
        cudaEventCreateWithFlags(&e_fork, cudaEventDisableTiming);
        cudaEventCreateWithFlags(&e_prep, cudaEventDisableTiming);
        cudaEventCreateWithFlags(&e_bin, cudaEventDisableTiming);
    }

    // fork
    cudaEventRecord(e_fork, 0);
    cudaStreamWaitEvent(s_prep, e_fork, 0);
    cudaStreamWaitEvent(s_bin, e_fork, 0);

    // branch A (main stream): transpose — the long pole
    {
        dim3 tb(256);
        dim3 tg(DIM / 32, DIM, DIM);
        transpose_kernel<<<tg, tb>>>(voxel);
    }

    // branch B (s_prep): weight folding
    prep1_kernel<<<27, 1024, 0, s_prep>>>(
        (const float*)d_in[2], (const float*)d_in[4], (const float*)d_in[10]);
    prep2_kernel<<<1, 1024, 0, s_prep>>>(
        (const float*)d_in[4], (const float*)d_in[3], (const float*)d_in[5],
        (const float*)d_in[6], (const float*)d_in[7], (const float*)d_in[8],
        (const float*)d_in[9], (const float*)d_in[10], (const float*)d_in[11]);
    cudaEventRecord(e_prep, s_prep);

    // branch C (s_bin): vertex spatial binning
    zero_kernel<<<(NCELL + 255) / 256, 256, 0, s_bin>>>();
    count_kernel<<<(Ntot + 255) / 256, 256, 0, s_bin>>>(verts, Ntot);
    scan_kernel<<<1, 1024, 0, s_bin>>>();
    scatter_kernel<<<(Ntot + 255) / 256, 256, 0, s_bin>>>(verts, Ntot);
    cudaEventRecord(e_bin, s_bin);

    // join
    cudaStreamWaitEvent(0, e_prep, 0);
    cudaStreamWaitEvent(0, e_bin, 0);

    const int nTiles = (Ntot + TPW - 1) / TPW;
    const int blocks = (nTiles + 3) / 4;
    main_kernel<<<blocks, 256>>>(verts, (float*)d_out, Ntot);
}

// round 13
// speedup vs baseline: 1.7947x; 1.0196x over previous
#include <cuda_runtime.h>
#include <cuda_fp16.h>
#include <cstdint>

#define C_CH 32
#define DIM  128
#define NK   27
#define VOL_ELEMS (C_CH * DIM * DIM * DIM)
#define NCELL 4096            // 16x16x16 cells of 8^3 voxels
#define PERM_MAX (1 << 18)
#define TPW 16                // vertices per tile

#define ROWB 80               // bytes per feat row (16 fp16 padded to 80B)
#define WFEAT (16 * ROWB)     // 1280B per warp feat tile
#define GB_WORDS (NK * 512)   // pre-packed B-fragment words (13824)

#define ZSPLIT 72             // slab boundary: cz<8 tiles sample z <= 68 < 72

// Scratch (device globals: allocation-free per harness rules)
__device__ __half g_volh[VOL_ELEMS];          // channel-last fp16 volume
__device__ float g_G[NK * C_CH * C_CH];       // [k][c][o] folded weights (fp32)
__device__ unsigned g_Gb[GB_WORDS];           // fp16 B-frags, paired lane layout
__device__ float g_bias[C_CH];
__device__ int   g_hist[NCELL];
__device__ int   g_base[NCELL];
__device__ int   g_perm[PERM_MAX];

// neighbour shifts pre-scaled to pixel space: {-1,0,1} * 0.0625 * 63.5
#define M1 -3.96875f
#define P1  3.96875f
#define Z0  0.0f
__constant__ float c_shx[NK] = {M1,M1,M1,M1,M1,M1,M1,M1,M1,
                                Z0,Z0,Z0,Z0,Z0,Z0,Z0,Z0,Z0,
                                P1,P1,P1,P1,P1,P1,P1,P1,P1};
__constant__ float c_shy[NK] = {M1,M1,M1,Z0,Z0,Z0,P1,P1,P1,
                                M1,M1,M1,Z0,Z0,Z0,P1,P1,P1,
                                M1,M1,M1,Z0,Z0,Z0,P1,P1,P1};
__constant__ float c_shz[NK] = {M1,Z0,P1,M1,Z0,P1,M1,Z0,P1,
                                M1,Z0,P1,M1,Z0,P1,M1,Z0,P1,
                                M1,Z0,P1,M1,Z0,P1,M1,Z0,P1};

// ---------------------------------------------------------------------------
// Prep 1 (27 blocks): M[k][j][o] = sum_c conv_w[o,c,k]*Wd[c,j]
// ---------------------------------------------------------------------------
__global__ __launch_bounds__(1024) void prep1_kernel(
    const float* __restrict__ w_d1, const float* __restrict__ w_d2,
    const float* __restrict__ conv_w)
{
    __shared__ float Wds[1024];    // Wd[c][j]
    __shared__ float convs[1024];  // conv[c][o] for this k
    const int tid = threadIdx.x, k = blockIdx.x;
    const int o = tid & 31, j = tid >> 5;

    {   // Wd = w_d2 @ w_d1
        float s = 0.f;
        #pragma unroll
        for (int m = 0; m < 32; m++)
            s += w_d2[(tid >> 5) * 32 + m] * w_d1[m * 32 + (tid & 31)];
        Wds[tid] = s;
    }
    convs[tid] = conv_w[(o * 32 + (tid >> 5)) * 27 + k];
    __syncthreads();

    float acc = 0.f;
    #pragma unroll
    for (int c = 0; c < 32; c++)
        acc += convs[c * 32 + o] * Wds[c * 32 + j];
    g_G[k * 1024 + j * 32 + o] = acc;
}

// ---------------------------------------------------------------------------
// Prep 2 (1 block): center-tap correction + fused bias
// + pack fp16 B-fragments (paired b0/b1 per lane) into g_Gb.
// ---------------------------------------------------------------------------
__global__ __launch_bounds__(1024) void prep2_kernel(
    const float* __restrict__ w_d2, const float* __restrict__ b_d1,
    const float* __restrict__ b_d2,
    const float* __restrict__ w_c1, const float* __restrict__ b_c1,
    const float* __restrict__ w_c2, const float* __restrict__ b_c2,
    const float* __restrict__ conv_w, const float* __restrict__ conv_b)
{
    __shared__ float Wcs[1024], part[1024], bds[32], bcs[32];
    const int tid = threadIdx.x;
    const int o = tid & 31, j = tid >> 5;

    {   // Wc = w_c2 @ w_c1
        float s = 0.f;
        #pragma unroll
        for (int m = 0; m < 32; m++)
            s += w_c2[(tid >> 5) * 32 + m] * w_c1[m * 32 + (tid & 31)];
        Wcs[tid] = s;
    }
    if (tid < 32) {
        float sd = 0.f, sc = 0.f;
        #pragma unroll
        for (int m = 0; m < 32; m++) {
            sd += w_d2[tid * 32 + m] * b_d1[m];
            sc += w_c2[tid * 32 + m] * b_c1[m];
        }
        bds[tid] = sd + b_d2[tid];
        bcs[tid] = sc + b_c2[tid];
    }
    float rs = 0.f;
    #pragma unroll
    for (int k = 0; k < NK; k++)
        rs += conv_w[(o * 32 + j) * 27 + k];
    __syncthreads();

    part[j * 32 + o] = bds[j] * rs;

    float S = 0.f;
    #pragma unroll
    for (int k = 0; k < NK; k++) S += g_G[k * 1024 + tid];
    g_G[13 * 1024 + tid] += Wcs[o * 32 + j] - S;
    __syncthreads();   // correction visible before packing

    // pack B-fragments, paired: word i = k*512 + ks*256 + nt*64 + 2l + r
    // half2{ G[k][c][o], G[k][c+1][o] }, c = 16ks+8r+2(l&3), o = 8nt+(l>>2)
    for (int i = tid; i < GB_WORDS; i += 1024) {
        const int k = i >> 9;
        const int e = i & 511;
        const int ks = e >> 8;
        const int nt = (e >> 6) & 3;
        const int l  = (e >> 1) & 31;
        const int r  = e & 1;
        const int c  = 16 * ks + 8 * r + 2 * (l & 3);
        const int oo = 8 * nt + (l >> 2);
        __half2 h = __floats2half2_rn(g_G[k * 1024 + c * 32 + oo],
                                      g_G[k * 1024 + (c + 1) * 32 + oo]);
        g_Gb[i] = *reinterpret_cast<unsigned*>(&h);
    }

    if (tid < 32) {
        float a = 0.f;
        #pragma unroll
        for (int c = 0; c < 32; c++) a += part[c * 32 + tid];
        g_bias[tid] = a + conv_b[tid] + bcs[tid];
    }
}

// ---------------------------------------------------------------------------
// Transpose + convert a z-slab: [C][D][H][W] fp32 -> channel-last fp16.
// ---------------------------------------------------------------------------
__global__ __launch_bounds__(256) void transpose_kernel(
    const float* __restrict__ vin, int z0)
{
    __shared__ float tile[32][33];
    const int x0 = blockIdx.x * 32;
    const int y = blockIdx.y, z = blockIdx.z + z0;
    const int tid = threadIdx.x;
    const int tx = tid & 31, ty = tid >> 5;

    #pragma unroll
    for (int i = 0; i < 4; i++) {
        const int c = ty + 8 * i;
        tile[c][tx] = vin[(((size_t)c * DIM + z) * DIM + y) * DIM + x0 + tx];
    }
    __syncthreads();

    const int g  = tid & 7;          // channel quad (4 halves = 8B)
    const int xx = tid >> 3;         // x within tile (0..31)
    const size_t obase = ((size_t)z * DIM + y) * DIM + x0;

    __half2 h01 = __floats2half2_rn(tile[4 * g + 0][xx], tile[4 * g + 1][xx]);
    __half2 h23 = __floats2half2_rn(tile[4 * g + 2][xx], tile[4 * g + 3][xx]);
    uint2 u;
    u.x = *reinterpret_cast<unsigned*>(&h01);
    u.y = *reinterpret_cast<unsigned*>(&h23);
    reinterpret_cast<uint2*>(g_volh + (obase + xx) * C_CH)[g] = u;
}

// ---------------------------------------------------------------------------
// Vertex binning: zero+count -> scan -> scatter (cells of 8^3 voxels).
// ---------------------------------------------------------------------------
__device__ __forceinline__ int cell_of(float x, float y, float z)
{
    float px = fminf(fmaxf((x + 1.f) * 63.5f, 0.f), 127.f);
    float py = fminf(fmaxf((y + 1.f) * 63.5f, 0.f), 127.f);
    float pz = fminf(fmaxf((z + 1.f) * 63.5f, 0.f), 127.f);
    const int cx = ((int)px) >> 3, cy = ((int)py) >> 3, cz = ((int)pz) >> 3;
    return (cz << 8) | (cy << 4) | cx;
}

__global__ void zero_kernel()
{
    const int t = blockIdx.x * blockDim.x + threadIdx.x;
    if (t < NCELL) { g_hist[t] = 0; g_base[t] = 0; }
}

__global__ void count_kernel(const float* __restrict__ verts, int Ntot)
{
    const int n = blockIdx.x * blockDim.x + threadIdx.x;
    if (n >= Ntot) return;
    atomicAdd(&g_hist[cell_of(verts[3 * n], verts[3 * n + 1], verts[3 * n + 2])], 1);
}

__global__ __launch_bounds__(1024) void scan_kernel()
{
    __shared__ int sh[1024];
    const int t = threadIdx.x;
    int h0 = g_hist[4 * t], h1 = g_hist[4 * t + 1],
        h2 = g_hist[4 * t + 2], h3 = g_hist[4 * t + 3];
    const int mysum = h0 + h1 + h2 + h3;
    sh[t] = mysum;
    __syncthreads();
    for (int off = 1; off < 1024; off <<= 1) {
        int v = (t >= off) ? sh[t - off] : 0;
        __syncthreads();
        sh[t] += v;
        __syncthreads();
    }
    int e = sh[t] - mysum;
    g_base[4 * t]     = e;
    g_base[4 * t + 1] = e + h0;
    g_base[4 * t + 2] = e + h0 + h1;
    g_base[4 * t + 3] = e + h0 + h1 + h2;
}

__global__ void scatter_kernel(const float* __restrict__ verts, int Ntot)
{
    const int n = blockIdx.x * blockDim.x + threadIdx.x;
    if (n >= Ntot) return;
    const int c = cell_of(verts[3 * n], verts[3 * n + 1], verts[3 * n + 2]);
    const int pos = atomicAdd(&g_base[c], 1);
    g_perm[pos] = n;
}

// ---------------------------------------------------------------------------
__device__ __forceinline__ __half2 u2h(unsigned u)
{
    return *reinterpret_cast<__half2*>(&u);
}

__device__ __forceinline__ void mma_16816(
    float* d, unsigned a0, unsigned a1, unsigned a2, unsigned a3,
    unsigned b0, unsigned b1)
{
    asm volatile(
        "mma.sync.aligned.m16n8k16.row.col.f32.f16.f16.f32 "
        "{%0,%1,%2,%3}, {%4,%5,%6,%7}, {%8,%9}, {%0,%1,%2,%3};"
        : "+f"(d[0]), "+f"(d[1]), "+f"(d[2]), "+f"(d[3])
        : "r"(a0), "r"(a1), "r"(a2), "r"(a3), "r"(b0), "r"(b1));
}

// ---------------------------------------------------------------------------
// Fused sample + tensor-core GEMM, 2-way split-K over neighbours, phased by
// z-slab: phase 0 runs tiles fully inside cz<8 (low slab, overlaps T2);
// phase 1 runs the rest after the whole volume is ready. Classification is a
// deterministic warp ballot over the tile's vertex cells (same in both phases).
// ---------------------------------------------------------------------------
__global__ __launch_bounds__(256, 3) void main_kernel(
    const float* __restrict__ verts, float* __restrict__ out, int Ntot,
    int phase)
{
    __shared__ __align__(16) unsigned char feats[8 * WFEAT];
    __shared__ float partial[4 * 16 * 32];      // [tib][q][lane]
    const int warp = threadIdx.x >> 5, lane = threadIdx.x & 31;
    const int tib = warp >> 1, khalf = warp & 1;
    const int nTiles = (Ntot + TPW - 1) / TPW;
    const int tile = blockIdx.x * 4 + tib;
    bool live = (tile < nTiles);

    const int n0 = tile * TPW;
    const int v = lane & 15;
    const int idx = n0 + v;
    const bool valid = live && (idx < Ntot);
    const int n = valid ? g_perm[idx] : 0;

    float px0 = 0.f, py0 = 0.f, pz0 = 0.f;   // hoisted pixel-space coords
    if (valid) {
        px0 = fmaf(verts[3 * n + 0], 63.5f, 63.5f);
        py0 = fmaf(verts[3 * n + 1], 63.5f, 63.5f);
        pz0 = fmaf(verts[3 * n + 2], 63.5f, 63.5f);
    }

    // slab classification (invalid lanes: pz0=0 -> low). Same in both phases.
    {
        const int czi = ((int)fminf(fmaxf(pz0, 0.f), 127.f)) >> 3;
        const bool allLow = __all_sync(0xffffffffu, czi < 8);
        live = live && (phase == 0 ? allLow : !allLow);
    }

    const int c4 = lane & 7;              // channel quad
    const int v4 = lane >> 3;             // vertex within group of 4

    unsigned char* fb = feats + warp * WFEAT;
    const unsigned fb_s = (unsigned)__cvta_generic_to_shared(fb);

    const int lg = lane >> 3;
    const unsigned arow = (lane & 7) + ((lg & 1) << 3);
    const unsigned lm0 = fb_s + arow * ROWB + ((lg >> 1) << 4);  // ks=0
    const unsigned lm1 = lm0 + 32;                                // ks=1

    float d[4][4];
    #pragma unroll
    for (int i = 0; i < 4; i++)
        #pragma unroll
        for (int q = 0; q < 4; q++) d[i][q] = 0.f;

    const int k0 = khalf ? 14 : 0;
    const int k1 = khalf ? NK : 14;

    if (live) {
        #pragma unroll 1
        for (int k = k0; k < k1; k++) {
            float px = fminf(fmaxf(px0 + c_shx[k], 0.f), 127.f);
            float py = fminf(fmaxf(py0 + c_shy[k], 0.f), 127.f);
            float pz = fminf(fmaxf(pz0 + c_shz[k], 0.f), 127.f);
            const float fx = floorf(px), fy = floorf(py), fz = floorf(pz);
            const int ix = (int)fx, iy = (int)fy, iz = (int)fz;
            const float wx = px - fx, wy = py - fy, wz = pz - fz;
            const int base = iz * (DIM * DIM * C_CH) + iy * (DIM * C_CH) + ix * C_CH;
            const int sx = (ix < DIM - 1) ? (C_CH >> 2) : 0;         // uint2 units
            const int sy = (iy < DIM - 1) ? (DIM * C_CH >> 2) : 0;
            const int sz = (iz < DIM - 1) ? (DIM * DIM * C_CH >> 2) : 0;

            #pragma unroll
            for (int g4 = 0; g4 < 4; g4++) {
                const int src = g4 * 4 + v4;
                const int b   = __shfl_sync(0xffffffffu, base, src);
                const int sx4 = __shfl_sync(0xffffffffu, sx, src);
                const int sy4 = __shfl_sync(0xffffffffu, sy, src);
                const int sz4 = __shfl_sync(0xffffffffu, sz, src);
                const float wxv = __shfl_sync(0xffffffffu, wx, src);
                const float wyv = __shfl_sync(0xffffffffu, wy, src);
                const float wzv = __shfl_sync(0xffffffffu, wz, src);

                const uint2* p = reinterpret_cast<const uint2*>(g_volh + b) + c4;
                const uint2 u000 = __ldg(p);
                const uint2 u001 = __ldg(p + sx4);
                const uint2 u010 = __ldg(p + sy4);
                const uint2 u011 = __ldg(p + sy4 + sx4);
                const uint2 u100 = __ldg(p + sz4);
                const uint2 u101 = __ldg(p + sz4 + sx4);
                const uint2 u110 = __ldg(p + sz4 + sy4);
                const uint2 u111 = __ldg(p + sz4 + sy4 + sx4);

                // corner weights in fp32, splat-packed to half2 (1 cvt each)
                const float ax0 = 1.f - wxv, ay0 = 1.f - wyv, az0 = 1.f - wzv;
                const float c00 = az0 * ay0, c01 = az0 * wyv;
                const float c10 = wzv * ay0, c11 = wzv * wyv;
                const __half2 h000 = __floats2half2_rn(c00 * ax0, c00 * ax0);
                const __half2 h001 = __floats2half2_rn(c00 * wxv, c00 * wxv);
                const __half2 h010 = __floats2half2_rn(c01 * ax0, c01 * ax0);
                const __half2 h011 = __floats2half2_rn(c01 * wxv, c01 * wxv);
                const __half2 h100 = __floats2half2_rn(c10 * ax0, c10 * ax0);
                const __half2 h101 = __floats2half2_rn(c10 * wxv, c10 * wxv);
                const __half2 h110 = __floats2half2_rn(c11 * ax0, c11 * ax0);
                const __half2 h111 = __floats2half2_rn(c11 * wxv, c11 * wxv);

                // trilinear entirely in fp16: two z-partials + final add
                __half2 paX = __hmul2(h000, u2h(u000.x));
                paX = __hfma2(h001, u2h(u001.x), paX);
                paX = __hfma2(h010, u2h(u010.x), paX);
                paX = __hfma2(h011, u2h(u011.x), paX);
                __half2 pbX = __hmul2(h100, u2h(u100.x));
                pbX = __hfma2(h101, u2h(u101.x), pbX);
                pbX = __hfma2(h110, u2h(u110.x), pbX);
                pbX = __hfma2(h111, u2h(u111.x), pbX);
                __half2 rX = __hadd2(paX, pbX);

                __half2 paY = __hmul2(h000, u2h(u000.y));
                paY = __hfma2(h001, u2h(u001.y), paY);
                paY = __hfma2(h010, u2h(u010.y), paY);
                paY = __hfma2(h011, u2h(u011.y), paY);
                __half2 pbY = __hmul2(h100, u2h(u100.y));
                pbY = __hfma2(h101, u2h(u101.y), pbY);
                pbY = __hfma2(h110, u2h(u110.y), pbY);
                pbY = __hfma2(h111, u2h(u111.y), pbY);
                __half2 rY = __hadd2(paY, pbY);

                uint2 u;
                u.x = *reinterpret_cast<unsigned*>(&rX);
                u.y = *reinterpret_cast<unsigned*>(&rY);
                *reinterpret_cast<uint2*>(fb + src * ROWB + c4 * 8) = u;
            }
            __syncwarp();

            unsigned a0, a1, a2, a3, a4, a5, a6, a7;
            asm volatile("ldmatrix.sync.aligned.m8n8.x4.shared.b16 {%0,%1,%2,%3}, [%4];"
                         : "=r"(a0), "=r"(a1), "=r"(a2), "=r"(a3) : "r"(lm0) : "memory");
            asm volatile("ldmatrix.sync.aligned.m8n8.x4.shared.b16 {%0,%1,%2,%3}, [%4];"
                         : "=r"(a4), "=r"(a5), "=r"(a6), "=r"(a7) : "r"(lm1) : "memory");

            // paired B fragments: LDG.64, coalesced
            const uint2* gb2 = reinterpret_cast<const uint2*>(g_Gb) +
                               k * 256 + lane;
            #pragma unroll
            for (int nt = 0; nt < 4; nt++) {
                const uint2 b01 = __ldg(gb2 + nt * 32);
                mma_16816(d[nt], a0, a1, a2, a3, b01.x, b01.y);
            }
            #pragma unroll
            for (int nt = 0; nt < 4; nt++) {
                const uint2 b01 = __ldg(gb2 + 128 + nt * 32);
                mma_16816(d[nt], a4, a5, a6, a7, b01.x, b01.y);
            }
            __syncwarp();
        }
    }

    // split-K combine: khalf=1 publishes, khalf=0 reduces + stores
    if (live && khalf) {
        #pragma unroll
        for (int nt = 0; nt < 4; nt++)
            #pragma unroll
            for (int q = 0; q < 4; q++)
                partial[tib * 512 + (nt * 4 + q) * 32 + lane] = d[nt][q];
    }
    __syncthreads();
    if (live && !khalf) {
        #pragma unroll
        for (int nt = 0; nt < 4; nt++)
            #pragma unroll
            for (int q = 0; q < 4; q++)
                d[nt][q] += partial[tib * 512 + (nt * 4 + q) * 32 + lane];

        const int r0 = lane >> 2;
        const int cb = 2 * (lane & 3);
        const int i0 = n0 + r0, i1 = i0 + 8;
        const int p0 = (i0 < Ntot) ? g_perm[i0] : -1;
        const int p1 = (i1 < Ntot) ? g_perm[i1] : -1;

        #pragma unroll
        for (int nt = 0; nt < 4; nt++) {
            const int col = 8 * nt + cb;
            const float blo = __ldg(&g_bias[col]);
            const float bhi = __ldg(&g_bias[col + 1]);
            if (p0 >= 0) {
                float2 w0 = make_float2(d[nt][0] + blo, d[nt][1] + bhi);
                *reinterpret_cast<float2*>(out + p0 * C_CH + col) = w0;
            }
            if (p1 >= 0) {
                float2 w1 = make_float2(d[nt][2] + blo, d[nt][3] + bhi);
                *reinterpret_cast<float2*>(out + p1 * C_CH + col) = w1;
            }
        }
    }
}

// ---------------------------------------------------------------------------
// Graph topology:
//   stream 0 : T1 (z<72) -> T2 (z>=72) -> [waits] mainB (phase 1) -> join mainA
//   s_mainA  : waits {T1, prep, bin} -> mainA (phase 0), overlaps T2
//   s_prep   : prep1 -> prep2
//   s_bin    : zero -> count -> scan -> scatter
// ---------------------------------------------------------------------------
extern "C" void kernel_launch(void* const* d_in, const int* in_sizes, int n_in,
                              void* d_out, int out_size)
{
    const float* voxel = (const float*)d_in[0];
    const float* verts = (const float*)d_in[1];
    const int Ntot = in_sizes[1] / 3;

    static cudaStream_t s_prep = nullptr, s_bin = nullptr, s_mainA = nullptr;
    static cudaEvent_t e_fork, e_prep, e_bin, e_T1, e_mainA;
    if (!s_prep) {
        cudaStreamCreateWithFlags(&s_prep, cudaStreamNonBlocking);
        cudaStreamCreateWithFlags(&s_bin, cudaStreamNonBlocking);
        cudaStreamCreateWithFlags(&s_mainA, cudaStreamNonBlocking);
        cudaEventCreateWithFlags(&e_fork, cudaEventDisableTiming);
        cudaEventCreateWithFlags(&e_prep, cudaEventDisableTiming);
        cudaEventCreateWithFlags(&e_bin, cudaEventDisableTiming);
        cudaEventCreateWithFlags(&e_T1, cudaEventDisableTiming);
        cudaEventCreateWithFlags(&e_mainA, cudaEventDisableTiming);
    }

    const int nTiles = (Ntot + TPW - 1) / TPW;
    const int blocks = (nTiles + 3) / 4;

    // fork
    cudaEventRecord(e_fork, 0);
    cudaStreamWaitEvent(s_prep, e_fork, 0);
    cudaStreamWaitEvent(s_bin, e_fork, 0);

    // stream 0: low-z transpose slab, then high-z slab
    {
        dim3 tb(256);
        dim3 tg1(DIM / 32, DIM, ZSPLIT);
        transpose_kernel<<<tg1, tb>>>(voxel, 0);
        cudaEventRecord(e_T1, 0);
        dim3 tg2(DIM / 32, DIM, DIM - ZSPLIT);
        transpose_kernel<<<tg2, tb>>>(voxel, ZSPLIT);
    }

    // s_prep: weight folding
    prep1_kernel<<<27, 1024, 0, s_prep>>>(
        (const float*)d_in[2], (const float*)d_in[4], (const float*)d_in[10]);
    prep2_kernel<<<1, 1024, 0, s_prep>>>(
        (const float*)d_in[4], (const float*)d_in[3], (const float*)d_in[5],
        (const float*)d_in[6], (const float*)d_in[7], (const float*)d_in[8],
        (const float*)d_in[9], (const float*)d_in[10], (const float*)d_in[11]);
    cudaEventRecord(e_prep, s_prep);

    // s_bin: vertex spatial binning
    zero_kernel<<<(NCELL + 255) / 256, 256, 0, s_bin>>>();
    count_kernel<<<(Ntot + 255) / 256, 256, 0, s_bin>>>(verts, Ntot);
    scan_kernel<<<1, 1024, 0, s_bin>>>();
    scatter_kernel<<<(Ntot + 255) / 256, 256, 0, s_bin>>>(verts, Ntot);
    cudaEventRecord(e_bin, s_bin);

    // s_mainA: phase-0 main (low-slab tiles), overlaps T2 on stream 0
    cudaStreamWaitEvent(s_mainA, e_T1, 0);
    cudaStreamWaitEvent(s_mainA, e_prep, 0);
    cudaStreamWaitEvent(s_mainA, e_bin, 0);
    main_kernel<<<blocks, 256, 0, s_mainA>>>(verts, (float*)d_out, Ntot, 0);
    cudaEventRecord(e_mainA, s_mainA);

    // stream 0: phase-1 main after full transpose (+ prep/bin), then join A
    cudaStreamWaitEvent(0, e_prep, 0);
    cudaStreamWaitEvent(0, e_bin, 0);
    main_kernel<<<blocks, 256>>>(verts, (float*)d_out, Ntot, 1);
    cudaStreamWaitEvent(0, e_mainA, 0);
}

// round 15
// speedup vs baseline: 1.9718x; 1.0986x over previous
#include <cuda_runtime.h>
#include <cuda_fp16.h>
#include <cstdint>

#define C_CH 32
#define DIM  128
#define NK   27
#define VOL_ELEMS (C_CH * DIM * DIM * DIM)
#define NCELL 4096            // 16x16x16 cells of 8^3 voxels
#define PERM_MAX (1 << 18)
#define TPW 16                // vertices per tile

#define ROWB 80               // bytes per feat row (16 fp16 padded to 80B)
#define WFEAT (16 * ROWB)     // 1280B per warp feat tile
#define GB_WORDS (NK * 512)   // pre-packed B-fragment words (13824)

#define ZS1 40                // slab 1 end: cz<4 tiles sample z <= 36.97 < 40
#define ZS2 72                // slab 2 end: cz<8 tiles sample z <= 68.97 < 72

// Scratch (device globals: allocation-free per harness rules)
__device__ __half g_volh[VOL_ELEMS];          // channel-last fp16 volume
__device__ float g_G[NK * C_CH * C_CH];       // [k][c][o] folded weights (fp32)
__device__ unsigned g_Gb[GB_WORDS];           // fp16 B-frags, paired lane layout
__device__ float g_bias[C_CH];
__device__ int   g_hist[NCELL];
__device__ int   g_base[NCELL];
__device__ int   g_perm[PERM_MAX];

// neighbour shifts pre-scaled to pixel space: {-1,0,1} * 0.0625 * 63.5
#define M1 -3.96875f
#define P1  3.96875f
#define Z0  0.0f
__constant__ float c_shx[NK] = {M1,M1,M1,M1,M1,M1,M1,M1,M1,
                                Z0,Z0,Z0,Z0,Z0,Z0,Z0,Z0,Z0,
                                P1,P1,P1,P1,P1,P1,P1,P1,P1};
__constant__ float c_shy[NK] = {M1,M1,M1,Z0,Z0,Z0,P1,P1,P1,
                                M1,M1,M1,Z0,Z0,Z0,P1,P1,P1,
                                M1,M1,M1,Z0,Z0,Z0,P1,P1,P1};
__constant__ float c_shz[NK] = {M1,Z0,P1,M1,Z0,P1,M1,Z0,P1,
                                M1,Z0,P1,M1,Z0,P1,M1,Z0,P1,
                                M1,Z0,P1,M1,Z0,P1,M1,Z0,P1};

// ---------------------------------------------------------------------------
// Prep 1 (27 blocks): M[k][j][o] = sum_c conv_w[o,c,k]*Wd[c,j]
// ---------------------------------------------------------------------------
__global__ __launch_bounds__(1024) void prep1_kernel(
    const float* __restrict__ w_d1, const float* __restrict__ w_d2,
    const float* __restrict__ conv_w)
{
    __shared__ float Wds[1024];    // Wd[c][j]
    __shared__ float convs[1024];  // conv[c][o] for this k
    const int tid = threadIdx.x, k = blockIdx.x;
    const int o = tid & 31, j = tid >> 5;

    {   // Wd = w_d2 @ w_d1
        float s = 0.f;
        #pragma unroll
        for (int m = 0; m < 32; m++)
            s += w_d2[(tid >> 5) * 32 + m] * w_d1[m * 32 + (tid & 31)];
        Wds[tid] = s;
    }
    convs[tid] = conv_w[(o * 32 + (tid >> 5)) * 27 + k];
    __syncthreads();

    float acc = 0.f;
    #pragma unroll
    for (int c = 0; c < 32; c++)
        acc += convs[c * 32 + o] * Wds[c * 32 + j];
    g_G[k * 1024 + j * 32 + o] = acc;
}

// ---------------------------------------------------------------------------
// Prep 2 (1 block): center-tap correction on k=13 + fused bias.
// ---------------------------------------------------------------------------
__global__ __launch_bounds__(1024) void prep2_kernel(
    const float* __restrict__ w_d2, const float* __restrict__ b_d1,
    const float* __restrict__ b_d2,
    const float* __restrict__ w_c1, const float* __restrict__ b_c1,
    const float* __restrict__ w_c2, const float* __restrict__ b_c2,
    const float* __restrict__ conv_w, const float* __restrict__ conv_b)
{
    __shared__ float Wcs[1024], part[1024], bds[32], bcs[32];
    const int tid = threadIdx.x;
    const int o = tid & 31, j = tid >> 5;

    {   // Wc = w_c2 @ w_c1
        float s = 0.f;
        #pragma unroll
        for (int m = 0; m < 32; m++)
            s += w_c2[(tid >> 5) * 32 + m] * w_c1[m * 32 + (tid & 31)];
        Wcs[tid] = s;
    }
    if (tid < 32) {
        float sd = 0.f, sc = 0.f;
        #pragma unroll
        for (int m = 0; m < 32; m++) {
            sd += w_d2[tid * 32 + m] * b_d1[m];
            sc += w_c2[tid * 32 + m] * b_c1[m];
        }
        bds[tid] = sd + b_d2[tid];
        bcs[tid] = sc + b_c2[tid];
    }
    float rs = 0.f;
    #pragma unroll
    for (int k = 0; k < NK; k++)
        rs += conv_w[(o * 32 + j) * 27 + k];
    __syncthreads();

    part[j * 32 + o] = bds[j] * rs;

    float S = 0.f;
    #pragma unroll
    for (int k = 0; k < NK; k++) S += g_G[k * 1024 + tid];
    g_G[13 * 1024 + tid] += Wcs[o * 32 + j] - S;
    __syncthreads();

    if (tid < 32) {
        float a = 0.f;
        #pragma unroll
        for (int c = 0; c < 32; c++) a += part[c * 32 + tid];
        g_bias[tid] = a + conv_b[tid] + bcs[tid];
    }
}

// ---------------------------------------------------------------------------
// Pack (27 blocks, one per k): fp16 B-fragments, paired lane layout.
// word e = ks*256 + nt*64 + 2l + r; c = 16ks+8r+2(l&3), o = 8nt+(l>>2)
// ---------------------------------------------------------------------------
__global__ __launch_bounds__(512) void pack_kernel()
{
    __shared__ float Gs[1024];
    const int k = blockIdx.x, tid = threadIdx.x;
    Gs[tid]       = g_G[k * 1024 + tid];
    Gs[tid + 512] = g_G[k * 1024 + tid + 512];
    __syncthreads();

    const int e  = tid;
    const int ks = e >> 8;
    const int nt = (e >> 6) & 3;
    const int l  = (e >> 1) & 31;
    const int r  = e & 1;
    const int c  = 16 * ks + 8 * r + 2 * (l & 3);
    const int oo = 8 * nt + (l >> 2);
    __half2 h = __floats2half2_rn(Gs[c * 32 + oo], Gs[(c + 1) * 32 + oo]);
    g_Gb[k * 512 + e] = *reinterpret_cast<unsigned*>(&h);
}

// ---------------------------------------------------------------------------
// Transpose + convert a z-slab: [C][D][H][W] fp32 -> channel-last fp16.
// ---------------------------------------------------------------------------
__global__ __launch_bounds__(256) void transpose_kernel(
    const float* __restrict__ vin, int z0)
{
    __shared__ float tile[32][33];
    const int x0 = blockIdx.x * 32;
    const int y = blockIdx.y, z = blockIdx.z + z0;
    const int tid = threadIdx.x;
    const int tx = tid & 31, ty = tid >> 5;

    #pragma unroll
    for (int i = 0; i < 4; i++) {
        const int c = ty + 8 * i;
        tile[c][tx] = vin[(((size_t)c * DIM + z) * DIM + y) * DIM + x0 + tx];
    }
    __syncthreads();

    const int g  = tid & 7;          // channel quad (4 halves = 8B)
    const int xx = tid >> 3;         // x within tile (0..31)
    const size_t obase = ((size_t)z * DIM + y) * DIM + x0;

    __half2 h01 = __floats2half2_rn(tile[4 * g + 0][xx], tile[4 * g + 1][xx]);
    __half2 h23 = __floats2half2_rn(tile[4 * g + 2][xx], tile[4 * g + 3][xx]);
    uint2 u;
    u.x = *reinterpret_cast<unsigned*>(&h01);
    u.y = *reinterpret_cast<unsigned*>(&h23);
    reinterpret_cast<uint2*>(g_volh + (obase + xx) * C_CH)[g] = u;
}

// ---------------------------------------------------------------------------
// Vertex binning: zero -> count -> scan -> scatter (cells of 8^3 voxels).
// ---------------------------------------------------------------------------
__device__ __forceinline__ int cell_of(float x, float y, float z)
{
    float px = fminf(fmaxf((x + 1.f) * 63.5f, 0.f), 127.f);
    float py = fminf(fmaxf((y + 1.f) * 63.5f, 0.f), 127.f);
    float pz = fminf(fmaxf((z + 1.f) * 63.5f, 0.f), 127.f);
    const int cx = ((int)px) >> 3, cy = ((int)py) >> 3, cz = ((int)pz) >> 3;
    return (cz << 8) | (cy << 4) | cx;
}

__global__ void zero_kernel()
{
    const int t = blockIdx.x * blockDim.x + threadIdx.x;
    if (t < NCELL) { g_hist[t] = 0; g_base[t] = 0; }
}

__global__ void count_kernel(const float* __restrict__ verts, int Ntot)
{
    const int n = blockIdx.x * blockDim.x + threadIdx.x;
    if (n >= Ntot) return;
    atomicAdd(&g_hist[cell_of(verts[3 * n], verts[3 * n + 1], verts[3 * n + 2])], 1);
}

__global__ __launch_bounds__(1024) void scan_kernel()
{
    __shared__ int sh[1024];
    const int t = threadIdx.x;
    int h0 = g_hist[4 * t], h1 = g_hist[4 * t + 1],
        h2 = g_hist[4 * t + 2], h3 = g_hist[4 * t + 3];
    const int mysum = h0 + h1 + h2 + h3;
    sh[t] = mysum;
    __syncthreads();
    for (int off = 1; off < 1024; off <<= 1) {
        int v = (t >= off) ? sh[t - off] : 0;
        __syncthreads();
        sh[t] += v;
        __syncthreads();
    }
    int e = sh[t] - mysum;
    g_base[4 * t]     = e;
    g_base[4 * t + 1] = e + h0;
    g_base[4 * t + 2] = e + h0 + h1;
    g_base[4 * t + 3] = e + h0 + h1 + h2;
}

__global__ void scatter_kernel(const float* __restrict__ verts, int Ntot)
{
    const int n = blockIdx.x * blockDim.x + threadIdx.x;
    if (n >= Ntot) return;
    const int c = cell_of(verts[3 * n], verts[3 * n + 1], verts[3 * n + 2]);
    const int pos = atomicAdd(&g_base[c], 1);
    g_perm[pos] = n;
}

// ---------------------------------------------------------------------------
__device__ __forceinline__ __half2 u2h(unsigned u)
{
    return *reinterpret_cast<__half2*>(&u);
}

__device__ __forceinline__ void mma_16816(
    float* d, unsigned a0, unsigned a1, unsigned a2, unsigned a3,
    unsigned b0, unsigned b1)
{
    asm volatile(
        "mma.sync.aligned.m16n8k16.row.col.f32.f16.f16.f32 "
        "{%0,%1,%2,%3}, {%4,%5,%6,%7}, {%8,%9}, {%0,%1,%2,%3};"
        : "+f"(d[0]), "+f"(d[1]), "+f"(d[2]), "+f"(d[3])
        : "r"(a0), "r"(a1), "r"(a2), "r"(a3), "r"(b0), "r"(b1));
}

// ---------------------------------------------------------------------------
// Fused sample + tensor-core GEMM, 2-way split-K over neighbours, 3 z-slab
// phases: phase 0 = tiles all cz<4 (needs z<40), phase 1 = all cz<8 minus
// phase 0 (needs z<72), phase 2 = rest (needs full volume). Classification is
// a deterministic warp ballot — identical across phases.
// ---------------------------------------------------------------------------
__global__ __launch_bounds__(256, 3) void main_kernel(
    const float* __restrict__ verts, float* __restrict__ out, int Ntot,
    int phase)
{
    __shared__ __align__(16) unsigned char feats[8 * WFEAT];
    __shared__ float partial[4 * 16 * 32];      // [tib][q][lane]
    const int warp = threadIdx.x >> 5, lane = threadIdx.x & 31;
    const int tib = warp >> 1, khalf = warp & 1;
    const int nTiles = (Ntot + TPW - 1) / TPW;
    const int tile = blockIdx.x * 4 + tib;
    bool live = (tile < nTiles);

    const int n0 = tile * TPW;
    const int v = lane & 15;
    const int idx = n0 + v;
    const bool valid = live && (idx < Ntot);
    const int n = valid ? g_perm[idx] : 0;

    float px0 = 0.f, py0 = 0.f, pz0 = 0.f;   // hoisted pixel-space coords
    if (valid) {
        px0 = fmaf(verts[3 * n + 0], 63.5f, 63.5f);
        py0 = fmaf(verts[3 * n + 1], 63.5f, 63.5f);
        pz0 = fmaf(verts[3 * n + 2], 63.5f, 63.5f);
    }

    // slab classification (invalid lanes: pz0=0 -> lowest). Same in all phases.
    {
        const int czi = ((int)fminf(fmaxf(pz0, 0.f), 127.f)) >> 3;
        const bool low4 = __all_sync(0xffffffffu, czi < 4);
        const bool low8 = __all_sync(0xffffffffu, czi < 8);
        const int myphase = low4 ? 0 : (low8 ? 1 : 2);
        live = live && (myphase == phase);
    }

    const int c4 = lane & 7;              // channel quad
    const int v4 = lane >> 3;             // vertex within group of 4

    unsigned char* fb = feats + warp * WFEAT;
    const unsigned fb_s = (unsigned)__cvta_generic_to_shared(fb);

    const int lg = lane >> 3;
    const unsigned arow = (lane & 7) + ((lg & 1) << 3);
    const unsigned lm0 = fb_s + arow * ROWB + ((lg >> 1) << 4);  // ks=0
    const unsigned lm1 = lm0 + 32;                                // ks=1

    float d[4][4];
    #pragma unroll
    for (int i = 0; i < 4; i++)
        #pragma unroll
        for (int q = 0; q < 4; q++) d[i][q] = 0.f;

    const int k0 = khalf ? 14 : 0;
    const int k1 = khalf ? NK : 14;

    if (live) {
        #pragma unroll 1
        for (int k = k0; k < k1; k++) {
            float px = fminf(fmaxf(px0 + c_shx[k], 0.f), 127.f);
            float py = fminf(fmaxf(py0 + c_shy[k], 0.f), 127.f);
            float pz = fminf(fmaxf(pz0 + c_shz[k], 0.f), 127.f);
            const float fx = floorf(px), fy = floorf(py), fz = floorf(pz);
            const int ix = (int)fx, iy = (int)fy, iz = (int)fz;
            const float wx = px - fx, wy = py - fy, wz = pz - fz;
            const int base = iz * (DIM * DIM * C_CH) + iy * (DIM * C_CH) + ix * C_CH;
            const int sx = (ix < DIM - 1) ? (C_CH >> 2) : 0;         // uint2 units
            const int sy = (iy < DIM - 1) ? (DIM * C_CH >> 2) : 0;
            const int sz = (iz < DIM - 1) ? (DIM * DIM * C_CH >> 2) : 0;

            #pragma unroll
            for (int g4 = 0; g4 < 4; g4++) {
                const int src = g4 * 4 + v4;
                const int b   = __shfl_sync(0xffffffffu, base, src);
                const int sx4 = __shfl_sync(0xffffffffu, sx, src);
                const int sy4 = __shfl_sync(0xffffffffu, sy, src);
                const int sz4 = __shfl_sync(0xffffffffu, sz, src);
                const float wxv = __shfl_sync(0xffffffffu, wx, src);
                const float wyv = __shfl_sync(0xffffffffu, wy, src);
                const float wzv = __shfl_sync(0xffffffffu, wz, src);

                const uint2* p = reinterpret_cast<const uint2*>(g_volh + b) + c4;
                const uint2 u000 = __ldg(p);
                const uint2 u001 = __ldg(p + sx4);
                const uint2 u010 = __ldg(p + sy4);
                const uint2 u011 = __ldg(p + sy4 + sx4);
                const uint2 u100 = __ldg(p + sz4);
                const uint2 u101 = __ldg(p + sz4 + sx4);
                const uint2 u110 = __ldg(p + sz4 + sy4);
                const uint2 u111 = __ldg(p + sz4 + sy4 + sx4);

                // corner weights in fp32, splat-packed to half2 (1 cvt each)
                const float ax0 = 1.f - wxv, ay0 = 1.f - wyv, az0 = 1.f - wzv;
                const float c00 = az0 * ay0, c01 = az0 * wyv;
                const float c10 = wzv * ay0, c11 = wzv * wyv;
                const __half2 h000 = __floats2half2_rn(c00 * ax0, c00 * ax0);
                const __half2 h001 = __floats2half2_rn(c00 * wxv, c00 * wxv);
                const __half2 h010 = __floats2half2_rn(c01 * ax0, c01 * ax0);
                const __half2 h011 = __floats2half2_rn(c01 * wxv, c01 * wxv);
                const __half2 h100 = __floats2half2_rn(c10 * ax0, c10 * ax0);
                const __half2 h101 = __floats2half2_rn(c10 * wxv, c10 * wxv);
                const __half2 h110 = __floats2half2_rn(c11 * ax0, c11 * ax0);
                const __half2 h111 = __floats2half2_rn(c11 * wxv, c11 * wxv);

                // trilinear entirely in fp16: two z-partials + final add
                __half2 paX = __hmul2(h000, u2h(u000.x));
                paX = __hfma2(h001, u2h(u001.x), paX);
                paX = __hfma2(h010, u2h(u010.x), paX);
                paX = __hfma2(h011, u2h(u011.x), paX);
                __half2 pbX = __hmul2(h100, u2h(u100.x));
                pbX = __hfma2(h101, u2h(u101.x), pbX);
                pbX = __hfma2(h110, u2h(u110.x), pbX);
                pbX = __hfma2(h111, u2h(u111.x), pbX);
                __half2 rX = __hadd2(paX, pbX);

                __half2 paY = __hmul2(h000, u2h(u000.y));
                paY = __hfma2(h001, u2h(u001.y), paY);
                paY = __hfma2(h010, u2h(u010.y), paY);
                paY = __hfma2(h011, u2h(u011.y), paY);
                __half2 pbY = __hmul2(h100, u2h(u100.y));
                pbY = __hfma2(h101, u2h(u101.y), pbY);
                pbY = __hfma2(h110, u2h(u110.y), pbY);
                pbY = __hfma2(h111, u2h(u111.y), pbY);
                __half2 rY = __hadd2(paY, pbY);

                uint2 u;
                u.x = *reinterpret_cast<unsigned*>(&rX);
                u.y = *reinterpret_cast<unsigned*>(&rY);
                *reinterpret_cast<uint2*>(fb + src * ROWB + c4 * 8) = u;
            }
            __syncwarp();

            unsigned a0, a1, a2, a3, a4, a5, a6, a7;
            asm volatile("ldmatrix.sync.aligned.m8n8.x4.shared.b16 {%0,%1,%2,%3}, [%4];"
                         : "=r"(a0), "=r"(a1), "=r"(a2), "=r"(a3) : "r"(lm0) : "memory");
            asm volatile("ldmatrix.sync.aligned.m8n8.x4.shared.b16 {%0,%1,%2,%3}, [%4];"
                         : "=r"(a4), "=r"(a5), "=r"(a6), "=r"(a7) : "r"(lm1) : "memory");

            // paired B fragments: LDG.64, coalesced
            const uint2* gb2 = reinterpret_cast<const uint2*>(g_Gb) +
                               k * 256 + lane;
            #pragma unroll
            for (int nt = 0; nt < 4; nt++) {
                const uint2 b01 = __ldg(gb2 + nt * 32);
                mma_16816(d[nt], a0, a1, a2, a3, b01.x, b01.y);
            }
            #pragma unroll
            for (int nt = 0; nt < 4; nt++) {
                const uint2 b01 = __ldg(gb2 + 128 + nt * 32);
                mma_16816(d[nt], a4, a5, a6, a7, b01.x, b01.y);
            }
            __syncwarp();
        }
    }

    // split-K combine: khalf=1 publishes, khalf=0 reduces + stores
    if (live && khalf) {
        #pragma unroll
        for (int nt = 0; nt < 4; nt++)
            #pragma unroll
            for (int q = 0; q < 4; q++)
                partial[tib * 512 + (nt * 4 + q) * 32 + lane] = d[nt][q];
    }
    __syncthreads();
    if (live && !khalf) {
        #pragma unroll
        for (int nt = 0; nt < 4; nt++)
            #pragma unroll
            for (int q = 0; q < 4; q++)
                d[nt][q] += partial[tib * 512 + (nt * 4 + q) * 32 + lane];

        const int r0 = lane >> 2;
        const int cb = 2 * (lane & 3);
        const int i0 = n0 + r0, i1 = i0 + 8;
        const int p0 = (i0 < Ntot) ? g_perm[i0] : -1;
        const int p1 = (i1 < Ntot) ? g_perm[i1] : -1;

        #pragma unroll
        for (int nt = 0; nt < 4; nt++) {
            const int col = 8 * nt + cb;
            const float blo = __ldg(&g_bias[col]);
            const float bhi = __ldg(&g_bias[col + 1]);
            if (p0 >= 0) {
                float2 w0 = make_float2(d[nt][0] + blo, d[nt][1] + bhi);
                *reinterpret_cast<float2*>(out + p0 * C_CH + col) = w0;
            }
            if (p1 >= 0) {
                float2 w1 = make_float2(d[nt][2] + blo, d[nt][3] + bhi);
                *reinterpret_cast<float2*>(out + p1 * C_CH + col) = w1;
            }
        }
    }
}

// ---------------------------------------------------------------------------
// Graph topology (3 side streams — R13's footprint, which passed the
// allocation guard; R14's 4th stream retained a 2MB driver allocation):
//   stream 0 : Ta[0,40) -> Tb[40,72) -> Tc[72,128) -> main(ph2) -> join A,B
//   s_mainA  : waits {Ta, prep, bin} -> main(ph0)   (overlaps Tb,Tc)
//   s_bin    : zero->count->scan->scatter -> waits {Tb, prep} -> main(ph1)
//   s_prep   : prep1 -> prep2 -> pack
// ---------------------------------------------------------------------------
extern "C" void kernel_launch(void* const* d_in, const int* in_sizes, int n_in,
                              void* d_out, int out_size)
{
    const float* voxel = (const float*)d_in[0];
    const float* verts = (const float*)d_in[1];
    const int Ntot = in_sizes[1] / 3;

    static cudaStream_t s_prep = nullptr, s_bin = nullptr, s_mainA = nullptr;
    static cudaEvent_t e_fork, e_prep, e_bin, e_Ta, e_Tb, e_mA, e_mB;
    if (!s_prep) {
        cudaStreamCreateWithFlags(&s_prep, cudaStreamNonBlocking);
        cudaStreamCreateWithFlags(&s_bin, cudaStreamNonBlocking);
        cudaStreamCreateWithFlags(&s_mainA, cudaStreamNonBlocking);
        cudaEventCreateWithFlags(&e_fork, cudaEventDisableTiming);
        cudaEventCreateWithFlags(&e_prep, cudaEventDisableTiming);
        cudaEventCreateWithFlags(&e_bin, cudaEventDisableTiming);
        cudaEventCreateWithFlags(&e_Ta, cudaEventDisableTiming);
        cudaEventCreateWithFlags(&e_Tb, cudaEventDisableTiming);
        cudaEventCreateWithFlags(&e_mA, cudaEventDisableTiming);
        cudaEventCreateWithFlags(&e_mB, cudaEventDisableTiming);
    }

    const int nTiles = (Ntot + TPW - 1) / TPW;
    const int blocks = (nTiles + 3) / 4;

    // fork
    cudaEventRecord(e_fork, 0);
    cudaStreamWaitEvent(s_prep, e_fork, 0);
    cudaStreamWaitEvent(s_bin, e_fork, 0);

    // stream 0: transpose in three z-slabs
    {
        dim3 tb(256);
        dim3 tga(DIM / 32, DIM, ZS1);
        transpose_kernel<<<tga, tb>>>(voxel, 0);
        cudaEventRecord(e_Ta, 0);
        dim3 tgb(DIM / 32, DIM, ZS2 - ZS1);
        transpose_kernel<<<tgb, tb>>>(voxel, ZS1);
        cudaEventRecord(e_Tb, 0);
        dim3 tgc(DIM / 32, DIM, DIM - ZS2);
        transpose_kernel<<<tgc, tb>>>(voxel, ZS2);
    }

    // s_prep: weight folding + parallel pack
    prep1_kernel<<<27, 1024, 0, s_prep>>>(
        (const float*)d_in[2], (const float*)d_in[4], (const float*)d_in[10]);
    prep2_kernel<<<1, 1024, 0, s_prep>>>(
        (const float*)d_in[4], (const float*)d_in[3], (const float*)d_in[5],
        (const float*)d_in[6], (const float*)d_in[7], (const float*)d_in[8],
        (const float*)d_in[9], (const float*)d_in[10], (const float*)d_in[11]);
    pack_kernel<<<27, 512, 0, s_prep>>>();
    cudaEventRecord(e_prep, s_prep);

    // s_bin: vertex spatial binning, then phase-1 main (stream reuse)
    zero_kernel<<<(NCELL + 255) / 256, 256, 0, s_bin>>>();
    count_kernel<<<(Ntot + 255) / 256, 256, 0, s_bin>>>(verts, Ntot);
    scan_kernel<<<1, 1024, 0, s_bin>>>();
    scatter_kernel<<<(Ntot + 255) / 256, 256, 0, s_bin>>>(verts, Ntot);
    cudaEventRecord(e_bin, s_bin);

    // s_mainA: phase-0 tiles (cz<4), start after slab a
    cudaStreamWaitEvent(s_mainA, e_Ta, 0);
    cudaStreamWaitEvent(s_mainA, e_prep, 0);
    cudaStreamWaitEvent(s_mainA, e_bin, 0);
    main_kernel<<<blocks, 256, 0, s_mainA>>>(verts, (float*)d_out, Ntot, 0);
    cudaEventRecord(e_mA, s_mainA);

    // s_bin (reused): phase-1 tiles (cz<8, not phase 0), after slab b + prep
    cudaStreamWaitEvent(s_bin, e_Tb, 0);
    cudaStreamWaitEvent(s_bin, e_prep, 0);
    main_kernel<<<blocks, 256, 0, s_bin>>>(verts, (float*)d_out, Ntot, 1);
    cudaEventRecord(e_mB, s_bin);

    // stream 0: phase-2 after full transpose, then join
    cudaStreamWaitEvent(0, e_prep, 0);
    cudaStreamWaitEvent(0, e_bin, 0);
    main_kernel<<<blocks, 256>>>(verts, (float*)d_out, Ntot, 2);
    cudaStreamWaitEvent(0, e_mA, 0);
    cudaStreamWaitEvent(0, e_mB, 0);
}

// round 16
// speedup vs baseline: 1.9751x; 1.0017x over previous
#include <cuda_runtime.h>
#include <cuda_fp16.h>
#include <cstdint>

#define C_CH 32
#define DIM  128
#define NK   27
#define VOL_ELEMS (C_CH * DIM * DIM * DIM)
#define NCELL 4096            // 16x16x16 cells of 8^3 voxels
#define PERM_MAX (1 << 18)
#define TPW 16                // vertices per tile

#define ROWB 80               // bytes per feat row (16 fp16 padded to 80B)
#define WFEAT (16 * ROWB)     // 1280B per warp feat tile
#define GB_WORDS (NK * 512)   // pre-packed B-fragment words (13824)

#define ZS1 40                // slab 1 end: cz<4 tiles sample z <= 36.97 < 40
#define ZS2 72                // slab 2 end: cz<8 tiles sample z <= 68.97 < 72

// Scratch (device globals: allocation-free per harness rules)
__device__ __half g_volh[VOL_ELEMS];          // channel-last fp16 volume
__device__ float g_G[NK * C_CH * C_CH];       // [k][c][o] folded weights (fp32)
__device__ unsigned g_Gb[GB_WORDS];           // fp16 B-frags, paired lane layout
__device__ float g_bias[C_CH];
__device__ int   g_hist[NCELL];
__device__ int   g_base[NCELL];
__device__ int   g_perm[PERM_MAX];
__device__ int   g_pb[2];                     // vertex counts: cz<4, cz<8

// neighbour shifts pre-scaled to pixel space: {-1,0,1} * 0.0625 * 63.5
#define M1 -3.96875f
#define P1  3.96875f
#define Z0  0.0f
__constant__ float c_shx[NK] = {M1,M1,M1,M1,M1,M1,M1,M1,M1,
                                Z0,Z0,Z0,Z0,Z0,Z0,Z0,Z0,Z0,
                                P1,P1,P1,P1,P1,P1,P1,P1,P1};
__constant__ float c_shy[NK] = {M1,M1,M1,Z0,Z0,Z0,P1,P1,P1,
                                M1,M1,M1,Z0,Z0,Z0,P1,P1,P1,
                                M1,M1,M1,Z0,Z0,Z0,P1,P1,P1};
__constant__ float c_shz[NK] = {M1,Z0,P1,M1,Z0,P1,M1,Z0,P1,
                                M1,Z0,P1,M1,Z0,P1,M1,Z0,P1,
                                M1,Z0,P1,M1,Z0,P1,M1,Z0,P1};

// ---------------------------------------------------------------------------
// Prep 1 (27 blocks): M[k][j][o] = sum_c conv_w[o,c,k]*Wd[c,j]
// ---------------------------------------------------------------------------
__global__ __launch_bounds__(1024) void prep1_kernel(
    const float* __restrict__ w_d1, const float* __restrict__ w_d2,
    const float* __restrict__ conv_w)
{
    __shared__ float Wds[1024];    // Wd[c][j]
    __shared__ float convs[1024];  // conv[c][o] for this k
    const int tid = threadIdx.x, k = blockIdx.x;
    const int o = tid & 31, j = tid >> 5;

    {   // Wd = w_d2 @ w_d1
        float s = 0.f;
        #pragma unroll
        for (int m = 0; m < 32; m++)
            s += w_d2[(tid >> 5) * 32 + m] * w_d1[m * 32 + (tid & 31)];
        Wds[tid] = s;
    }
    convs[tid] = conv_w[(o * 32 + (tid >> 5)) * 27 + k];
    __syncthreads();

    float acc = 0.f;
    #pragma unroll
    for (int c = 0; c < 32; c++)
        acc += convs[c * 32 + o] * Wds[c * 32 + j];
    g_G[k * 1024 + j * 32 + o] = acc;
}

// ---------------------------------------------------------------------------
// Prep 2 (1 block): center-tap correction on k=13 + fused bias.
// ---------------------------------------------------------------------------
__global__ __launch_bounds__(1024) void prep2_kernel(
    const float* __restrict__ w_d2, const float* __restrict__ b_d1,
    const float* __restrict__ b_d2,
    const float* __restrict__ w_c1, const float* __restrict__ b_c1,
    const float* __restrict__ w_c2, const float* __restrict__ b_c2,
    const float* __restrict__ conv_w, const float* __restrict__ conv_b)
{
    __shared__ float Wcs[1024], part[1024], bds[32], bcs[32];
    const int tid = threadIdx.x;
    const int o = tid & 31, j = tid >> 5;

    {   // Wc = w_c2 @ w_c1
        float s = 0.f;
        #pragma unroll
        for (int m = 0; m < 32; m++)
            s += w_c2[(tid >> 5) * 32 + m] * w_c1[m * 32 + (tid & 31)];
        Wcs[tid] = s;
    }
    if (tid < 32) {
        float sd = 0.f, sc = 0.f;
        #pragma unroll
        for (int m = 0; m < 32; m++) {
            sd += w_d2[tid * 32 + m] * b_d1[m];
            sc += w_c2[tid * 32 + m] * b_c1[m];
        }
        bds[tid] = sd + b_d2[tid];
        bcs[tid] = sc + b_c2[tid];
    }
    float rs = 0.f;
    #pragma unroll
    for (int k = 0; k < NK; k++)
        rs += conv_w[(o * 32 + j) * 27 + k];
    __syncthreads();

    part[j * 32 + o] = bds[j] * rs;

    float S = 0.f;
    #pragma unroll
    for (int k = 0; k < NK; k++) S += g_G[k * 1024 + tid];
    g_G[13 * 1024 + tid] += Wcs[o * 32 + j] - S;
    __syncthreads();

    if (tid < 32) {
        float a = 0.f;
        #pragma unroll
        for (int c = 0; c < 32; c++) a += part[c * 32 + tid];
        g_bias[tid] = a + conv_b[tid] + bcs[tid];
    }
}

// ---------------------------------------------------------------------------
// Pack (27 blocks, one per k): fp16 B-fragments, paired lane layout.
// ---------------------------------------------------------------------------
__global__ __launch_bounds__(512) void pack_kernel()
{
    __shared__ float Gs[1024];
    const int k = blockIdx.x, tid = threadIdx.x;
    Gs[tid]       = g_G[k * 1024 + tid];
    Gs[tid + 512] = g_G[k * 1024 + tid + 512];
    __syncthreads();

    const int e  = tid;
    const int ks = e >> 8;
    const int nt = (e >> 6) & 3;
    const int l  = (e >> 1) & 31;
    const int r  = e & 1;
    const int c  = 16 * ks + 8 * r + 2 * (l & 3);
    const int oo = 8 * nt + (l >> 2);
    __half2 h = __floats2half2_rn(Gs[c * 32 + oo], Gs[(c + 1) * 32 + oo]);
    g_Gb[k * 512 + e] = *reinterpret_cast<unsigned*>(&h);
}

// ---------------------------------------------------------------------------
// Transpose + convert a z-slab: [C][D][H][W] fp32 -> channel-last fp16.
// ---------------------------------------------------------------------------
__global__ __launch_bounds__(256) void transpose_kernel(
    const float* __restrict__ vin, int z0)
{
    __shared__ float tile[32][33];
    const int x0 = blockIdx.x * 32;
    const int y = blockIdx.y, z = blockIdx.z + z0;
    const int tid = threadIdx.x;
    const int tx = tid & 31, ty = tid >> 5;

    #pragma unroll
    for (int i = 0; i < 4; i++) {
        const int c = ty + 8 * i;
        tile[c][tx] = vin[(((size_t)c * DIM + z) * DIM + y) * DIM + x0 + tx];
    }
    __syncthreads();

    const int g  = tid & 7;          // channel quad (4 halves = 8B)
    const int xx = tid >> 3;         // x within tile (0..31)
    const size_t obase = ((size_t)z * DIM + y) * DIM + x0;

    __half2 h01 = __floats2half2_rn(tile[4 * g + 0][xx], tile[4 * g + 1][xx]);
    __half2 h23 = __floats2half2_rn(tile[4 * g + 2][xx], tile[4 * g + 3][xx]);
    uint2 u;
    u.x = *reinterpret_cast<unsigned*>(&h01);
    u.y = *reinterpret_cast<unsigned*>(&h23);
    reinterpret_cast<uint2*>(g_volh + (obase + xx) * C_CH)[g] = u;
}

// ---------------------------------------------------------------------------
// Vertex binning: count -> scan (also phase bounds) -> scatter.
// ---------------------------------------------------------------------------
__device__ __forceinline__ int cell_of(float x, float y, float z)
{
    float px = fminf(fmaxf((x + 1.f) * 63.5f, 0.f), 127.f);
    float py = fminf(fmaxf((y + 1.f) * 63.5f, 0.f), 127.f);
    float pz = fminf(fmaxf((z + 1.f) * 63.5f, 0.f), 127.f);
    const int cx = ((int)px) >> 3, cy = ((int)py) >> 3, cz = ((int)pz) >> 3;
    return (cz << 8) | (cy << 4) | cx;
}

__global__ void count_kernel(const float* __restrict__ verts, int Ntot)
{
    const int n = blockIdx.x * blockDim.x + threadIdx.x;
    if (n >= Ntot) return;
    atomicAdd(&g_hist[cell_of(verts[3 * n], verts[3 * n + 1], verts[3 * n + 2])], 1);
}

__global__ __launch_bounds__(1024) void scan_kernel()
{
    __shared__ int sh[1024];
    const int t = threadIdx.x;
    int h0 = g_hist[4 * t], h1 = g_hist[4 * t + 1],
        h2 = g_hist[4 * t + 2], h3 = g_hist[4 * t + 3];
    const int mysum = h0 + h1 + h2 + h3;
    sh[t] = mysum;
    __syncthreads();
    for (int off = 1; off < 1024; off <<= 1) {
        int v = (t >= off) ? sh[t - off] : 0;
        __syncthreads();
        sh[t] += v;
        __syncthreads();
    }
    int e = sh[t] - mysum;
    g_base[4 * t]     = e;
    g_base[4 * t + 1] = e + h0;
    g_base[4 * t + 2] = e + h0 + h1;
    g_base[4 * t + 3] = e + h0 + h1 + h2;
    // phase bounds: verts with cz<4 = cells < 1024 (groups 0..255, inclusive
    // prefix sh[255]); cz<8 = cells < 2048 (sh[511]).
    if (t == 255) g_pb[0] = sh[255];
    if (t == 511) g_pb[1] = sh[511];
}

__global__ void scatter_kernel(const float* __restrict__ verts, int Ntot)
{
    const int n = blockIdx.x * blockDim.x + threadIdx.x;
    if (n >= Ntot) return;
    const int c = cell_of(verts[3 * n], verts[3 * n + 1], verts[3 * n + 2]);
    const int pos = atomicAdd(&g_base[c], 1);
    g_perm[pos] = n;
}

// ---------------------------------------------------------------------------
__device__ __forceinline__ __half2 u2h(unsigned u)
{
    return *reinterpret_cast<__half2*>(&u);
}

__device__ __forceinline__ void mma_16816(
    float* d, unsigned a0, unsigned a1, unsigned a2, unsigned a3,
    unsigned b0, unsigned b1)
{
    asm volatile(
        "mma.sync.aligned.m16n8k16.row.col.f32.f16.f16.f32 "
        "{%0,%1,%2,%3}, {%4,%5,%6,%7}, {%8,%9}, {%0,%1,%2,%3};"
        : "+f"(d[0]), "+f"(d[1]), "+f"(d[2]), "+f"(d[3])
        : "r"(a0), "r"(a1), "r"(a2), "r"(a3), "r"(b0), "r"(b1));
}

// ---------------------------------------------------------------------------
// Fused sample + tensor-core GEMM, 2-way split-K, phased by CONTIGUOUS tile
// ranges (perm is z-major sorted, so phase membership is a range): phase 0 =
// tiles [0, pb0/16), phase 1 = [pb0/16, pb1/16), phase 2 = rest. Out-of-range
// blocks exit after one L1-hit load — no perm/vert loads, no ballot.
// ---------------------------------------------------------------------------
__global__ __launch_bounds__(256, 3) void main_kernel(
    const float* __restrict__ verts, float* __restrict__ out, int Ntot,
    int phase)
{
    const int nTiles = (Ntot + TPW - 1) / TPW;
    const int t4 = g_pb[0] >> 4;          // tiles fully cz<4
    const int t8 = g_pb[1] >> 4;          // tiles fully cz<8
    const int lo = (phase == 0) ? 0  : ((phase == 1) ? t4 : t8);
    const int hi = (phase == 0) ? t4 : ((phase == 1) ? t8 : nTiles);

    const int tbase = blockIdx.x * 4;
    if (tbase >= hi || tbase + 3 < lo) return;   // whole block dead

    __shared__ __align__(16) unsigned char feats[8 * WFEAT];
    __shared__ float partial[4 * 16 * 32];      // [tib][q][lane]
    const int warp = threadIdx.x >> 5, lane = threadIdx.x & 31;
    const int tib = warp >> 1, khalf = warp & 1;
    const int tile = tbase + tib;
    const bool live = (tile >= lo) && (tile < hi);

    const int n0 = tile * TPW;
    const int v = lane & 15;
    const int idx = n0 + v;
    const bool valid = live && (idx < Ntot);
    const int n = valid ? g_perm[idx] : 0;

    float px0 = 0.f, py0 = 0.f, pz0 = 0.f;   // hoisted pixel-space coords
    if (valid) {
        px0 = fmaf(verts[3 * n + 0], 63.5f, 63.5f);
        py0 = fmaf(verts[3 * n + 1], 63.5f, 63.5f);
        pz0 = fmaf(verts[3 * n + 2], 63.5f, 63.5f);
    }

    const int c4 = lane & 7;              // channel quad
    const int v4 = lane >> 3;             // vertex within group of 4

    unsigned char* fb = feats + warp * WFEAT;
    const unsigned fb_s = (unsigned)__cvta_generic_to_shared(fb);

    const int lg = lane >> 3;
    const unsigned arow = (lane & 7) + ((lg & 1) << 3);
    const unsigned lm0 = fb_s + arow * ROWB + ((lg >> 1) << 4);  // ks=0
    const unsigned lm1 = lm0 + 32;                                // ks=1

    float d[4][4];
    #pragma unroll
    for (int i = 0; i < 4; i++)
        #pragma unroll
        for (int q = 0; q < 4; q++) d[i][q] = 0.f;

    const int k0 = khalf ? 14 : 0;
    const int k1 = khalf ? NK : 14;

    if (live) {
        #pragma unroll 1
        for (int k = k0; k < k1; k++) {
            float px = fminf(fmaxf(px0 + c_shx[k], 0.f), 127.f);
            float py = fminf(fmaxf(py0 + c_shy[k], 0.f), 127.f);
            float pz = fminf(fmaxf(pz0 + c_shz[k], 0.f), 127.f);
            const float fx = floorf(px), fy = floorf(py), fz = floorf(pz);
            const int ix = (int)fx, iy = (int)fy, iz = (int)fz;
            const float wx = px - fx, wy = py - fy, wz = pz - fz;
            // uint2 index of voxel (multiple of 8) with step flags packed in
            // the low 3 bits: bit0 x+1 valid, bit1 y+1 valid, bit2 z+1 valid.
            const int bidx = (iz * (DIM * DIM * C_CH >> 2)) +
                             (iy * (DIM * C_CH >> 2)) + (ix * (C_CH >> 2));
            const int pk = bidx | ((ix < DIM - 1) ? 1 : 0)
                                | ((iy < DIM - 1) ? 2 : 0)
                                | ((iz < DIM - 1) ? 4 : 0);

            #pragma unroll
            for (int g4 = 0; g4 < 4; g4++) {
                const int src = g4 * 4 + v4;
                const int pkv = __shfl_sync(0xffffffffu, pk, src);
                const float wxv = __shfl_sync(0xffffffffu, wx, src);
                const float wyv = __shfl_sync(0xffffffffu, wy, src);
                const float wzv = __shfl_sync(0xffffffffu, wz, src);
                const int b   = pkv & ~7;
                const int sx4 = (pkv & 1) ? (C_CH >> 2) : 0;
                const int sy4 = (pkv & 2) ? (DIM * C_CH >> 2) : 0;
                const int sz4 = (pkv & 4) ? (DIM * DIM * C_CH >> 2) : 0;

                const uint2* p = reinterpret_cast<const uint2*>(g_volh) + b + c4;
                const uint2 u000 = __ldg(p);
                const uint2 u001 = __ldg(p + sx4);
                const uint2 u010 = __ldg(p + sy4);
                const uint2 u011 = __ldg(p + sy4 + sx4);
                const uint2 u100 = __ldg(p + sz4);
                const uint2 u101 = __ldg(p + sz4 + sx4);
                const uint2 u110 = __ldg(p + sz4 + sy4);
                const uint2 u111 = __ldg(p + sz4 + sy4 + sx4);

                // corner weights in fp32, splat-packed to half2 (1 cvt each)
                const float ax0 = 1.f - wxv, ay0 = 1.f - wyv, az0 = 1.f - wzv;
                const float c00 = az0 * ay0, c01 = az0 * wyv;
                const float c10 = wzv * ay0, c11 = wzv * wyv;
                const __half2 h000 = __floats2half2_rn(c00 * ax0, c00 * ax0);
                const __half2 h001 = __floats2half2_rn(c00 * wxv, c00 * wxv);
                const __half2 h010 = __floats2half2_rn(c01 * ax0, c01 * ax0);
                const __half2 h011 = __floats2half2_rn(c01 * wxv, c01 * wxv);
                const __half2 h100 = __floats2half2_rn(c10 * ax0, c10 * ax0);
                const __half2 h101 = __floats2half2_rn(c10 * wxv, c10 * wxv);
                const __half2 h110 = __floats2half2_rn(c11 * ax0, c11 * ax0);
                const __half2 h111 = __floats2half2_rn(c11 * wxv, c11 * wxv);

                // trilinear entirely in fp16: two z-partials + final add
                __half2 paX = __hmul2(h000, u2h(u000.x));
                paX = __hfma2(h001, u2h(u001.x), paX);
                paX = __hfma2(h010, u2h(u010.x), paX);
                paX = __hfma2(h011, u2h(u011.x), paX);
                __half2 pbX = __hmul2(h100, u2h(u100.x));
                pbX = __hfma2(h101, u2h(u101.x), pbX);
                pbX = __hfma2(h110, u2h(u110.x), pbX);
                pbX = __hfma2(h111, u2h(u111.x), pbX);
                __half2 rX = __hadd2(paX, pbX);

                __half2 paY = __hmul2(h000, u2h(u000.y));
                paY = __hfma2(h001, u2h(u001.y), paY);
                paY = __hfma2(h010, u2h(u010.y), paY);
                paY = __hfma2(h011, u2h(u011.y), paY);
                __half2 pbY = __hmul2(h100, u2h(u100.y));
                pbY = __hfma2(h101, u2h(u101.y), pbY);
                pbY = __hfma2(h110, u2h(u110.y), pbY);
                pbY = __hfma2(h111, u2h(u111.y), pbY);
                __half2 rY = __hadd2(paY, pbY);

                uint2 u;
                u.x = *reinterpret_cast<unsigned*>(&rX);
                u.y = *reinterpret_cast<unsigned*>(&rY);
                *reinterpret_cast<uint2*>(fb + src * ROWB + c4 * 8) = u;
            }
            __syncwarp();

            unsigned a0, a1, a2, a3, a4, a5, a6, a7;
            asm volatile("ldmatrix.sync.aligned.m8n8.x4.shared.b16 {%0,%1,%2,%3}, [%4];"
                         : "=r"(a0), "=r"(a1), "=r"(a2), "=r"(a3) : "r"(lm0) : "memory");
            asm volatile("ldmatrix.sync.aligned.m8n8.x4.shared.b16 {%0,%1,%2,%3}, [%4];"
                         : "=r"(a4), "=r"(a5), "=r"(a6), "=r"(a7) : "r"(lm1) : "memory");

            // paired B fragments: LDG.64, coalesced
            const uint2* gb2 = reinterpret_cast<const uint2*>(g_Gb) +
                               k * 256 + lane;
            #pragma unroll
            for (int nt = 0; nt < 4; nt++) {
                const uint2 b01 = __ldg(gb2 + nt * 32);
                mma_16816(d[nt], a0, a1, a2, a3, b01.x, b01.y);
            }
            #pragma unroll
            for (int nt = 0; nt < 4; nt++) {
                const uint2 b01 = __ldg(gb2 + 128 + nt * 32);
                mma_16816(d[nt], a4, a5, a6, a7, b01.x, b01.y);
            }
            __syncwarp();
        }
    }

    // split-K combine: khalf=1 publishes, khalf=0 reduces + stores
    if (live && khalf) {
        #pragma unroll
        for (int nt = 0; nt < 4; nt++)
            #pragma unroll
            for (int q = 0; q < 4; q++)
                partial[tib * 512 + (nt * 4 + q) * 32 + lane] = d[nt][q];
    }
    __syncthreads();
    if (live && !khalf) {
        #pragma unroll
        for (int nt = 0; nt < 4; nt++)
            #pragma unroll
            for (int q = 0; q < 4; q++)
                d[nt][q] += partial[tib * 512 + (nt * 4 + q) * 32 + lane];

        const int r0 = lane >> 2;
        const int cb = 2 * (lane & 3);
        const int i0 = n0 + r0, i1 = i0 + 8;
        const int p0 = (i0 < Ntot) ? g_perm[i0] : -1;
        const int p1 = (i1 < Ntot) ? g_perm[i1] : -1;

        #pragma unroll
        for (int nt = 0; nt < 4; nt++) {
            const int col = 8 * nt + cb;
            const float blo = __ldg(&g_bias[col]);
            const float bhi = __ldg(&g_bias[col + 1]);
            if (p0 >= 0) {
                float2 w0 = make_float2(d[nt][0] + blo, d[nt][1] + bhi);
                *reinterpret_cast<float2*>(out + p0 * C_CH + col) = w0;
            }
            if (p1 >= 0) {
                float2 w1 = make_float2(d[nt][2] + blo, d[nt][3] + bhi);
                *reinterpret_cast<float2*>(out + p1 * C_CH + col) = w1;
            }
        }
    }
}

// ---------------------------------------------------------------------------
// Graph topology (3 side streams):
//   stream 0 : Ta[0,40) -> Tb[40,72) -> Tc[72,128) -> main(ph2) -> join A,B
//   s_mainA  : waits {Ta, prep, bin} -> main(ph0)   (overlaps Tb,Tc)
//   s_bin    : memset->count->scan->scatter -> waits {Tb, prep} -> main(ph1)
//   s_prep   : prep1 -> prep2 -> pack
// ---------------------------------------------------------------------------
extern "C" void kernel_launch(void* const* d_in, const int* in_sizes, int n_in,
                              void* d_out, int out_size)
{
    const float* voxel = (const float*)d_in[0];
    const float* verts = (const float*)d_in[1];
    const int Ntot = in_sizes[1] / 3;

    static cudaStream_t s_prep = nullptr, s_bin = nullptr, s_mainA = nullptr;
    static cudaEvent_t e_fork, e_prep, e_bin, e_Ta, e_Tb, e_mA, e_mB;
    static void* hist_ptr = nullptr;
    static void* base_ptr = nullptr;
    if (!s_prep) {
        cudaStreamCreateWithFlags(&s_prep, cudaStreamNonBlocking);
        cudaStreamCreateWithFlags(&s_bin, cudaStreamNonBlocking);
        cudaStreamCreateWithFlags(&s_mainA, cudaStreamNonBlocking);
        cudaEventCreateWithFlags(&e_fork, cudaEventDisableTiming);
        cudaEventCreateWithFlags(&e_prep, cudaEventDisableTiming);
        cudaEventCreateWithFlags(&e_bin, cudaEventDisableTiming);
        cudaEventCreateWithFlags(&e_Ta, cudaEventDisableTiming);
        cudaEventCreateWithFlags(&e_Tb, cudaEventDisableTiming);
        cudaEventCreateWithFlags(&e_mA, cudaEventDisableTiming);
        cudaEventCreateWithFlags(&e_mB, cudaEventDisableTiming);
        cudaGetSymbolAddress(&hist_ptr, g_hist);
        cudaGetSymbolAddress(&base_ptr, g_base);
    }

    const int nTiles = (Ntot + TPW - 1) / TPW;
    const int blocks = (nTiles + 3) / 4;

    // fork
    cudaEventRecord(e_fork, 0);
    cudaStreamWaitEvent(s_prep, e_fork, 0);
    cudaStreamWaitEvent(s_bin, e_fork, 0);

    // stream 0: transpose in three z-slabs
    {
        dim3 tb(256);
        dim3 tga(DIM / 32, DIM, ZS1);
        transpose_kernel<<<tga, tb>>>(voxel, 0);
        cudaEventRecord(e_Ta, 0);
        dim3 tgb(DIM / 32, DIM, ZS2 - ZS1);
        transpose_kernel<<<tgb, tb>>>(voxel, ZS1);
        cudaEventRecord(e_Tb, 0);
        dim3 tgc(DIM / 32, DIM, DIM - ZS2);
        transpose_kernel<<<tgc, tb>>>(voxel, ZS2);
    }

    // s_prep: weight folding + parallel pack
    prep1_kernel<<<27, 1024, 0, s_prep>>>(
        (const float*)d_in[2], (const float*)d_in[4], (const float*)d_in[10]);
    prep2_kernel<<<1, 1024, 0, s_prep>>>(
        (const float*)d_in[4], (const float*)d_in[3], (const float*)d_in[5],
        (const float*)d_in[6], (const float*)d_in[7], (const float*)d_in[8],
        (const float*)d_in[9], (const float*)d_in[10], (const float*)d_in[11]);
    pack_kernel<<<27, 512, 0, s_prep>>>();
    cudaEventRecord(e_prep, s_prep);

    // s_bin: vertex spatial binning, then phase-1 main (stream reuse)
    cudaMemsetAsync(hist_ptr, 0, NCELL * sizeof(int), s_bin);
    cudaMemsetAsync(base_ptr, 0, NCELL * sizeof(int), s_bin);
    count_kernel<<<(Ntot + 255) / 256, 256, 0, s_bin>>>(verts, Ntot);
    scan_kernel<<<1, 1024, 0, s_bin>>>();
    scatter_kernel<<<(Ntot + 255) / 256, 256, 0, s_bin>>>(verts, Ntot);
    cudaEventRecord(e_bin, s_bin);

    // s_mainA: phase-0 tiles (cz<4), start after slab a
    cudaStreamWaitEvent(s_mainA, e_Ta, 0);
    cudaStreamWaitEvent(s_mainA, e_prep, 0);
    cudaStreamWaitEvent(s_mainA, e_bin, 0);
    main_kernel<<<blocks, 256, 0, s_mainA>>>(verts, (float*)d_out, Ntot, 0);
    cudaEventRecord(e_mA, s_mainA);

    // s_bin (reused): phase-1 tiles (cz<8, not phase 0), after slab b + prep
    cudaStreamWaitEvent(s_bin, e_Tb, 0);
    cudaStreamWaitEvent(s_bin, e_prep, 0);
    main_kernel<<<blocks, 256, 0, s_bin>>>(verts, (float*)d_out, Ntot, 1);
    cudaEventRecord(e_mB, s_bin);

    // stream 0: phase-2 after full transpose, then join
    cudaStreamWaitEvent(0, e_prep, 0);
    cudaStreamWaitEvent(0, e_bin, 0);
    main_kernel<<<blocks, 256>>>(verts, (float*)d_out, Ntot, 2);
    cudaStreamWaitEvent(0, e_mA, 0);
    cudaStreamWaitEvent(0, e_mB, 0);
}